// round 1
// baseline (speedup 1.0000x reference)
#include <cuda_runtime.h>
#include <math.h>

#define BB 2
#define QL 1024
#define ML 1024
#define KL 2048
#define EE 1024
#define HH 16
#define DH 64
#define FF 4096

// ---------------- scratch (static device globals; no runtime allocation) ----
__device__ float g_cat[BB*KL*EE];   // concat(member, w)      [B*KL, E]
__device__ float g_kp [BB*KL*EE];   // K projection           [B*KL, H*DH]
__device__ float g_vp [BB*KL*EE];   // V projection
__device__ float g_qp [BB*QL*EE];   // Q projection           [B*QL, H*DH]
__device__ float g_rp [KL*EE];      // R projection           [KL,   H*DH]
__device__ float g_att[BB*QL*EE];   // attention output       [B*QL, H*DH]
__device__ float g_ao [BB*QL*EE];   // att @ Wo
__device__ float g_x  [BB*QL*EE];   // LN1 output
__device__ float g_h  [BB*QL*FF];   // FFN hidden
__device__ float g_y  [BB*QL*EE];   // FFN out (pre-residual)

// ---------------- concat: [member; w] along sequence -----------------------
__global__ __launch_bounds__(256) void concat_kernel(
    const float* __restrict__ member, const float* __restrict__ w)
{
    int idx = (blockIdx.x * 256 + threadIdx.x) * 4;       // float4 index
    int b   = idx / (KL*EE);
    int rem = idx % (KL*EE);
    int s   = rem / EE;
    int e   = rem % EE;
    float4 v;
    if (s < ML) v = *(const float4*)&member[(size_t)(b*ML + s)*EE + e];
    else        v = *(const float4*)&w[(size_t)(b*QL + (s-ML))*EE + e];
    *(float4*)&g_cat[idx] = v;
}

// ---------------- SGEMM: C[M,N] = A[M,K] @ B[K,N], optional ReLU -----------
// 128x128 block tile, BK=16, 8x8 per thread, 256 threads.
template<int EPI>   // 0 = none, 1 = relu
__global__ __launch_bounds__(256) void sgemm_kernel(
    const float* __restrict__ A, const float* __restrict__ Bm,
    float* __restrict__ C, int M, int N, int K)
{
    __shared__ float As[16][128];   // transposed A tile
    __shared__ float Bs[16][128];

    const int tid = threadIdx.x;
    const int tx = tid & 15, ty = tid >> 4;
    const int row0 = blockIdx.y * 128, col0 = blockIdx.x * 128;

    const int ar = tid >> 2;            // 0..63
    const int ac = (tid & 3) * 4;       // 0,4,8,12
    const int br = tid >> 5;            // 0..7
    const int bc = (tid & 31) * 4;      // 0..124

    float acc[8][8];
    #pragma unroll
    for (int i = 0; i < 8; i++)
        #pragma unroll
        for (int j = 0; j < 8; j++) acc[i][j] = 0.f;

    for (int k0 = 0; k0 < K; k0 += 16) {
        float4 a0 = *(const float4*)&A[(size_t)(row0+ar   )*K + k0 + ac];
        float4 a1 = *(const float4*)&A[(size_t)(row0+ar+64)*K + k0 + ac];
        float4 b0 = *(const float4*)&Bm[(size_t)(k0+br  )*N + col0 + bc];
        float4 b1 = *(const float4*)&Bm[(size_t)(k0+br+8)*N + col0 + bc];

        As[ac+0][ar] = a0.x; As[ac+1][ar] = a0.y;
        As[ac+2][ar] = a0.z; As[ac+3][ar] = a0.w;
        As[ac+0][ar+64] = a1.x; As[ac+1][ar+64] = a1.y;
        As[ac+2][ar+64] = a1.z; As[ac+3][ar+64] = a1.w;
        *(float4*)&Bs[br  ][bc] = b0;
        *(float4*)&Bs[br+8][bc] = b1;
        __syncthreads();

        #pragma unroll
        for (int kk = 0; kk < 16; kk++) {
            float a[8], b[8];
            *(float4*)(a  ) = *(const float4*)&As[kk][ty*8  ];
            *(float4*)(a+4) = *(const float4*)&As[kk][ty*8+4];
            *(float4*)(b  ) = *(const float4*)&Bs[kk][tx*8  ];
            *(float4*)(b+4) = *(const float4*)&Bs[kk][tx*8+4];
            #pragma unroll
            for (int i = 0; i < 8; i++)
                #pragma unroll
                for (int j = 0; j < 8; j++)
                    acc[i][j] += a[i] * b[j];
        }
        __syncthreads();
    }

    #pragma unroll
    for (int i = 0; i < 8; i++) {
        size_t r = (size_t)(row0 + ty*8 + i) * N + col0 + tx*8;
        #pragma unroll
        for (int j = 0; j < 8; j += 4) {
            float4 v = make_float4(acc[i][j], acc[i][j+1], acc[i][j+2], acc[i][j+3]);
            if (EPI == 1) {
                v.x = fmaxf(v.x, 0.f); v.y = fmaxf(v.y, 0.f);
                v.z = fmaxf(v.z, 0.f); v.w = fmaxf(v.w, 0.f);
            }
            *(float4*)&C[r + j] = v;
        }
    }
}

// ---------------- fused rel-attention (flash-style, fused rel_shift) -------
// grid: (QL/64, H, B), 256 threads. 64x64 score tiles, online softmax.
// BD rel-shift fused: shifted[i,j] = qr[i] . rh[j - i + QL - 1]  (valid for
// all unmasked cells; masked cells forced to -1e30 to match reference).
struct AttnSmem {
    float qw[64][68];   // [kk][i]  q + r_w_bias (K-major)
    float qr[64][68];   // [kk][i]  q + r_r_bias
    float k [64][68];   // [kk][j]
    float v [64][64];   // [j][d]
    float r [64][132];  // [kk][dloc], dloc in [0,127), window of rh
    float p [64][64];   // [i][j] probs
};

__global__ __launch_bounds__(256) void attn_kernel(
    const float* __restrict__ QP, const float* __restrict__ KP,
    const float* __restrict__ VP, const float* __restrict__ RP,
    const float* __restrict__ rwb, const float* __restrict__ rrb,
    float* __restrict__ OUT)
{
    extern __shared__ char smem_raw[];
    AttnSmem& sm = *reinterpret_cast<AttnSmem*>(smem_raw);

    const int i0 = blockIdx.x * 64;
    const int h  = blockIdx.y;
    const int b  = blockIdx.z;
    const int tid = threadIdx.x;
    const int tx = tid & 15, ty = tid >> 4;
    const int tx4 = tx * 4, ty4 = ty * 4;

    const int rowi = tid >> 4;          // 0..15 (load mapping)
    const int d4   = (tid & 15) * 4;

    // ---- load Q tile once, producing both biased variants (K-major) ----
    {
        const float4 bw = *(const float4*)&rwb[h*DH + d4];
        const float4 br = *(const float4*)&rrb[h*DH + d4];
        #pragma unroll
        for (int it = 0; it < 4; it++) {
            int ii = rowi + it*16;
            float4 q = *(const float4*)&QP[(size_t)(b*QL + i0 + ii)*EE + h*DH + d4];
            sm.qw[d4+0][ii] = q.x + bw.x; sm.qw[d4+1][ii] = q.y + bw.y;
            sm.qw[d4+2][ii] = q.z + bw.z; sm.qw[d4+3][ii] = q.w + bw.w;
            sm.qr[d4+0][ii] = q.x + br.x; sm.qr[d4+1][ii] = q.y + br.y;
            sm.qr[d4+2][ii] = q.z + br.z; sm.qr[d4+3][ii] = q.w + br.w;
        }
    }

    float m_i[4], l_i[4], O[4][4];
    #pragma unroll
    for (int r = 0; r < 4; r++) {
        m_i[r] = -INFINITY; l_i[r] = 0.f;
        #pragma unroll
        for (int c = 0; c < 4; c++) O[r][c] = 0.f;
    }

    int njt = (i0 + 63 + ML) / 64 + 1;          // skip fully masked k-tiles
    if (njt > KL/64) njt = KL/64;
    const int rb = tx4 - ty4 + 60;              // rh window base for this thread

    for (int jt = 0; jt < njt; jt++) {
        const int j0 = jt * 64;
        __syncthreads();   // previous-iteration consumers done

        // ---- load K (transposed), V (natural), R window ----
        {
            const float* kptr = KP + (size_t)(b*KL + j0)*EE + h*DH + d4;
            const float* vptr = VP + (size_t)(b*KL + j0)*EE + h*DH + d4;
            #pragma unroll
            for (int it = 0; it < 4; it++) {
                int jj = rowi + it*16;
                float4 kv = *(const float4*)(kptr + (size_t)jj*EE);
                sm.k[d4+0][jj] = kv.x; sm.k[d4+1][jj] = kv.y;
                sm.k[d4+2][jj] = kv.z; sm.k[d4+3][jj] = kv.w;
                *(float4*)&sm.v[jj][d4] = *(const float4*)(vptr + (size_t)jj*EE);
            }
            const int rbase = j0 - i0 + QL - 64;   // >= 0 always
            #pragma unroll
            for (int it = 0; it < 8; it++) {
                int dl = rowi + it*16;             // 0..127
                int dg = rbase + dl;
                float4 rv = make_float4(0.f, 0.f, 0.f, 0.f);
                if (dg < KL) rv = *(const float4*)&RP[(size_t)dg*EE + h*DH + d4];
                sm.r[d4+0][dl] = rv.x; sm.r[d4+1][dl] = rv.y;
                sm.r[d4+2][dl] = rv.z; sm.r[d4+3][dl] = rv.w;
            }
        }
        __syncthreads();

        // ---- scores: AC + rel-shifted BD ----
        float s[4][4];
        #pragma unroll
        for (int r = 0; r < 4; r++)
            #pragma unroll
            for (int c = 0; c < 4; c++) s[r][c] = 0.f;

        #pragma unroll 4
        for (int kk = 0; kk < 64; kk++) {
            float aw[4], aq[4], bk[4], rr[8];
            *(float4*)aw     = *(const float4*)&sm.qw[kk][ty4];
            *(float4*)aq     = *(const float4*)&sm.qr[kk][ty4];
            *(float4*)bk     = *(const float4*)&sm.k [kk][tx4];
            *(float4*)rr     = *(const float4*)&sm.r [kk][rb];
            *(float4*)(rr+4) = *(const float4*)&sm.r [kk][rb+4];
            #pragma unroll
            for (int r = 0; r < 4; r++)
                #pragma unroll
                for (int c = 0; c < 4; c++)
                    s[r][c] += aw[r]*bk[c] + aq[r]*rr[c - r + 3];
        }

        // ---- scale, mask, online softmax update ----
        #pragma unroll
        for (int r = 0; r < 4; r++) {
            const int ig = i0 + ty4 + r;
            #pragma unroll
            for (int c = 0; c < 4; c++) {
                const int jg = j0 + tx4 + c;
                s[r][c] = (jg > ig + ML) ? -1e30f : s[r][c] * 0.03125f;
            }
            float mx = fmaxf(fmaxf(s[r][0], s[r][1]), fmaxf(s[r][2], s[r][3]));
            mx = fmaxf(mx, __shfl_xor_sync(0xffffffffu, mx, 1, 16));
            mx = fmaxf(mx, __shfl_xor_sync(0xffffffffu, mx, 2, 16));
            mx = fmaxf(mx, __shfl_xor_sync(0xffffffffu, mx, 4, 16));
            mx = fmaxf(mx, __shfl_xor_sync(0xffffffffu, mx, 8, 16));
            const float mnew = fmaxf(m_i[r], mx);
            const float sf = __expf(m_i[r] - mnew);     // -inf -> 0 first tile
            float ps = 0.f;
            #pragma unroll
            for (int c = 0; c < 4; c++) {
                float p = __expf(s[r][c] - mnew);
                s[r][c] = p; ps += p;
            }
            ps += __shfl_xor_sync(0xffffffffu, ps, 1, 16);
            ps += __shfl_xor_sync(0xffffffffu, ps, 2, 16);
            ps += __shfl_xor_sync(0xffffffffu, ps, 4, 16);
            ps += __shfl_xor_sync(0xffffffffu, ps, 8, 16);
            l_i[r] = l_i[r]*sf + ps;
            m_i[r] = mnew;
            #pragma unroll
            for (int c = 0; c < 4; c++) O[r][c] *= sf;
            *(float4*)&sm.p[ty4+r][tx4] =
                make_float4(s[r][0], s[r][1], s[r][2], s[r][3]);
        }
        __syncthreads();

        // ---- O += P @ V ----
        #pragma unroll 2
        for (int j4 = 0; j4 < 64; j4 += 4) {
            float pr[4][4];
            #pragma unroll
            for (int r = 0; r < 4; r++)
                *(float4*)pr[r] = *(const float4*)&sm.p[ty4+r][j4];
            #pragma unroll
            for (int u = 0; u < 4; u++) {
                float4 vv = *(const float4*)&sm.v[j4+u][tx4];
                #pragma unroll
                for (int r = 0; r < 4; r++) {
                    O[r][0] += pr[r][u]*vv.x;
                    O[r][1] += pr[r][u]*vv.y;
                    O[r][2] += pr[r][u]*vv.z;
                    O[r][3] += pr[r][u]*vv.w;
                }
            }
        }
    }

    // ---- normalize + write [b, i, h*DH + d] ----
    #pragma unroll
    for (int r = 0; r < 4; r++) {
        const float inv = 1.0f / l_i[r];
        float4 o = make_float4(O[r][0]*inv, O[r][1]*inv, O[r][2]*inv, O[r][3]*inv);
        *(float4*)&OUT[(size_t)(b*QL + i0 + ty4 + r)*EE + h*DH + tx4] = o;
    }
}

// ---------------- residual add + LayerNorm (row = 1024) --------------------
__global__ __launch_bounds__(256) void add_ln_kernel(
    const float* __restrict__ a, const float* __restrict__ res,
    const float* __restrict__ g, const float* __restrict__ bt,
    float* __restrict__ out)
{
    __shared__ float red[256];
    const int row = blockIdx.x;
    const int tid = threadIdx.x;
    const size_t base = (size_t)row * EE;

    float v[4];
    #pragma unroll
    for (int u = 0; u < 4; u++)
        v[u] = a[base + u*256 + tid] + res[base + u*256 + tid];

    float s = v[0] + v[1] + v[2] + v[3];
    red[tid] = s; __syncthreads();
    for (int off = 128; off > 0; off >>= 1) {
        if (tid < off) red[tid] += red[tid + off];
        __syncthreads();
    }
    const float mu = red[0] * (1.0f / EE);
    __syncthreads();

    float d = 0.f;
    #pragma unroll
    for (int u = 0; u < 4; u++) { float t = v[u] - mu; d += t*t; }
    red[tid] = d; __syncthreads();
    for (int off = 128; off > 0; off >>= 1) {
        if (tid < off) red[tid] += red[tid + off];
        __syncthreads();
    }
    const float rs = rsqrtf(red[0] * (1.0f / EE) + 1e-3f);

    #pragma unroll
    for (int u = 0; u < 4; u++) {
        int c = u*256 + tid;
        out[base + c] = (v[u] - mu) * rs * g[c] + bt[c];
    }
}

// ---------------- launch ---------------------------------------------------
extern "C" void kernel_launch(void* const* d_in, const int* in_sizes, int n_in,
                              void* d_out, int out_size)
{
    const float* w      = (const float*)d_in[0];
    const float* r      = (const float*)d_in[1];
    const float* member = (const float*)d_in[2];
    /* d_in[3] = attn_mask (analytic causal mask used instead) */
    const float* Wq     = (const float*)d_in[4];
    const float* Wk     = (const float*)d_in[5];
    const float* Wv     = (const float*)d_in[6];
    const float* Wr     = (const float*)d_in[7];
    const float* Wo     = (const float*)d_in[8];
    const float* rwb    = (const float*)d_in[9];
    const float* rrb    = (const float*)d_in[10];
    const float* ln1g   = (const float*)d_in[11];
    const float* ln1b   = (const float*)d_in[12];
    const float* W1     = (const float*)d_in[13];
    const float* W2     = (const float*)d_in[14];
    const float* ln2g   = (const float*)d_in[15];
    const float* ln2b   = (const float*)d_in[16];
    float* out = (float*)d_out;

    float *cat, *kp, *vp, *qp, *rp, *att, *ao, *x, *hh, *y;
    cudaGetSymbolAddress((void**)&cat, g_cat);
    cudaGetSymbolAddress((void**)&kp,  g_kp);
    cudaGetSymbolAddress((void**)&vp,  g_vp);
    cudaGetSymbolAddress((void**)&qp,  g_qp);
    cudaGetSymbolAddress((void**)&rp,  g_rp);
    cudaGetSymbolAddress((void**)&att, g_att);
    cudaGetSymbolAddress((void**)&ao,  g_ao);
    cudaGetSymbolAddress((void**)&x,   g_x);
    cudaGetSymbolAddress((void**)&hh,  g_h);
    cudaGetSymbolAddress((void**)&y,   g_y);

    // 1. concat
    concat_kernel<<<(BB*KL*EE/4 + 255)/256, 256>>>(member, w);

    // 2. projections
    sgemm_kernel<0><<<dim3(EE/128, (BB*KL)/128), 256>>>(cat, Wk, kp, BB*KL, EE, EE);
    sgemm_kernel<0><<<dim3(EE/128, (BB*KL)/128), 256>>>(cat, Wv, vp, BB*KL, EE, EE);
    sgemm_kernel<0><<<dim3(EE/128, (BB*QL)/128), 256>>>(w,   Wq, qp, BB*QL, EE, EE);
    sgemm_kernel<0><<<dim3(EE/128, KL/128),      256>>>(r,   Wr, rp, KL,    EE, EE);

    // 3. fused relative attention
    static const int attn_smem = (int)sizeof(AttnSmem);
    cudaFuncSetAttribute(attn_kernel, cudaFuncAttributeMaxDynamicSharedMemorySize, attn_smem);
    attn_kernel<<<dim3(QL/64, HH, BB), 256, attn_smem>>>(qp, kp, vp, rp, rwb, rrb, att);

    // 4. output projection + LN1
    sgemm_kernel<0><<<dim3(EE/128, (BB*QL)/128), 256>>>(att, Wo, ao, BB*QL, EE, EE);
    add_ln_kernel<<<BB*QL, 256>>>(ao, w, ln1g, ln1b, x);

    // 5. FFN + LN2
    sgemm_kernel<1><<<dim3(FF/128, (BB*QL)/128), 256>>>(x,  W1, hh, BB*QL, FF, EE);
    sgemm_kernel<0><<<dim3(EE/128, (BB*QL)/128), 256>>>(hh, W2, y,  BB*QL, EE, FF);
    add_ln_kernel<<<BB*QL, 256>>>(y, x, ln2g, ln2b, out);
}

// round 3
// speedup vs baseline: 2.9868x; 2.9868x over previous
#include <cuda_runtime.h>
#include <cuda_bf16.h>
#include <math.h>
#include <stdint.h>

#define BB 2
#define QL 1024
#define ML 1024
#define KL 2048
#define EE 1024
#define HH 16
#define DH 64
#define FF 4096

typedef __nv_bfloat16 bf16;

// ---------------- scratch (static device globals) ---------------------------
__device__ float g_kp [BB*KL*EE];
__device__ float g_vp [BB*KL*EE];
__device__ float g_qp [BB*QL*EE];
__device__ float g_rp [KL*EE];
__device__ float g_ao [BB*QL*EE];
__device__ float g_x  [BB*QL*EE];
__device__ float g_y  [BB*QL*EE];

__device__ bf16 g_cat_h[BB*KL*EE], g_cat_l[BB*KL*EE];
__device__ bf16 g_w_h  [BB*QL*EE], g_w_l  [BB*QL*EE];
__device__ bf16 g_r_h  [KL*EE],    g_r_l  [KL*EE];
__device__ bf16 g_att_h[BB*QL*EE], g_att_l[BB*QL*EE];
__device__ bf16 g_x_h  [BB*QL*EE], g_x_l  [BB*QL*EE];
__device__ bf16 g_hh_h [BB*QL*FF], g_hh_l [BB*QL*FF];
__device__ bf16 g_Wq_h[EE*EE], g_Wq_l[EE*EE];
__device__ bf16 g_Wk_h[EE*EE], g_Wk_l[EE*EE];
__device__ bf16 g_Wv_h[EE*EE], g_Wv_l[EE*EE];
__device__ bf16 g_Wr_h[EE*EE], g_Wr_l[EE*EE];
__device__ bf16 g_Wo_h[EE*EE], g_Wo_l[EE*EE];
__device__ bf16 g_W1_h[FF*EE], g_W1_l[FF*EE];   // W1^T : [4096,1024]
__device__ bf16 g_W2_h[EE*FF], g_W2_l[EE*FF];   // W2^T : [1024,4096]

// ---------------- helpers ----------------------------------------------------
__device__ __forceinline__ uint32_t smem_u32(const void* p) {
    uint32_t a;
    asm("{ .reg .u64 t; cvta.to.shared.u64 t, %1; cvt.u32.u64 %0, t; }"
        : "=r"(a) : "l"(p));
    return a;
}
__device__ __forceinline__ void split2(float v, bf16& h, bf16& l) {
    h = __float2bfloat16(v);
    l = __float2bfloat16(v - __bfloat162float(h));
}
__device__ __forceinline__ void ldsm4(uint32_t& r0, uint32_t& r1,
                                      uint32_t& r2, uint32_t& r3, uint32_t addr) {
    asm volatile("ldmatrix.sync.aligned.m8n8.x4.shared.b16 {%0,%1,%2,%3}, [%4];"
        : "=r"(r0), "=r"(r1), "=r"(r2), "=r"(r3) : "r"(addr));
}
__device__ __forceinline__ void mma16816(float* d, const uint32_t* a, const uint32_t* b) {
    asm volatile(
        "mma.sync.aligned.m16n8k16.row.col.f32.bf16.bf16.f32 "
        "{%0,%1,%2,%3}, {%4,%5,%6,%7}, {%8,%9}, {%0,%1,%2,%3};"
        : "+f"(d[0]), "+f"(d[1]), "+f"(d[2]), "+f"(d[3])
        : "r"(a[0]), "r"(a[1]), "r"(a[2]), "r"(a[3]), "r"(b[0]), "r"(b[1]));
}

// ---------------- conversion kernels ----------------------------------------
__global__ __launch_bounds__(256) void concat_convert_kernel(
    const float* __restrict__ member, const float* __restrict__ w,
    bf16* __restrict__ dh, bf16* __restrict__ dl)
{
    int idx = blockIdx.x * 256 + threadIdx.x;     // float4 id
    int fidx = idx * 4;
    int b   = fidx / (KL*EE);
    int rem = fidx % (KL*EE);
    int s   = rem / EE;
    int e   = rem % EE;
    float4 v;
    if (s < ML) v = *(const float4*)&member[(size_t)(b*ML + s)*EE + e];
    else        v = *(const float4*)&w[(size_t)(b*QL + (s-ML))*EE + e];
    bf16 h0,l0,h1,l1,h2,l2,h3,l3;
    split2(v.x,h0,l0); split2(v.y,h1,l1); split2(v.z,h2,l2); split2(v.w,h3,l3);
    __nv_bfloat162 hp0, hp1, lp0, lp1;
    hp0.x=h0; hp0.y=h1; hp1.x=h2; hp1.y=h3;
    lp0.x=l0; lp0.y=l1; lp1.x=l2; lp1.y=l3;
    ((__nv_bfloat162*)dh)[idx*2]   = hp0; ((__nv_bfloat162*)dh)[idx*2+1] = hp1;
    ((__nv_bfloat162*)dl)[idx*2]   = lp0; ((__nv_bfloat162*)dl)[idx*2+1] = lp1;
}

__global__ __launch_bounds__(256) void convert_split_kernel(
    const float* __restrict__ s, bf16* __restrict__ dh, bf16* __restrict__ dl)
{
    int idx = blockIdx.x * 256 + threadIdx.x;     // float4 id
    float4 v = ((const float4*)s)[idx];
    bf16 h0,l0,h1,l1,h2,l2,h3,l3;
    split2(v.x,h0,l0); split2(v.y,h1,l1); split2(v.z,h2,l2); split2(v.w,h3,l3);
    __nv_bfloat162 hp0, hp1, lp0, lp1;
    hp0.x=h0; hp0.y=h1; hp1.x=h2; hp1.y=h3;
    lp0.x=l0; lp0.y=l1; lp1.x=l2; lp1.y=l3;
    ((__nv_bfloat162*)dh)[idx*2]   = hp0; ((__nv_bfloat162*)dh)[idx*2+1] = hp1;
    ((__nv_bfloat162*)dl)[idx*2]   = lp0; ((__nv_bfloat162*)dl)[idx*2+1] = lp1;
}

// W [K,N] row-major -> W^T [N,K] bf16 hi/lo
__global__ void transpose_convert_kernel(
    const float* __restrict__ s, bf16* __restrict__ dh, bf16* __restrict__ dl,
    int K, int N)
{
    __shared__ float t[32][33];
    int n0 = blockIdx.x * 32, k0 = blockIdx.y * 32;
    int tx = threadIdx.x, ty = threadIdx.y;       // 32 x 8
    #pragma unroll
    for (int i = 0; i < 4; i++)
        t[ty + i*8][tx] = s[(size_t)(k0 + ty + i*8)*N + n0 + tx];
    __syncthreads();
    #pragma unroll
    for (int i = 0; i < 4; i++) {
        float v = t[tx][ty + i*8];
        bf16 h, l; split2(v, h, l);
        size_t o = (size_t)(n0 + ty + i*8)*K + k0 + tx;
        dh[o] = h; dl[o] = l;
    }
}

// ---------------- bf16x3 warp-MMA GEMM --------------------------------------
// C[M,N] = (Ah+Al)[M,K] @ ((Bh+Bl)[N,K])^T  (lo*lo dropped)
// 128x128 CTA tile, 8 warps (2x4 grid, 64x32 warp tiles), BK=32,
// double-buffered smem, stride-80B rows (conflict-free ldmatrix).
#define SROW     40                 // bf16 per smem row (80 bytes)
#define OPELEMS  (128*SROW)         // 5120 bf16 per operand tile
#define OPBYTES  (OPELEMS*2)        // 10240
#define BUFELEMS (4*OPELEMS)        // Ah,Al,Bh,Bl
#define BUFBYTES (BUFELEMS*2)       // 40960
#define GSM_TOTAL (2*BUFBYTES)      // 81920

template<int EPI>   // 0 = fp32 store, 1 = relu + bf16 hi/lo split store
__global__ __launch_bounds__(256) void mma_gemm(
    const bf16* __restrict__ Ah, const bf16* __restrict__ Al,
    const bf16* __restrict__ Bh, const bf16* __restrict__ Bl,
    float* __restrict__ Cf, bf16* __restrict__ Ch, bf16* __restrict__ Cl,
    int M, int N, int K)
{
    extern __shared__ bf16 smem[];
    const int tid = threadIdx.x, wid = tid >> 5, lane = tid & 31;
    const int row0 = blockIdx.y * 128, col0 = blockIdx.x * 128;
    const int wm = wid & 1, wn = wid >> 1;
    const uint32_t sbase0 = smem_u32(smem);

    float acc[4][4][4];
    #pragma unroll
    for (int mt = 0; mt < 4; mt++)
        #pragma unroll
        for (int nt = 0; nt < 4; nt++)
            #pragma unroll
            for (int u = 0; u < 4; u++) acc[mt][nt][u] = 0.f;

    const int nc = K >> 5;
    const int r0q = tid >> 2, c0q = (tid & 3) * 8;            // load mapping
    const int r1q = (tid + 256) >> 2, c1q = ((tid + 256) & 3) * 8;

    uint4 st[8];

    // ---- prologue: load + store chunk 0 ----
    {
        const size_t a0 = (size_t)(row0 + r0q)*K + c0q;
        const size_t a1 = (size_t)(row0 + r1q)*K + c1q;
        const size_t b0 = (size_t)(col0 + r0q)*K + c0q;
        const size_t b1 = (size_t)(col0 + r1q)*K + c1q;
        st[0] = *(const uint4*)(Ah + a0); st[1] = *(const uint4*)(Al + a0);
        st[2] = *(const uint4*)(Bh + b0); st[3] = *(const uint4*)(Bl + b0);
        st[4] = *(const uint4*)(Ah + a1); st[5] = *(const uint4*)(Al + a1);
        st[6] = *(const uint4*)(Bh + b1); st[7] = *(const uint4*)(Bl + b1);
        bf16* bp = smem;
        const int s0 = r0q*SROW + c0q, s1 = r1q*SROW + c1q;
        *(uint4*)(bp + s0)             = st[0];
        *(uint4*)(bp + OPELEMS + s0)   = st[1];
        *(uint4*)(bp + 2*OPELEMS + s0) = st[2];
        *(uint4*)(bp + 3*OPELEMS + s0) = st[3];
        *(uint4*)(bp + s1)             = st[4];
        *(uint4*)(bp + OPELEMS + s1)   = st[5];
        *(uint4*)(bp + 2*OPELEMS + s1) = st[6];
        *(uint4*)(bp + 3*OPELEMS + s1) = st[7];
    }

    // precomputed ldmatrix lane addressing (byte offsets within buffer)
    const uint32_t a_row_off = (uint32_t)(wm*64 + (lane & 15)) * 80
                             + (uint32_t)(lane >> 4) * 16;           // + ks*32 + mt*1280
    const uint32_t b_row_off = 2*OPBYTES
                             + (uint32_t)(wn*32 + (lane & 7) + ((lane >> 4) & 1)*8) * 80
                             + (uint32_t)((lane >> 3) & 1) * 16;     // + ks*32 + p*1280

    for (int c = 0; c < nc; c++) {
        __syncthreads();
        // issue next chunk's global loads (latency hidden behind compute)
        if (c + 1 < nc) {
            const size_t k0 = (size_t)(c + 1) * 32;
            const size_t a0 = (size_t)(row0 + r0q)*K + k0 + c0q;
            const size_t a1 = (size_t)(row0 + r1q)*K + k0 + c1q;
            const size_t b0 = (size_t)(col0 + r0q)*K + k0 + c0q;
            const size_t b1 = (size_t)(col0 + r1q)*K + k0 + c1q;
            st[0] = *(const uint4*)(Ah + a0); st[1] = *(const uint4*)(Al + a0);
            st[2] = *(const uint4*)(Bh + b0); st[3] = *(const uint4*)(Bl + b0);
            st[4] = *(const uint4*)(Ah + a1); st[5] = *(const uint4*)(Al + a1);
            st[6] = *(const uint4*)(Bh + b1); st[7] = *(const uint4*)(Bl + b1);
        }

        // ---- compute on buffer c&1 ----
        const uint32_t sb = sbase0 + (uint32_t)(c & 1) * BUFBYTES;
        #pragma unroll
        for (int ks = 0; ks < 2; ks++) {
            uint32_t ah[4][4], al[4][4], bh[4][2], bl[4][2];
            const uint32_t abase = sb + a_row_off + ks*32;
            #pragma unroll
            for (int mt = 0; mt < 4; mt++) {
                const uint32_t ad = abase + mt*(16*80);
                ldsm4(ah[mt][0], ah[mt][1], ah[mt][2], ah[mt][3], ad);
                ldsm4(al[mt][0], al[mt][1], al[mt][2], al[mt][3], ad + OPBYTES);
            }
            const uint32_t bbase = sb + b_row_off + ks*32;
            #pragma unroll
            for (int p = 0; p < 2; p++) {
                const uint32_t bd = bbase + p*(16*80);
                ldsm4(bh[2*p][0], bh[2*p][1], bh[2*p+1][0], bh[2*p+1][1], bd);
                ldsm4(bl[2*p][0], bl[2*p][1], bl[2*p+1][0], bl[2*p+1][1], bd + OPBYTES);
            }
            #pragma unroll
            for (int mt = 0; mt < 4; mt++)
                #pragma unroll
                for (int nt = 0; nt < 4; nt++) {
                    mma16816(acc[mt][nt], ah[mt], bh[nt]);
                    mma16816(acc[mt][nt], ah[mt], bl[nt]);
                    mma16816(acc[mt][nt], al[mt], bh[nt]);
                }
        }

        // store next chunk into the other buffer (safe: all warps passed the
        // top-of-loop barrier, so nobody still reads buffer (c+1)&1)
        if (c + 1 < nc) {
            bf16* bp = smem + ((c + 1) & 1) * BUFELEMS;
            const int s0 = r0q*SROW + c0q, s1 = r1q*SROW + c1q;
            *(uint4*)(bp + s0)             = st[0];
            *(uint4*)(bp + OPELEMS + s0)   = st[1];
            *(uint4*)(bp + 2*OPELEMS + s0) = st[2];
            *(uint4*)(bp + 3*OPELEMS + s0) = st[3];
            *(uint4*)(bp + s1)             = st[4];
            *(uint4*)(bp + OPELEMS + s1)   = st[5];
            *(uint4*)(bp + 2*OPELEMS + s1) = st[6];
            *(uint4*)(bp + 3*OPELEMS + s1) = st[7];
        }
    }

    // ---- epilogue ----
    const int er = lane >> 2, ec = (lane & 3) * 2;
    #pragma unroll
    for (int mt = 0; mt < 4; mt++) {
        #pragma unroll
        for (int nt = 0; nt < 4; nt++) {
            const int grow = row0 + wm*64 + mt*16 + er;
            const int gcol = col0 + wn*32 + nt*8 + ec;
            if (EPI == 0) {
                *(float2*)&Cf[(size_t)grow*N + gcol] =
                    make_float2(acc[mt][nt][0], acc[mt][nt][1]);
                *(float2*)&Cf[(size_t)(grow+8)*N + gcol] =
                    make_float2(acc[mt][nt][2], acc[mt][nt][3]);
            } else {
                float f0 = fmaxf(acc[mt][nt][0], 0.f);
                float f1 = fmaxf(acc[mt][nt][1], 0.f);
                float f2 = fmaxf(acc[mt][nt][2], 0.f);
                float f3 = fmaxf(acc[mt][nt][3], 0.f);
                bf16 h0,l0,h1,l1,h2,l2,h3,l3;
                split2(f0,h0,l0); split2(f1,h1,l1);
                split2(f2,h2,l2); split2(f3,h3,l3);
                __nv_bfloat162 hp0, lp0, hp1, lp1;
                hp0.x=h0; hp0.y=h1; lp0.x=l0; lp0.y=l1;
                hp1.x=h2; hp1.y=h3; lp1.x=l2; lp1.y=l3;
                *(__nv_bfloat162*)&Ch[(size_t)grow*N + gcol]     = hp0;
                *(__nv_bfloat162*)&Cl[(size_t)grow*N + gcol]     = lp0;
                *(__nv_bfloat162*)&Ch[(size_t)(grow+8)*N + gcol] = hp1;
                *(__nv_bfloat162*)&Cl[(size_t)(grow+8)*N + gcol] = lp1;
            }
        }
    }
}

// ---------------- fused rel-attention (fp32 SIMT; bf16-split output) --------
struct AttnSmem {
    float qw[64][68];
    float qr[64][68];
    float k [64][68];
    float v [64][64];
    float r [64][132];
    float p [64][64];
};

__global__ __launch_bounds__(256) void attn_kernel(
    const float* __restrict__ QP, const float* __restrict__ KP,
    const float* __restrict__ VP, const float* __restrict__ RP,
    const float* __restrict__ rwb, const float* __restrict__ rrb,
    bf16* __restrict__ OH, bf16* __restrict__ OL)
{
    extern __shared__ char smem_raw[];
    AttnSmem& sm = *reinterpret_cast<AttnSmem*>(smem_raw);

    const int i0 = blockIdx.x * 64;
    const int h  = blockIdx.y;
    const int b  = blockIdx.z;
    const int tid = threadIdx.x;
    const int tx = tid & 15, ty = tid >> 4;
    const int tx4 = tx * 4, ty4 = ty * 4;
    const int rowi = tid >> 4;
    const int d4   = (tid & 15) * 4;

    {
        const float4 bw = *(const float4*)&rwb[h*DH + d4];
        const float4 br = *(const float4*)&rrb[h*DH + d4];
        #pragma unroll
        for (int it = 0; it < 4; it++) {
            int ii = rowi + it*16;
            float4 q = *(const float4*)&QP[(size_t)(b*QL + i0 + ii)*EE + h*DH + d4];
            sm.qw[d4+0][ii] = q.x + bw.x; sm.qw[d4+1][ii] = q.y + bw.y;
            sm.qw[d4+2][ii] = q.z + bw.z; sm.qw[d4+3][ii] = q.w + bw.w;
            sm.qr[d4+0][ii] = q.x + br.x; sm.qr[d4+1][ii] = q.y + br.y;
            sm.qr[d4+2][ii] = q.z + br.z; sm.qr[d4+3][ii] = q.w + br.w;
        }
    }

    float m_i[4], l_i[4], O[4][4];
    #pragma unroll
    for (int r = 0; r < 4; r++) {
        m_i[r] = -INFINITY; l_i[r] = 0.f;
        #pragma unroll
        for (int c = 0; c < 4; c++) O[r][c] = 0.f;
    }

    int njt = (i0 + 63 + ML) / 64 + 1;
    if (njt > KL/64) njt = KL/64;
    const int rb = tx4 - ty4 + 60;

    for (int jt = 0; jt < njt; jt++) {
        const int j0 = jt * 64;
        __syncthreads();
        {
            const float* kptr = KP + (size_t)(b*KL + j0)*EE + h*DH + d4;
            const float* vptr = VP + (size_t)(b*KL + j0)*EE + h*DH + d4;
            #pragma unroll
            for (int it = 0; it < 4; it++) {
                int jj = rowi + it*16;
                float4 kv = *(const float4*)(kptr + (size_t)jj*EE);
                sm.k[d4+0][jj] = kv.x; sm.k[d4+1][jj] = kv.y;
                sm.k[d4+2][jj] = kv.z; sm.k[d4+3][jj] = kv.w;
                *(float4*)&sm.v[jj][d4] = *(const float4*)(vptr + (size_t)jj*EE);
            }
            const int rbase = j0 - i0 + QL - 64;
            #pragma unroll
            for (int it = 0; it < 8; it++) {
                int dl = rowi + it*16;
                int dg = rbase + dl;
                float4 rv = make_float4(0.f, 0.f, 0.f, 0.f);
                if (dg < KL) rv = *(const float4*)&RP[(size_t)dg*EE + h*DH + d4];
                sm.r[d4+0][dl] = rv.x; sm.r[d4+1][dl] = rv.y;
                sm.r[d4+2][dl] = rv.z; sm.r[d4+3][dl] = rv.w;
            }
        }
        __syncthreads();

        float s[4][4];
        #pragma unroll
        for (int r = 0; r < 4; r++)
            #pragma unroll
            for (int c = 0; c < 4; c++) s[r][c] = 0.f;

        #pragma unroll 4
        for (int kk = 0; kk < 64; kk++) {
            float aw[4], aq[4], bk[4], rr[8];
            *(float4*)aw     = *(const float4*)&sm.qw[kk][ty4];
            *(float4*)aq     = *(const float4*)&sm.qr[kk][ty4];
            *(float4*)bk     = *(const float4*)&sm.k [kk][tx4];
            *(float4*)rr     = *(const float4*)&sm.r [kk][rb];
            *(float4*)(rr+4) = *(const float4*)&sm.r [kk][rb+4];
            #pragma unroll
            for (int r = 0; r < 4; r++)
                #pragma unroll
                for (int c = 0; c < 4; c++)
                    s[r][c] += aw[r]*bk[c] + aq[r]*rr[c - r + 3];
        }

        #pragma unroll
        for (int r = 0; r < 4; r++) {
            const int ig = i0 + ty4 + r;
            #pragma unroll
            for (int c = 0; c < 4; c++) {
                const int jg = j0 + tx4 + c;
                s[r][c] = (jg > ig + ML) ? -1e30f : s[r][c] * 0.03125f;
            }
            float mx = fmaxf(fmaxf(s[r][0], s[r][1]), fmaxf(s[r][2], s[r][3]));
            mx = fmaxf(mx, __shfl_xor_sync(0xffffffffu, mx, 1, 16));
            mx = fmaxf(mx, __shfl_xor_sync(0xffffffffu, mx, 2, 16));
            mx = fmaxf(mx, __shfl_xor_sync(0xffffffffu, mx, 4, 16));
            mx = fmaxf(mx, __shfl_xor_sync(0xffffffffu, mx, 8, 16));
            const float mnew = fmaxf(m_i[r], mx);
            const float sf = __expf(m_i[r] - mnew);
            float ps = 0.f;
            #pragma unroll
            for (int c = 0; c < 4; c++) {
                float p = __expf(s[r][c] - mnew);
                s[r][c] = p; ps += p;
            }
            ps += __shfl_xor_sync(0xffffffffu, ps, 1, 16);
            ps += __shfl_xor_sync(0xffffffffu, ps, 2, 16);
            ps += __shfl_xor_sync(0xffffffffu, ps, 4, 16);
            ps += __shfl_xor_sync(0xffffffffu, ps, 8, 16);
            l_i[r] = l_i[r]*sf + ps;
            m_i[r] = mnew;
            #pragma unroll
            for (int c = 0; c < 4; c++) O[r][c] *= sf;
            *(float4*)&sm.p[ty4+r][tx4] =
                make_float4(s[r][0], s[r][1], s[r][2], s[r][3]);
        }
        __syncthreads();

        #pragma unroll 2
        for (int j4 = 0; j4 < 64; j4 += 4) {
            float pr[4][4];
            #pragma unroll
            for (int r = 0; r < 4; r++)
                *(float4*)pr[r] = *(const float4*)&sm.p[ty4+r][j4];
            #pragma unroll
            for (int u = 0; u < 4; u++) {
                float4 vv = *(const float4*)&sm.v[j4+u][tx4];
                #pragma unroll
                for (int r = 0; r < 4; r++) {
                    O[r][0] += pr[r][u]*vv.x;
                    O[r][1] += pr[r][u]*vv.y;
                    O[r][2] += pr[r][u]*vv.z;
                    O[r][3] += pr[r][u]*vv.w;
                }
            }
        }
    }

    #pragma unroll
    for (int r = 0; r < 4; r++) {
        const float inv = 1.0f / l_i[r];
        float o0 = O[r][0]*inv, o1 = O[r][1]*inv, o2 = O[r][2]*inv, o3 = O[r][3]*inv;
        const size_t base = (size_t)(b*QL + i0 + ty4 + r)*EE + h*DH + tx4;
        bf16 h0,l0,h1,l1,h2,l2,h3,l3;
        split2(o0,h0,l0); split2(o1,h1,l1); split2(o2,h2,l2); split2(o3,h3,l3);
        __nv_bfloat162 hp0, hp1, lp0, lp1;
        hp0.x=h0; hp0.y=h1; hp1.x=h2; hp1.y=h3;
        lp0.x=l0; lp0.y=l1; lp1.x=l2; lp1.y=l3;
        *(__nv_bfloat162*)(OH + base)     = hp0;
        *(__nv_bfloat162*)(OH + base + 2) = hp1;
        *(__nv_bfloat162*)(OL + base)     = lp0;
        *(__nv_bfloat162*)(OL + base + 2) = lp1;
    }
}

// ---------------- residual add + LayerNorm ----------------------------------
template<int WB>
__global__ __launch_bounds__(256) void add_ln_kernel(
    const float* __restrict__ a, const float* __restrict__ res,
    const float* __restrict__ g, const float* __restrict__ bt,
    float* __restrict__ out, bf16* __restrict__ oh, bf16* __restrict__ ol)
{
    __shared__ float red[256];
    const int row = blockIdx.x;
    const int tid = threadIdx.x;
    const size_t base = (size_t)row * EE;

    float v[4];
    #pragma unroll
    for (int u = 0; u < 4; u++)
        v[u] = a[base + u*256 + tid] + res[base + u*256 + tid];

    float s = v[0] + v[1] + v[2] + v[3];
    red[tid] = s; __syncthreads();
    for (int off = 128; off > 0; off >>= 1) {
        if (tid < off) red[tid] += red[tid + off];
        __syncthreads();
    }
    const float mu = red[0] * (1.0f / EE);
    __syncthreads();

    float d = 0.f;
    #pragma unroll
    for (int u = 0; u < 4; u++) { float t = v[u] - mu; d += t*t; }
    red[tid] = d; __syncthreads();
    for (int off = 128; off > 0; off >>= 1) {
        if (tid < off) red[tid] += red[tid + off];
        __syncthreads();
    }
    const float rs = rsqrtf(red[0] * (1.0f / EE) + 1e-3f);

    #pragma unroll
    for (int u = 0; u < 4; u++) {
        int c = u*256 + tid;
        float o = (v[u] - mu) * rs * g[c] + bt[c];
        out[base + c] = o;
        if (WB) {
            bf16 hh_, ll_; split2(o, hh_, ll_);
            oh[base + c] = hh_; ol[base + c] = ll_;
        }
    }
}

// ---------------- launch ----------------------------------------------------
extern "C" void kernel_launch(void* const* d_in, const int* in_sizes, int n_in,
                              void* d_out, int out_size)
{
    const float* w      = (const float*)d_in[0];
    const float* r      = (const float*)d_in[1];
    const float* member = (const float*)d_in[2];
    const float* Wq     = (const float*)d_in[4];
    const float* Wk     = (const float*)d_in[5];
    const float* Wv     = (const float*)d_in[6];
    const float* Wr     = (const float*)d_in[7];
    const float* Wo     = (const float*)d_in[8];
    const float* rwb    = (const float*)d_in[9];
    const float* rrb    = (const float*)d_in[10];
    const float* ln1g   = (const float*)d_in[11];
    const float* ln1b   = (const float*)d_in[12];
    const float* W1     = (const float*)d_in[13];
    const float* W2     = (const float*)d_in[14];
    const float* ln2g   = (const float*)d_in[15];
    const float* ln2b   = (const float*)d_in[16];
    float* out = (float*)d_out;

    float *kp,*vp,*qp,*rp,*ao,*x,*y;
    cudaGetSymbolAddress((void**)&kp, g_kp);
    cudaGetSymbolAddress((void**)&vp, g_vp);
    cudaGetSymbolAddress((void**)&qp, g_qp);
    cudaGetSymbolAddress((void**)&rp, g_rp);
    cudaGetSymbolAddress((void**)&ao, g_ao);
    cudaGetSymbolAddress((void**)&x,  g_x);
    cudaGetSymbolAddress((void**)&y,  g_y);
    bf16 *cath,*catl,*wh,*wl,*rh,*rl,*atth,*attl,*xh,*xl,*hhh,*hhl;
    bf16 *wqh,*wql,*wkh,*wkl,*wvh,*wvl,*wrh,*wrl,*woh,*wol,*w1h,*w1l,*w2h,*w2l;
    cudaGetSymbolAddress((void**)&cath, g_cat_h); cudaGetSymbolAddress((void**)&catl, g_cat_l);
    cudaGetSymbolAddress((void**)&wh,   g_w_h);   cudaGetSymbolAddress((void**)&wl,   g_w_l);
    cudaGetSymbolAddress((void**)&rh,   g_r_h);   cudaGetSymbolAddress((void**)&rl,   g_r_l);
    cudaGetSymbolAddress((void**)&atth, g_att_h); cudaGetSymbolAddress((void**)&attl, g_att_l);
    cudaGetSymbolAddress((void**)&xh,   g_x_h);   cudaGetSymbolAddress((void**)&xl,   g_x_l);
    cudaGetSymbolAddress((void**)&hhh,  g_hh_h);  cudaGetSymbolAddress((void**)&hhl,  g_hh_l);
    cudaGetSymbolAddress((void**)&wqh,  g_Wq_h);  cudaGetSymbolAddress((void**)&wql,  g_Wq_l);
    cudaGetSymbolAddress((void**)&wkh,  g_Wk_h);  cudaGetSymbolAddress((void**)&wkl,  g_Wk_l);
    cudaGetSymbolAddress((void**)&wvh,  g_Wv_h);  cudaGetSymbolAddress((void**)&wvl,  g_Wv_l);
    cudaGetSymbolAddress((void**)&wrh,  g_Wr_h);  cudaGetSymbolAddress((void**)&wrl,  g_Wr_l);
    cudaGetSymbolAddress((void**)&woh,  g_Wo_h);  cudaGetSymbolAddress((void**)&wol,  g_Wo_l);
    cudaGetSymbolAddress((void**)&w1h,  g_W1_h);  cudaGetSymbolAddress((void**)&w1l,  g_W1_l);
    cudaGetSymbolAddress((void**)&w2h,  g_W2_h);  cudaGetSymbolAddress((void**)&w2l,  g_W2_l);

    cudaFuncSetAttribute(mma_gemm<0>, cudaFuncAttributeMaxDynamicSharedMemorySize, GSM_TOTAL);
    cudaFuncSetAttribute(mma_gemm<1>, cudaFuncAttributeMaxDynamicSharedMemorySize, GSM_TOTAL);

    // input conversions
    concat_convert_kernel<<<BB*KL*EE/4/256, 256>>>(member, w, cath, catl);
    convert_split_kernel <<<BB*QL*EE/4/256, 256>>>(w, wh, wl);
    convert_split_kernel <<<KL*EE/4/256,    256>>>(r, rh, rl);
    transpose_convert_kernel<<<dim3(EE/32, EE/32), dim3(32,8)>>>(Wq, wqh, wql, EE, EE);
    transpose_convert_kernel<<<dim3(EE/32, EE/32), dim3(32,8)>>>(Wk, wkh, wkl, EE, EE);
    transpose_convert_kernel<<<dim3(EE/32, EE/32), dim3(32,8)>>>(Wv, wvh, wvl, EE, EE);
    transpose_convert_kernel<<<dim3(EE/32, EE/32), dim3(32,8)>>>(Wr, wrh, wrl, EE, EE);
    transpose_convert_kernel<<<dim3(EE/32, EE/32), dim3(32,8)>>>(Wo, woh, wol, EE, EE);
    transpose_convert_kernel<<<dim3(FF/32, EE/32), dim3(32,8)>>>(W1, w1h, w1l, EE, FF);
    transpose_convert_kernel<<<dim3(EE/32, FF/32), dim3(32,8)>>>(W2, w2h, w2l, FF, EE);

    // projections
    mma_gemm<0><<<dim3(EE/128, (BB*KL)/128), 256, GSM_TOTAL>>>(
        cath, catl, wkh, wkl, kp, nullptr, nullptr, BB*KL, EE, EE);
    mma_gemm<0><<<dim3(EE/128, (BB*KL)/128), 256, GSM_TOTAL>>>(
        cath, catl, wvh, wvl, vp, nullptr, nullptr, BB*KL, EE, EE);
    mma_gemm<0><<<dim3(EE/128, (BB*QL)/128), 256, GSM_TOTAL>>>(
        wh, wl, wqh, wql, qp, nullptr, nullptr, BB*QL, EE, EE);
    mma_gemm<0><<<dim3(EE/128, KL/128), 256, GSM_TOTAL>>>(
        rh, rl, wrh, wrl, rp, nullptr, nullptr, KL, EE, EE);

    // attention
    static const int attn_smem = (int)sizeof(AttnSmem);
    cudaFuncSetAttribute(attn_kernel, cudaFuncAttributeMaxDynamicSharedMemorySize, attn_smem);
    attn_kernel<<<dim3(QL/64, HH, BB), 256, attn_smem>>>(qp, kp, vp, rp, rwb, rrb, atth, attl);

    // output projection + LN1
    mma_gemm<0><<<dim3(EE/128, (BB*QL)/128), 256, GSM_TOTAL>>>(
        atth, attl, woh, wol, ao, nullptr, nullptr, BB*QL, EE, EE);
    add_ln_kernel<1><<<BB*QL, 256>>>(ao, w, ln1g, ln1b, x, xh, xl);

    // FFN + LN2
    mma_gemm<1><<<dim3(FF/128, (BB*QL)/128), 256, GSM_TOTAL>>>(
        xh, xl, w1h, w1l, nullptr, hhh, hhl, BB*QL, FF, EE);
    mma_gemm<0><<<dim3(EE/128, (BB*QL)/128), 256, GSM_TOTAL>>>(
        hhh, hhl, w2h, w2l, y, nullptr, nullptr, BB*QL, EE, FF);
    add_ln_kernel<0><<<BB*QL, 256>>>(y, x, ln2g, ln2b, out, nullptr, nullptr);
}

// round 4
// speedup vs baseline: 4.4522x; 1.4906x over previous
#include <cuda_runtime.h>
#include <cuda_bf16.h>
#include <math.h>
#include <stdint.h>

#define BB 2
#define QL 1024
#define ML 1024
#define KL 2048
#define EE 1024
#define HH 16
#define DH 64
#define FF 4096

typedef __nv_bfloat16 bf16;

// ---------------- scratch (static device globals) ---------------------------
__device__ float g_ao [BB*QL*EE];
__device__ float g_x  [BB*QL*EE];
__device__ float g_y  [BB*QL*EE];

__device__ bf16 g_cat_h[BB*KL*EE], g_cat_l[BB*KL*EE];
__device__ bf16 g_w_h  [BB*QL*EE], g_w_l  [BB*QL*EE];
__device__ bf16 g_r_h  [KL*EE],    g_r_l  [KL*EE];
__device__ bf16 g_q_h  [BB*QL*EE], g_q_l  [BB*QL*EE];
__device__ bf16 g_k_h  [BB*KL*EE], g_k_l  [BB*KL*EE];
__device__ bf16 g_v_h  [BB*KL*EE], g_v_l  [BB*KL*EE];
__device__ bf16 g_rpj_h[KL*EE],    g_rpj_l[KL*EE];
__device__ bf16 g_att_h[BB*QL*EE], g_att_l[BB*QL*EE];
__device__ bf16 g_x_h  [BB*QL*EE], g_x_l  [BB*QL*EE];
__device__ bf16 g_hh_h [BB*QL*FF], g_hh_l [BB*QL*FF];
__device__ bf16 g_Wq_h[EE*EE], g_Wq_l[EE*EE];
__device__ bf16 g_Wk_h[EE*EE], g_Wk_l[EE*EE];
__device__ bf16 g_Wv_h[EE*EE], g_Wv_l[EE*EE];
__device__ bf16 g_Wr_h[EE*EE], g_Wr_l[EE*EE];
__device__ bf16 g_Wo_h[EE*EE], g_Wo_l[EE*EE];
__device__ bf16 g_W1_h[FF*EE], g_W1_l[FF*EE];
__device__ bf16 g_W2_h[EE*FF], g_W2_l[EE*FF];

// ---------------- helpers ----------------------------------------------------
__device__ __forceinline__ uint32_t smem_u32(const void* p) {
    uint32_t a;
    asm("{ .reg .u64 t; cvta.to.shared.u64 t, %1; cvt.u32.u64 %0, t; }"
        : "=r"(a) : "l"(p));
    return a;
}
__device__ __forceinline__ void split2(float v, bf16& h, bf16& l) {
    h = __float2bfloat16(v);
    l = __float2bfloat16(v - __bfloat162float(h));
}
__device__ __forceinline__ void ldsm4(uint32_t& r0, uint32_t& r1,
                                      uint32_t& r2, uint32_t& r3, uint32_t addr) {
    asm volatile("ldmatrix.sync.aligned.m8n8.x4.shared.b16 {%0,%1,%2,%3}, [%4];"
        : "=r"(r0), "=r"(r1), "=r"(r2), "=r"(r3) : "r"(addr));
}
__device__ __forceinline__ void ldsm4t(uint32_t& r0, uint32_t& r1,
                                       uint32_t& r2, uint32_t& r3, uint32_t addr) {
    asm volatile("ldmatrix.sync.aligned.m8n8.x4.trans.shared.b16 {%0,%1,%2,%3}, [%4];"
        : "=r"(r0), "=r"(r1), "=r"(r2), "=r"(r3) : "r"(addr));
}
__device__ __forceinline__ void mma16816(float* d, const uint32_t* a, const uint32_t* b) {
    asm volatile(
        "mma.sync.aligned.m16n8k16.row.col.f32.bf16.bf16.f32 "
        "{%0,%1,%2,%3}, {%4,%5,%6,%7}, {%8,%9}, {%0,%1,%2,%3};"
        : "+f"(d[0]), "+f"(d[1]), "+f"(d[2]), "+f"(d[3])
        : "r"(a[0]), "r"(a[1]), "r"(a[2]), "r"(a[3]), "r"(b[0]), "r"(b[1]));
}

// ---------------- conversion kernels ----------------------------------------
__global__ __launch_bounds__(256) void concat_convert_kernel(
    const float* __restrict__ member, const float* __restrict__ w,
    bf16* __restrict__ dh, bf16* __restrict__ dl)
{
    int idx = blockIdx.x * 256 + threadIdx.x;
    int fidx = idx * 4;
    int b   = fidx / (KL*EE);
    int rem = fidx % (KL*EE);
    int s   = rem / EE;
    int e   = rem % EE;
    float4 v;
    if (s < ML) v = *(const float4*)&member[(size_t)(b*ML + s)*EE + e];
    else        v = *(const float4*)&w[(size_t)(b*QL + (s-ML))*EE + e];
    bf16 h0,l0,h1,l1,h2,l2,h3,l3;
    split2(v.x,h0,l0); split2(v.y,h1,l1); split2(v.z,h2,l2); split2(v.w,h3,l3);
    __nv_bfloat162 hp0, hp1, lp0, lp1;
    hp0.x=h0; hp0.y=h1; hp1.x=h2; hp1.y=h3;
    lp0.x=l0; lp0.y=l1; lp1.x=l2; lp1.y=l3;
    ((__nv_bfloat162*)dh)[idx*2]   = hp0; ((__nv_bfloat162*)dh)[idx*2+1] = hp1;
    ((__nv_bfloat162*)dl)[idx*2]   = lp0; ((__nv_bfloat162*)dl)[idx*2+1] = lp1;
}

__global__ __launch_bounds__(256) void convert_split_kernel(
    const float* __restrict__ s, bf16* __restrict__ dh, bf16* __restrict__ dl)
{
    int idx = blockIdx.x * 256 + threadIdx.x;
    float4 v = ((const float4*)s)[idx];
    bf16 h0,l0,h1,l1,h2,l2,h3,l3;
    split2(v.x,h0,l0); split2(v.y,h1,l1); split2(v.z,h2,l2); split2(v.w,h3,l3);
    __nv_bfloat162 hp0, hp1, lp0, lp1;
    hp0.x=h0; hp0.y=h1; hp1.x=h2; hp1.y=h3;
    lp0.x=l0; lp0.y=l1; lp1.x=l2; lp1.y=l3;
    ((__nv_bfloat162*)dh)[idx*2]   = hp0; ((__nv_bfloat162*)dh)[idx*2+1] = hp1;
    ((__nv_bfloat162*)dl)[idx*2]   = lp0; ((__nv_bfloat162*)dl)[idx*2+1] = lp1;
}

__global__ void transpose_convert_kernel(
    const float* __restrict__ s, bf16* __restrict__ dh, bf16* __restrict__ dl,
    int K, int N)
{
    __shared__ float t[32][33];
    int n0 = blockIdx.x * 32, k0 = blockIdx.y * 32;
    int tx = threadIdx.x, ty = threadIdx.y;
    #pragma unroll
    for (int i = 0; i < 4; i++)
        t[ty + i*8][tx] = s[(size_t)(k0 + ty + i*8)*N + n0 + tx];
    __syncthreads();
    #pragma unroll
    for (int i = 0; i < 4; i++) {
        float v = t[tx][ty + i*8];
        bf16 h, l; split2(v, h, l);
        size_t o = (size_t)(n0 + ty + i*8)*K + k0 + tx;
        dh[o] = h; dl[o] = l;
    }
}

// ---------------- bf16x3 warp-MMA GEMM --------------------------------------
#define SROW     40
#define OPELEMS  (128*SROW)
#define OPBYTES  (OPELEMS*2)
#define BUFELEMS (4*OPELEMS)
#define BUFBYTES (BUFELEMS*2)
#define GSM_TOTAL (2*BUFBYTES)

template<int EPI>   // 0 = fp32 store, 1 = relu + split bf16, 2 = split bf16
__global__ __launch_bounds__(256) void mma_gemm(
    const bf16* __restrict__ Ah, const bf16* __restrict__ Al,
    const bf16* __restrict__ Bh, const bf16* __restrict__ Bl,
    float* __restrict__ Cf, bf16* __restrict__ Ch, bf16* __restrict__ Cl,
    int M, int N, int K)
{
    extern __shared__ bf16 smem[];
    const int tid = threadIdx.x, wid = tid >> 5, lane = tid & 31;
    const int row0 = blockIdx.y * 128, col0 = blockIdx.x * 128;
    const int wm = wid & 1, wn = wid >> 1;
    const uint32_t sbase0 = smem_u32(smem);

    float acc[4][4][4];
    #pragma unroll
    for (int mt = 0; mt < 4; mt++)
        #pragma unroll
        for (int nt = 0; nt < 4; nt++)
            #pragma unroll
            for (int u = 0; u < 4; u++) acc[mt][nt][u] = 0.f;

    const int nc = K >> 5;
    const int r0q = tid >> 2, c0q = (tid & 3) * 8;
    const int r1q = (tid + 256) >> 2, c1q = ((tid + 256) & 3) * 8;

    uint4 st[8];

    {
        const size_t a0 = (size_t)(row0 + r0q)*K + c0q;
        const size_t a1 = (size_t)(row0 + r1q)*K + c1q;
        const size_t b0 = (size_t)(col0 + r0q)*K + c0q;
        const size_t b1 = (size_t)(col0 + r1q)*K + c1q;
        st[0] = *(const uint4*)(Ah + a0); st[1] = *(const uint4*)(Al + a0);
        st[2] = *(const uint4*)(Bh + b0); st[3] = *(const uint4*)(Bl + b0);
        st[4] = *(const uint4*)(Ah + a1); st[5] = *(const uint4*)(Al + a1);
        st[6] = *(const uint4*)(Bh + b1); st[7] = *(const uint4*)(Bl + b1);
        bf16* bp = smem;
        const int s0 = r0q*SROW + c0q, s1 = r1q*SROW + c1q;
        *(uint4*)(bp + s0)             = st[0];
        *(uint4*)(bp + OPELEMS + s0)   = st[1];
        *(uint4*)(bp + 2*OPELEMS + s0) = st[2];
        *(uint4*)(bp + 3*OPELEMS + s0) = st[3];
        *(uint4*)(bp + s1)             = st[4];
        *(uint4*)(bp + OPELEMS + s1)   = st[5];
        *(uint4*)(bp + 2*OPELEMS + s1) = st[6];
        *(uint4*)(bp + 3*OPELEMS + s1) = st[7];
    }

    const uint32_t a_row_off = (uint32_t)(wm*64 + (lane & 15)) * 80
                             + (uint32_t)(lane >> 4) * 16;
    const uint32_t b_row_off = 2*OPBYTES
                             + (uint32_t)(wn*32 + (lane & 7) + ((lane >> 4) & 1)*8) * 80
                             + (uint32_t)((lane >> 3) & 1) * 16;

    for (int c = 0; c < nc; c++) {
        __syncthreads();
        if (c + 1 < nc) {
            const size_t k0 = (size_t)(c + 1) * 32;
            const size_t a0 = (size_t)(row0 + r0q)*K + k0 + c0q;
            const size_t a1 = (size_t)(row0 + r1q)*K + k0 + c1q;
            const size_t b0 = (size_t)(col0 + r0q)*K + k0 + c0q;
            const size_t b1 = (size_t)(col0 + r1q)*K + k0 + c1q;
            st[0] = *(const uint4*)(Ah + a0); st[1] = *(const uint4*)(Al + a0);
            st[2] = *(const uint4*)(Bh + b0); st[3] = *(const uint4*)(Bl + b0);
            st[4] = *(const uint4*)(Ah + a1); st[5] = *(const uint4*)(Al + a1);
            st[6] = *(const uint4*)(Bh + b1); st[7] = *(const uint4*)(Bl + b1);
        }

        const uint32_t sb = sbase0 + (uint32_t)(c & 1) * BUFBYTES;
        #pragma unroll
        for (int ks = 0; ks < 2; ks++) {
            uint32_t ah[4][4], al[4][4], bh[4][2], bl[4][2];
            const uint32_t abase = sb + a_row_off + ks*32;
            #pragma unroll
            for (int mt = 0; mt < 4; mt++) {
                const uint32_t ad = abase + mt*(16*80);
                ldsm4(ah[mt][0], ah[mt][1], ah[mt][2], ah[mt][3], ad);
                ldsm4(al[mt][0], al[mt][1], al[mt][2], al[mt][3], ad + OPBYTES);
            }
            const uint32_t bbase = sb + b_row_off + ks*32;
            #pragma unroll
            for (int p = 0; p < 2; p++) {
                const uint32_t bd = bbase + p*(16*80);
                ldsm4(bh[2*p][0], bh[2*p][1], bh[2*p+1][0], bh[2*p+1][1], bd);
                ldsm4(bl[2*p][0], bl[2*p][1], bl[2*p+1][0], bl[2*p+1][1], bd + OPBYTES);
            }
            #pragma unroll
            for (int mt = 0; mt < 4; mt++)
                #pragma unroll
                for (int nt = 0; nt < 4; nt++) {
                    mma16816(acc[mt][nt], ah[mt], bh[nt]);
                    mma16816(acc[mt][nt], ah[mt], bl[nt]);
                    mma16816(acc[mt][nt], al[mt], bh[nt]);
                }
        }

        if (c + 1 < nc) {
            bf16* bp = smem + ((c + 1) & 1) * BUFELEMS;
            const int s0 = r0q*SROW + c0q, s1 = r1q*SROW + c1q;
            *(uint4*)(bp + s0)             = st[0];
            *(uint4*)(bp + OPELEMS + s0)   = st[1];
            *(uint4*)(bp + 2*OPELEMS + s0) = st[2];
            *(uint4*)(bp + 3*OPELEMS + s0) = st[3];
            *(uint4*)(bp + s1)             = st[4];
            *(uint4*)(bp + OPELEMS + s1)   = st[5];
            *(uint4*)(bp + 2*OPELEMS + s1) = st[6];
            *(uint4*)(bp + 3*OPELEMS + s1) = st[7];
        }
    }

    const int er = lane >> 2, ec = (lane & 3) * 2;
    #pragma unroll
    for (int mt = 0; mt < 4; mt++) {
        #pragma unroll
        for (int nt = 0; nt < 4; nt++) {
            const int grow = row0 + wm*64 + mt*16 + er;
            const int gcol = col0 + wn*32 + nt*8 + ec;
            if (EPI == 0) {
                *(float2*)&Cf[(size_t)grow*N + gcol] =
                    make_float2(acc[mt][nt][0], acc[mt][nt][1]);
                *(float2*)&Cf[(size_t)(grow+8)*N + gcol] =
                    make_float2(acc[mt][nt][2], acc[mt][nt][3]);
            } else {
                float f0 = acc[mt][nt][0], f1 = acc[mt][nt][1];
                float f2 = acc[mt][nt][2], f3 = acc[mt][nt][3];
                if (EPI == 1) {
                    f0 = fmaxf(f0, 0.f); f1 = fmaxf(f1, 0.f);
                    f2 = fmaxf(f2, 0.f); f3 = fmaxf(f3, 0.f);
                }
                bf16 h0,l0,h1,l1,h2,l2,h3,l3;
                split2(f0,h0,l0); split2(f1,h1,l1);
                split2(f2,h2,l2); split2(f3,h3,l3);
                __nv_bfloat162 hp0, lp0, hp1, lp1;
                hp0.x=h0; hp0.y=h1; lp0.x=l0; lp0.y=l1;
                hp1.x=h2; hp1.y=h3; lp1.x=l2; lp1.y=l3;
                *(__nv_bfloat162*)&Ch[(size_t)grow*N + gcol]     = hp0;
                *(__nv_bfloat162*)&Cl[(size_t)grow*N + gcol]     = lp0;
                *(__nv_bfloat162*)&Ch[(size_t)(grow+8)*N + gcol] = hp1;
                *(__nv_bfloat162*)&Cl[(size_t)(grow+8)*N + gcol] = lp1;
            }
        }
    }
}

// ---------------- MMA flash attention with fused rel-shift -------------------
// CTA = 128 threads (4 warps), i-tile 64 rows of one (b,h). j-tiles of 64 keys.
// Warp w owns rows w*16..w*16+15 of the tile for S/BDW/P/O.
#define ASTR 144                 // bytes per smem row (72 bf16)
#define A_QWH 0
#define A_QWL 9216
#define A_QRH 18432
#define A_QRL 27648
#define A_KH  36864
#define A_KL  46080
#define A_VH  55296
#define A_VL  64512
#define A_RH  73728
#define A_RL  92160
#define A_SCR 110592             // 4 warp blocks of 8448 B (BDW fp32 / P hi+lo)
#define A_TOT 144384

__global__ __launch_bounds__(128) void attn_mma_kernel(
    const bf16* __restrict__ Qh, const bf16* __restrict__ Ql,
    const bf16* __restrict__ Kh, const bf16* __restrict__ Kl,
    const bf16* __restrict__ Vh, const bf16* __restrict__ Vl,
    const bf16* __restrict__ Rh, const bf16* __restrict__ Rl,
    const float* __restrict__ rwb, const float* __restrict__ rrb,
    bf16* __restrict__ OHp, bf16* __restrict__ OLp)
{
    extern __shared__ char sm[];
    const uint32_t sb = smem_u32(sm);
    const int i0 = blockIdx.x * 64;
    const int h  = blockIdx.y, b = blockIdx.z;
    const int tid = threadIdx.x, w = tid >> 5, lane = tid & 31;

    // ---- load Q, add biases, split, store both variants ----
    #pragma unroll
    for (int it = 0; it < 4; it++) {
        int idx = tid + it*128;
        int row = idx >> 3, c8 = (idx & 7) * 8;
        const size_t g = (size_t)(b*QL + i0 + row)*EE + h*DH + c8;
        union { uint4 u; bf16 e[8]; } uh, ul;
        uh.u = *(const uint4*)(Qh + g);
        ul.u = *(const uint4*)(Ql + g);
        bf16* qwh = (bf16*)(sm + A_QWH + row*ASTR) + c8;
        bf16* qwl = (bf16*)(sm + A_QWL + row*ASTR) + c8;
        bf16* qrh = (bf16*)(sm + A_QRH + row*ASTR) + c8;
        bf16* qrl = (bf16*)(sm + A_QRL + row*ASTR) + c8;
        #pragma unroll
        for (int e = 0; e < 8; e++) {
            float q = __bfloat162float(uh.e[e]) + __bfloat162float(ul.e[e]);
            bf16 hh, ll;
            split2(q + rwb[h*DH + c8 + e], hh, ll); qwh[e] = hh; qwl[e] = ll;
            split2(q + rrb[h*DH + c8 + e], hh, ll); qrh[e] = hh; qrl[e] = ll;
        }
    }

    float O[8][4];
    #pragma unroll
    for (int nt = 0; nt < 8; nt++)
        #pragma unroll
        for (int u = 0; u < 4; u++) O[nt][u] = 0.f;
    float m_i[2] = {-INFINITY, -INFINITY}, l_i[2] = {0.f, 0.f};

    const uint32_t aoff = (uint32_t)(w*16 + (lane&15))*ASTR + ((lane>>4)&1)*16;
    const uint32_t boff = (uint32_t)((lane&7) + ((lane>>4)&1)*8)*ASTR + ((lane>>3)&1)*16;
    const uint32_t voff = (uint32_t)((lane&7) + ((lane>>3)&1)*8)*ASTR + ((lane>>4)&1)*16;
    const uint32_t poff = (uint32_t)(lane&15)*ASTR + ((lane>>4)&1)*16;
    const uint32_t wscr = A_SCR + w*8448;
    const int er = lane >> 2, ec = (lane & 3) * 2;
    const int lr0 = w*16 + er, lr1 = lr0 + 8;
    const int ig0 = i0 + lr0, ig1 = i0 + lr1;

    int njt = (i0 + 63 + ML)/64 + 1;
    if (njt > KL/64) njt = KL/64;

    for (int jt = 0; jt < njt; jt++) {
        const int j0 = jt * 64;
        __syncthreads();
        // ---- cooperative K/V/R loads ----
        #pragma unroll
        for (int it = 0; it < 4; it++) {
            int idx = tid + it*128;
            int row = idx >> 3, c8 = (idx & 7) * 8;
            const size_t g = (size_t)(b*KL + j0 + row)*EE + h*DH + c8;
            *(uint4*)(sm + A_KH + row*ASTR + c8*2) = *(const uint4*)(Kh + g);
            *(uint4*)(sm + A_KL + row*ASTR + c8*2) = *(const uint4*)(Kl + g);
            *(uint4*)(sm + A_VH + row*ASTR + c8*2) = *(const uint4*)(Vh + g);
            *(uint4*)(sm + A_VL + row*ASTR + c8*2) = *(const uint4*)(Vl + g);
        }
        const int rbase = j0 - i0 + QL - 64;
        #pragma unroll
        for (int it = 0; it < 8; it++) {
            int idx = tid + it*128;
            int row = idx >> 3, c8 = (idx & 7) * 8;
            int dg = rbase + row;
            uint4 hv = make_uint4(0,0,0,0), lv = make_uint4(0,0,0,0);
            if (dg < KL) {
                const size_t g = (size_t)dg*EE + h*DH + c8;
                hv = *(const uint4*)(Rh + g);
                lv = *(const uint4*)(Rl + g);
            }
            *(uint4*)(sm + A_RH + row*ASTR + c8*2) = hv;
            *(uint4*)(sm + A_RL + row*ASTR + c8*2) = lv;
        }
        __syncthreads();

        // ---- BDW = Qr @ Rwindow^T (two 64-col halves) -> warp scratch ----
        #pragma unroll
        for (int half = 0; half < 2; half++) {
            float D[8][4];
            #pragma unroll
            for (int nt = 0; nt < 8; nt++)
                #pragma unroll
                for (int u = 0; u < 4; u++) D[nt][u] = 0.f;
            #pragma unroll
            for (int ks = 0; ks < 4; ks++) {
                uint32_t arh[4], arl[4];
                ldsm4(arh[0], arh[1], arh[2], arh[3], sb + A_QRH + aoff + ks*32);
                ldsm4(arl[0], arl[1], arl[2], arl[3], sb + A_QRL + aoff + ks*32);
                #pragma unroll
                for (int p = 0; p < 4; p++) {
                    uint32_t bh4[4], bl4[4];
                    const uint32_t ra = sb + boff + (uint32_t)(half*64 + p*16)*ASTR + ks*32;
                    ldsm4(bh4[0], bh4[1], bh4[2], bh4[3], ra + A_RH);
                    ldsm4(bl4[0], bl4[1], bl4[2], bl4[3], ra + A_RL);
                    mma16816(D[2*p],   arh, bh4);   mma16816(D[2*p],   arh, bl4);
                    mma16816(D[2*p],   arl, bh4);
                    mma16816(D[2*p+1], arh, bh4+2); mma16816(D[2*p+1], arh, bl4+2);
                    mma16816(D[2*p+1], arl, bh4+2);
                }
            }
            float* bdw = (float*)(sm + wscr);
            #pragma unroll
            for (int nt = 0; nt < 8; nt++) {
                const int c = half*64 + nt*8 + ec;
                bdw[er*132 + c]       = D[nt][0];
                bdw[er*132 + c + 1]   = D[nt][1];
                bdw[(er+8)*132 + c]   = D[nt][2];
                bdw[(er+8)*132 + c+1] = D[nt][3];
            }
        }

        // ---- AC = Qw @ K^T ----
        float S[8][4];
        #pragma unroll
        for (int nt = 0; nt < 8; nt++)
            #pragma unroll
            for (int u = 0; u < 4; u++) S[nt][u] = 0.f;
        #pragma unroll
        for (int ks = 0; ks < 4; ks++) {
            uint32_t awh[4], awl[4];
            ldsm4(awh[0], awh[1], awh[2], awh[3], sb + A_QWH + aoff + ks*32);
            ldsm4(awl[0], awl[1], awl[2], awl[3], sb + A_QWL + aoff + ks*32);
            #pragma unroll
            for (int p = 0; p < 4; p++) {
                uint32_t bh4[4], bl4[4];
                const uint32_t ka = sb + boff + (uint32_t)(p*16)*ASTR + ks*32;
                ldsm4(bh4[0], bh4[1], bh4[2], bh4[3], ka + A_KH);
                ldsm4(bl4[0], bl4[1], bl4[2], bl4[3], ka + A_KL);
                mma16816(S[2*p],   awh, bh4);   mma16816(S[2*p],   awh, bl4);
                mma16816(S[2*p],   awl, bh4);
                mma16816(S[2*p+1], awh, bh4+2); mma16816(S[2*p+1], awh, bl4+2);
                mma16816(S[2*p+1], awl, bh4+2);
            }
        }
        __syncwarp();

        // ---- gather BD diagonal, mask+scale, online softmax ----
        const float* bdw = (const float*)(sm + wscr);
        float mx0 = -INFINITY, mx1 = -INFINITY;
        #pragma unroll
        for (int nt = 0; nt < 8; nt++) {
            const int c = nt*8 + ec;
            float s00 = S[nt][0] + bdw[er*132     + (c   - lr0 + 63)];
            float s01 = S[nt][1] + bdw[er*132     + (c+1 - lr0 + 63)];
            float s10 = S[nt][2] + bdw[(er+8)*132 + (c   - lr1 + 63)];
            float s11 = S[nt][3] + bdw[(er+8)*132 + (c+1 - lr1 + 63)];
            const int jg = j0 + c;
            s00 = (jg   > ig0 + ML) ? -1e30f : s00 * 0.03125f;
            s01 = (jg+1 > ig0 + ML) ? -1e30f : s01 * 0.03125f;
            s10 = (jg   > ig1 + ML) ? -1e30f : s10 * 0.03125f;
            s11 = (jg+1 > ig1 + ML) ? -1e30f : s11 * 0.03125f;
            S[nt][0] = s00; S[nt][1] = s01; S[nt][2] = s10; S[nt][3] = s11;
            mx0 = fmaxf(mx0, fmaxf(s00, s01));
            mx1 = fmaxf(mx1, fmaxf(s10, s11));
        }
        mx0 = fmaxf(mx0, __shfl_xor_sync(0xffffffffu, mx0, 1));
        mx0 = fmaxf(mx0, __shfl_xor_sync(0xffffffffu, mx0, 2));
        mx1 = fmaxf(mx1, __shfl_xor_sync(0xffffffffu, mx1, 1));
        mx1 = fmaxf(mx1, __shfl_xor_sync(0xffffffffu, mx1, 2));
        const float mn0 = fmaxf(m_i[0], mx0), mn1 = fmaxf(m_i[1], mx1);
        const float sf0 = __expf(m_i[0] - mn0), sf1 = __expf(m_i[1] - mn1);
        m_i[0] = mn0; m_i[1] = mn1;

        __syncwarp();   // gathers done before P overwrites scratch
        bf16* pph = (bf16*)(sm + wscr);
        bf16* ppl = (bf16*)(sm + wscr + 2304);
        float ps0 = 0.f, ps1 = 0.f;
        #pragma unroll
        for (int nt = 0; nt < 8; nt++) {
            const int c = nt*8 + ec;
            float p00 = __expf(S[nt][0] - mn0);
            float p01 = __expf(S[nt][1] - mn0);
            float p10 = __expf(S[nt][2] - mn1);
            float p11 = __expf(S[nt][3] - mn1);
            ps0 += p00 + p01; ps1 += p10 + p11;
            bf16 h0,l0,h1,l1;
            __nv_bfloat162 hp, lp;
            split2(p00,h0,l0); split2(p01,h1,l1);
            hp.x=h0; hp.y=h1; lp.x=l0; lp.y=l1;
            *(__nv_bfloat162*)(pph + er*72 + c) = hp;
            *(__nv_bfloat162*)(ppl + er*72 + c) = lp;
            split2(p10,h0,l0); split2(p11,h1,l1);
            hp.x=h0; hp.y=h1; lp.x=l0; lp.y=l1;
            *(__nv_bfloat162*)(pph + (er+8)*72 + c) = hp;
            *(__nv_bfloat162*)(ppl + (er+8)*72 + c) = lp;
        }
        ps0 += __shfl_xor_sync(0xffffffffu, ps0, 1);
        ps0 += __shfl_xor_sync(0xffffffffu, ps0, 2);
        ps1 += __shfl_xor_sync(0xffffffffu, ps1, 1);
        ps1 += __shfl_xor_sync(0xffffffffu, ps1, 2);
        l_i[0] = l_i[0]*sf0 + ps0;
        l_i[1] = l_i[1]*sf1 + ps1;
        #pragma unroll
        for (int nt = 0; nt < 8; nt++) {
            O[nt][0] *= sf0; O[nt][1] *= sf0;
            O[nt][2] *= sf1; O[nt][3] *= sf1;
        }
        __syncwarp();

        // ---- O += P @ V (V^T frags via ldmatrix.trans) ----
        #pragma unroll
        for (int ks = 0; ks < 4; ks++) {
            uint32_t ph4[4], pl4[4];
            ldsm4(ph4[0], ph4[1], ph4[2], ph4[3], sb + wscr + poff + ks*32);
            ldsm4(pl4[0], pl4[1], pl4[2], pl4[3], sb + wscr + 2304 + poff + ks*32);
            #pragma unroll
            for (int p = 0; p < 4; p++) {
                uint32_t vh4[4], vl4[4];
                const uint32_t va = sb + voff + (uint32_t)(ks*16)*ASTR + p*32;
                ldsm4t(vh4[0], vh4[1], vh4[2], vh4[3], va + A_VH);
                ldsm4t(vl4[0], vl4[1], vl4[2], vl4[3], va + A_VL);
                mma16816(O[2*p],   ph4, vh4);   mma16816(O[2*p],   ph4, vl4);
                mma16816(O[2*p],   pl4, vh4);
                mma16816(O[2*p+1], ph4, vh4+2); mma16816(O[2*p+1], ph4, vl4+2);
                mma16816(O[2*p+1], pl4, vh4+2);
            }
        }
    }

    // ---- epilogue: normalize + split store ----
    const float inv0 = 1.0f / l_i[0], inv1 = 1.0f / l_i[1];
    #pragma unroll
    for (int nt = 0; nt < 8; nt++) {
        const int c = nt*8 + ec;
        const size_t g0 = (size_t)(b*QL + ig0)*EE + h*DH + c;
        const size_t g1 = (size_t)(b*QL + ig1)*EE + h*DH + c;
        bf16 h0,l0,h1,l1;
        __nv_bfloat162 hp, lp;
        split2(O[nt][0]*inv0, h0, l0); split2(O[nt][1]*inv0, h1, l1);
        hp.x=h0; hp.y=h1; lp.x=l0; lp.y=l1;
        *(__nv_bfloat162*)(OHp + g0) = hp;
        *(__nv_bfloat162*)(OLp + g0) = lp;
        split2(O[nt][2]*inv1, h0, l0); split2(O[nt][3]*inv1, h1, l1);
        hp.x=h0; hp.y=h1; lp.x=l0; lp.y=l1;
        *(__nv_bfloat162*)(OHp + g1) = hp;
        *(__nv_bfloat162*)(OLp + g1) = lp;
    }
}

// ---------------- residual add + LayerNorm ----------------------------------
template<int WB>
__global__ __launch_bounds__(256) void add_ln_kernel(
    const float* __restrict__ a, const float* __restrict__ res,
    const float* __restrict__ g, const float* __restrict__ bt,
    float* __restrict__ out, bf16* __restrict__ oh, bf16* __restrict__ ol)
{
    __shared__ float red[256];
    const int row = blockIdx.x;
    const int tid = threadIdx.x;
    const size_t base = (size_t)row * EE;

    float v[4];
    #pragma unroll
    for (int u = 0; u < 4; u++)
        v[u] = a[base + u*256 + tid] + res[base + u*256 + tid];

    float s = v[0] + v[1] + v[2] + v[3];
    red[tid] = s; __syncthreads();
    for (int off = 128; off > 0; off >>= 1) {
        if (tid < off) red[tid] += red[tid + off];
        __syncthreads();
    }
    const float mu = red[0] * (1.0f / EE);
    __syncthreads();

    float d = 0.f;
    #pragma unroll
    for (int u = 0; u < 4; u++) { float t = v[u] - mu; d += t*t; }
    red[tid] = d; __syncthreads();
    for (int off = 128; off > 0; off >>= 1) {
        if (tid < off) red[tid] += red[tid + off];
        __syncthreads();
    }
    const float rs = rsqrtf(red[0] * (1.0f / EE) + 1e-3f);

    #pragma unroll
    for (int u = 0; u < 4; u++) {
        int c = u*256 + tid;
        float o = (v[u] - mu) * rs * g[c] + bt[c];
        out[base + c] = o;
        if (WB) {
            bf16 hh_, ll_; split2(o, hh_, ll_);
            oh[base + c] = hh_; ol[base + c] = ll_;
        }
    }
}

// ---------------- launch ----------------------------------------------------
extern "C" void kernel_launch(void* const* d_in, const int* in_sizes, int n_in,
                              void* d_out, int out_size)
{
    const float* w      = (const float*)d_in[0];
    const float* r      = (const float*)d_in[1];
    const float* member = (const float*)d_in[2];
    const float* Wq     = (const float*)d_in[4];
    const float* Wk     = (const float*)d_in[5];
    const float* Wv     = (const float*)d_in[6];
    const float* Wr     = (const float*)d_in[7];
    const float* Wo     = (const float*)d_in[8];
    const float* rwb    = (const float*)d_in[9];
    const float* rrb    = (const float*)d_in[10];
    const float* ln1g   = (const float*)d_in[11];
    const float* ln1b   = (const float*)d_in[12];
    const float* W1     = (const float*)d_in[13];
    const float* W2     = (const float*)d_in[14];
    const float* ln2g   = (const float*)d_in[15];
    const float* ln2b   = (const float*)d_in[16];
    float* out = (float*)d_out;

    float *ao,*x,*y;
    cudaGetSymbolAddress((void**)&ao, g_ao);
    cudaGetSymbolAddress((void**)&x,  g_x);
    cudaGetSymbolAddress((void**)&y,  g_y);
    bf16 *cath,*catl,*wh,*wl,*rih,*ril,*atth,*attl,*xh,*xl,*hhh,*hhl;
    bf16 *qph,*qpl,*kph,*kpl,*vph,*vpl,*rph,*rpl;
    bf16 *wqh,*wql,*wkh,*wkl,*wvh,*wvl,*wrh,*wrl,*woh,*wol,*w1h,*w1l,*w2h,*w2l;
    cudaGetSymbolAddress((void**)&cath, g_cat_h); cudaGetSymbolAddress((void**)&catl, g_cat_l);
    cudaGetSymbolAddress((void**)&wh,   g_w_h);   cudaGetSymbolAddress((void**)&wl,   g_w_l);
    cudaGetSymbolAddress((void**)&rih,  g_r_h);   cudaGetSymbolAddress((void**)&ril,  g_r_l);
    cudaGetSymbolAddress((void**)&qph,  g_q_h);   cudaGetSymbolAddress((void**)&qpl,  g_q_l);
    cudaGetSymbolAddress((void**)&kph,  g_k_h);   cudaGetSymbolAddress((void**)&kpl,  g_k_l);
    cudaGetSymbolAddress((void**)&vph,  g_v_h);   cudaGetSymbolAddress((void**)&vpl,  g_v_l);
    cudaGetSymbolAddress((void**)&rph,  g_rpj_h); cudaGetSymbolAddress((void**)&rpl,  g_rpj_l);
    cudaGetSymbolAddress((void**)&atth, g_att_h); cudaGetSymbolAddress((void**)&attl, g_att_l);
    cudaGetSymbolAddress((void**)&xh,   g_x_h);   cudaGetSymbolAddress((void**)&xl,   g_x_l);
    cudaGetSymbolAddress((void**)&hhh,  g_hh_h);  cudaGetSymbolAddress((void**)&hhl,  g_hh_l);
    cudaGetSymbolAddress((void**)&wqh,  g_Wq_h);  cudaGetSymbolAddress((void**)&wql,  g_Wq_l);
    cudaGetSymbolAddress((void**)&wkh,  g_Wk_h);  cudaGetSymbolAddress((void**)&wkl,  g_Wk_l);
    cudaGetSymbolAddress((void**)&wvh,  g_Wv_h);  cudaGetSymbolAddress((void**)&wvl,  g_Wv_l);
    cudaGetSymbolAddress((void**)&wrh,  g_Wr_h);  cudaGetSymbolAddress((void**)&wrl,  g_Wr_l);
    cudaGetSymbolAddress((void**)&woh,  g_Wo_h);  cudaGetSymbolAddress((void**)&wol,  g_Wo_l);
    cudaGetSymbolAddress((void**)&w1h,  g_W1_h);  cudaGetSymbolAddress((void**)&w1l,  g_W1_l);
    cudaGetSymbolAddress((void**)&w2h,  g_W2_h);  cudaGetSymbolAddress((void**)&w2l,  g_W2_l);

    cudaFuncSetAttribute(mma_gemm<0>, cudaFuncAttributeMaxDynamicSharedMemorySize, GSM_TOTAL);
    cudaFuncSetAttribute(mma_gemm<1>, cudaFuncAttributeMaxDynamicSharedMemorySize, GSM_TOTAL);
    cudaFuncSetAttribute(mma_gemm<2>, cudaFuncAttributeMaxDynamicSharedMemorySize, GSM_TOTAL);
    cudaFuncSetAttribute(attn_mma_kernel, cudaFuncAttributeMaxDynamicSharedMemorySize, A_TOT);

    // input conversions
    concat_convert_kernel<<<BB*KL*EE/4/256, 256>>>(member, w, cath, catl);
    convert_split_kernel <<<BB*QL*EE/4/256, 256>>>(w, wh, wl);
    convert_split_kernel <<<KL*EE/4/256,    256>>>(r, rih, ril);
    transpose_convert_kernel<<<dim3(EE/32, EE/32), dim3(32,8)>>>(Wq, wqh, wql, EE, EE);
    transpose_convert_kernel<<<dim3(EE/32, EE/32), dim3(32,8)>>>(Wk, wkh, wkl, EE, EE);
    transpose_convert_kernel<<<dim3(EE/32, EE/32), dim3(32,8)>>>(Wv, wvh, wvl, EE, EE);
    transpose_convert_kernel<<<dim3(EE/32, EE/32), dim3(32,8)>>>(Wr, wrh, wrl, EE, EE);
    transpose_convert_kernel<<<dim3(EE/32, EE/32), dim3(32,8)>>>(Wo, woh, wol, EE, EE);
    transpose_convert_kernel<<<dim3(FF/32, EE/32), dim3(32,8)>>>(W1, w1h, w1l, EE, FF);
    transpose_convert_kernel<<<dim3(EE/32, FF/32), dim3(32,8)>>>(W2, w2h, w2l, FF, EE);

    // projections (split bf16 outputs)
    mma_gemm<2><<<dim3(EE/128, (BB*KL)/128), 256, GSM_TOTAL>>>(
        cath, catl, wkh, wkl, nullptr, kph, kpl, BB*KL, EE, EE);
    mma_gemm<2><<<dim3(EE/128, (BB*KL)/128), 256, GSM_TOTAL>>>(
        cath, catl, wvh, wvl, nullptr, vph, vpl, BB*KL, EE, EE);
    mma_gemm<2><<<dim3(EE/128, (BB*QL)/128), 256, GSM_TOTAL>>>(
        wh, wl, wqh, wql, nullptr, qph, qpl, BB*QL, EE, EE);
    mma_gemm<2><<<dim3(EE/128, KL/128), 256, GSM_TOTAL>>>(
        rih, ril, wrh, wrl, nullptr, rph, rpl, KL, EE, EE);

    // fused MMA attention
    attn_mma_kernel<<<dim3(QL/64, HH, BB), 128, A_TOT>>>(
        qph, qpl, kph, kpl, vph, vpl, rph, rpl, rwb, rrb, atth, attl);

    // output projection + LN1
    mma_gemm<0><<<dim3(EE/128, (BB*QL)/128), 256, GSM_TOTAL>>>(
        atth, attl, woh, wol, ao, nullptr, nullptr, BB*QL, EE, EE);
    add_ln_kernel<1><<<BB*QL, 256>>>(ao, w, ln1g, ln1b, x, xh, xl);

    // FFN + LN2
    mma_gemm<1><<<dim3(FF/128, (BB*QL)/128), 256, GSM_TOTAL>>>(
        xh, xl, w1h, w1l, nullptr, hhh, hhl, BB*QL, FF, EE);
    mma_gemm<0><<<dim3(EE/128, (BB*QL)/128), 256, GSM_TOTAL>>>(
        hhh, hhl, w2h, w2l, y, nullptr, nullptr, BB*QL, EE, FF);
    add_ln_kernel<0><<<BB*QL, 256>>>(y, x, ln2g, ln2b, out, nullptr, nullptr);
}

// round 6
// speedup vs baseline: 5.0747x; 1.1398x over previous
#include <cuda_runtime.h>
#include <cuda_bf16.h>
#include <math.h>
#include <stdint.h>

#define BB 2
#define QL 1024
#define ML 1024
#define KL 2048
#define EE 1024
#define HH 16
#define DH 64
#define FF 4096

typedef __nv_bfloat16 bf16;

// ---------------- scratch (static device globals) ---------------------------
__device__ float g_ao [BB*QL*EE];
__device__ float g_x  [BB*QL*EE];
__device__ float g_y  [BB*QL*EE];

__device__ bf16 g_cat_h[BB*KL*EE], g_cat_l[BB*KL*EE];
__device__ bf16 g_w_h  [BB*QL*EE], g_w_l  [BB*QL*EE];
__device__ bf16 g_r_h  [KL*EE],    g_r_l  [KL*EE];
__device__ bf16 g_q_h  [BB*QL*EE], g_q_l  [BB*QL*EE];
__device__ bf16 g_k_h  [BB*KL*EE], g_k_l  [BB*KL*EE];
__device__ bf16 g_v_h  [BB*KL*EE], g_v_l  [BB*KL*EE];
__device__ bf16 g_rpj_h[KL*EE],    g_rpj_l[KL*EE];
__device__ bf16 g_att_h[BB*QL*EE], g_att_l[BB*QL*EE];
__device__ bf16 g_x_h  [BB*QL*EE], g_x_l  [BB*QL*EE];
__device__ bf16 g_hh_h [BB*QL*FF], g_hh_l [BB*QL*FF];
__device__ bf16 g_Wq_h[EE*EE], g_Wq_l[EE*EE];
__device__ bf16 g_Wk_h[EE*EE], g_Wk_l[EE*EE];
__device__ bf16 g_Wv_h[EE*EE], g_Wv_l[EE*EE];
__device__ bf16 g_Wr_h[EE*EE], g_Wr_l[EE*EE];
__device__ bf16 g_Wo_h[EE*EE], g_Wo_l[EE*EE];
__device__ bf16 g_W1_h[FF*EE], g_W1_l[FF*EE];
__device__ bf16 g_W2_h[EE*FF], g_W2_l[EE*FF];

// ---------------- helpers ----------------------------------------------------
__device__ __forceinline__ uint32_t smem_u32(const void* p) {
    uint32_t a;
    asm("{ .reg .u64 t; cvta.to.shared.u64 t, %1; cvt.u32.u64 %0, t; }"
        : "=r"(a) : "l"(p));
    return a;
}
__device__ __forceinline__ void split2(float v, bf16& h, bf16& l) {
    h = __float2bfloat16(v);
    l = __float2bfloat16(v - __bfloat162float(h));
}
__device__ __forceinline__ void ldsm4(uint32_t& r0, uint32_t& r1,
                                      uint32_t& r2, uint32_t& r3, uint32_t addr) {
    asm volatile("ldmatrix.sync.aligned.m8n8.x4.shared.b16 {%0,%1,%2,%3}, [%4];"
        : "=r"(r0), "=r"(r1), "=r"(r2), "=r"(r3) : "r"(addr));
}
__device__ __forceinline__ void ldsm4t(uint32_t& r0, uint32_t& r1,
                                       uint32_t& r2, uint32_t& r3, uint32_t addr) {
    asm volatile("ldmatrix.sync.aligned.m8n8.x4.trans.shared.b16 {%0,%1,%2,%3}, [%4];"
        : "=r"(r0), "=r"(r1), "=r"(r2), "=r"(r3) : "r"(addr));
}
__device__ __forceinline__ void mma16816(float* d, const uint32_t* a, const uint32_t* b) {
    asm volatile(
        "mma.sync.aligned.m16n8k16.row.col.f32.bf16.bf16.f32 "
        "{%0,%1,%2,%3}, {%4,%5,%6,%7}, {%8,%9}, {%0,%1,%2,%3};"
        : "+f"(d[0]), "+f"(d[1]), "+f"(d[2]), "+f"(d[3])
        : "r"(a[0]), "r"(a[1]), "r"(a[2]), "r"(a[3]), "r"(b[0]), "r"(b[1]));
}
__device__ __forceinline__ void cpa16(uint32_t d, const void* s) {
    asm volatile("cp.async.cg.shared.global [%0], [%1], 16;" :: "r"(d), "l"(s));
}
__device__ __forceinline__ void cpa16z(uint32_t d, const void* s, int sz) {
    asm volatile("cp.async.cg.shared.global [%0], [%1], 16, %2;"
                 :: "r"(d), "l"(s), "r"(sz));
}
#define CPA_COMMIT() asm volatile("cp.async.commit_group;")
template<int N> __device__ __forceinline__ void cpa_wait() {
    asm volatile("cp.async.wait_group %0;" :: "n"(N));
}

// ---------------- conversion kernels ----------------------------------------
__global__ __launch_bounds__(256) void concat_convert_kernel(
    const float* __restrict__ member, const float* __restrict__ w,
    bf16* __restrict__ dh, bf16* __restrict__ dl)
{
    int idx = blockIdx.x * 256 + threadIdx.x;
    int fidx = idx * 4;
    int b   = fidx / (KL*EE);
    int rem = fidx % (KL*EE);
    int s   = rem / EE;
    int e   = rem % EE;
    float4 v;
    if (s < ML) v = *(const float4*)&member[(size_t)(b*ML + s)*EE + e];
    else        v = *(const float4*)&w[(size_t)(b*QL + (s-ML))*EE + e];
    bf16 h0,l0,h1,l1,h2,l2,h3,l3;
    split2(v.x,h0,l0); split2(v.y,h1,l1); split2(v.z,h2,l2); split2(v.w,h3,l3);
    __nv_bfloat162 hp0, hp1, lp0, lp1;
    hp0.x=h0; hp0.y=h1; hp1.x=h2; hp1.y=h3;
    lp0.x=l0; lp0.y=l1; lp1.x=l2; lp1.y=l3;
    ((__nv_bfloat162*)dh)[idx*2]   = hp0; ((__nv_bfloat162*)dh)[idx*2+1] = hp1;
    ((__nv_bfloat162*)dl)[idx*2]   = lp0; ((__nv_bfloat162*)dl)[idx*2+1] = lp1;
}

__global__ __launch_bounds__(256) void convert_split_kernel(
    const float* __restrict__ s, bf16* __restrict__ dh, bf16* __restrict__ dl)
{
    int idx = blockIdx.x * 256 + threadIdx.x;
    float4 v = ((const float4*)s)[idx];
    bf16 h0,l0,h1,l1,h2,l2,h3,l3;
    split2(v.x,h0,l0); split2(v.y,h1,l1); split2(v.z,h2,l2); split2(v.w,h3,l3);
    __nv_bfloat162 hp0, hp1, lp0, lp1;
    hp0.x=h0; hp0.y=h1; hp1.x=h2; hp1.y=h3;
    lp0.x=l0; lp0.y=l1; lp1.x=l2; lp1.y=l3;
    ((__nv_bfloat162*)dh)[idx*2]   = hp0; ((__nv_bfloat162*)dh)[idx*2+1] = hp1;
    ((__nv_bfloat162*)dl)[idx*2]   = lp0; ((__nv_bfloat162*)dl)[idx*2+1] = lp1;
}

struct TC5 { const float* s[5]; bf16* dh[5]; bf16* dl[5]; };

__global__ void transpose_convert5_kernel(TC5 p)   // 5x square EExEE
{
    __shared__ float t[32][33];
    const float* s = p.s[blockIdx.z];
    bf16* dh = p.dh[blockIdx.z];
    bf16* dl = p.dl[blockIdx.z];
    int n0 = blockIdx.x * 32, k0 = blockIdx.y * 32;
    int tx = threadIdx.x, ty = threadIdx.y;
    #pragma unroll
    for (int i = 0; i < 4; i++)
        t[ty + i*8][tx] = s[(size_t)(k0 + ty + i*8)*EE + n0 + tx];
    __syncthreads();
    #pragma unroll
    for (int i = 0; i < 4; i++) {
        float v = t[tx][ty + i*8];
        bf16 h, l; split2(v, h, l);
        size_t o = (size_t)(n0 + ty + i*8)*EE + k0 + tx;
        dh[o] = h; dl[o] = l;
    }
}

__global__ void transpose_convert_kernel(
    const float* __restrict__ s, bf16* __restrict__ dh, bf16* __restrict__ dl,
    int K, int N)
{
    __shared__ float t[32][33];
    int n0 = blockIdx.x * 32, k0 = blockIdx.y * 32;
    int tx = threadIdx.x, ty = threadIdx.y;
    #pragma unroll
    for (int i = 0; i < 4; i++)
        t[ty + i*8][tx] = s[(size_t)(k0 + ty + i*8)*N + n0 + tx];
    __syncthreads();
    #pragma unroll
    for (int i = 0; i < 4; i++) {
        float v = t[tx][ty + i*8];
        bf16 h, l; split2(v, h, l);
        size_t o = (size_t)(n0 + ty + i*8)*K + k0 + tx;
        dh[o] = h; dl[o] = l;
    }
}

// ---------------- bf16x3 warp-MMA GEMM (unchanged from R4) -------------------
#define SROW     40
#define OPELEMS  (128*SROW)
#define OPBYTES  (OPELEMS*2)
#define BUFELEMS (4*OPELEMS)
#define BUFBYTES (BUFELEMS*2)
#define GSM_TOTAL (2*BUFBYTES)

template<int EPI>   // 0 = fp32 store, 1 = relu + split bf16, 2 = split bf16
__global__ __launch_bounds__(256) void mma_gemm(
    const bf16* __restrict__ Ah, const bf16* __restrict__ Al,
    const bf16* __restrict__ Bh, const bf16* __restrict__ Bl,
    float* __restrict__ Cf, bf16* __restrict__ Ch, bf16* __restrict__ Cl,
    int M, int N, int K)
{
    extern __shared__ bf16 smem[];
    const int tid = threadIdx.x, wid = tid >> 5, lane = tid & 31;
    const int row0 = blockIdx.y * 128, col0 = blockIdx.x * 128;
    const int wm = wid & 1, wn = wid >> 1;
    const uint32_t sbase0 = smem_u32(smem);

    float acc[4][4][4];
    #pragma unroll
    for (int mt = 0; mt < 4; mt++)
        #pragma unroll
        for (int nt = 0; nt < 4; nt++)
            #pragma unroll
            for (int u = 0; u < 4; u++) acc[mt][nt][u] = 0.f;

    const int nc = K >> 5;
    const int r0q = tid >> 2, c0q = (tid & 3) * 8;
    const int r1q = (tid + 256) >> 2, c1q = ((tid + 256) & 3) * 8;

    uint4 st[8];

    {
        const size_t a0 = (size_t)(row0 + r0q)*K + c0q;
        const size_t a1 = (size_t)(row0 + r1q)*K + c1q;
        const size_t b0 = (size_t)(col0 + r0q)*K + c0q;
        const size_t b1 = (size_t)(col0 + r1q)*K + c1q;
        st[0] = *(const uint4*)(Ah + a0); st[1] = *(const uint4*)(Al + a0);
        st[2] = *(const uint4*)(Bh + b0); st[3] = *(const uint4*)(Bl + b0);
        st[4] = *(const uint4*)(Ah + a1); st[5] = *(const uint4*)(Al + a1);
        st[6] = *(const uint4*)(Bh + b1); st[7] = *(const uint4*)(Bl + b1);
        bf16* bp = smem;
        const int s0 = r0q*SROW + c0q, s1 = r1q*SROW + c1q;
        *(uint4*)(bp + s0)             = st[0];
        *(uint4*)(bp + OPELEMS + s0)   = st[1];
        *(uint4*)(bp + 2*OPELEMS + s0) = st[2];
        *(uint4*)(bp + 3*OPELEMS + s0) = st[3];
        *(uint4*)(bp + s1)             = st[4];
        *(uint4*)(bp + OPELEMS + s1)   = st[5];
        *(uint4*)(bp + 2*OPELEMS + s1) = st[6];
        *(uint4*)(bp + 3*OPELEMS + s1) = st[7];
    }

    const uint32_t a_row_off = (uint32_t)(wm*64 + (lane & 15)) * 80
                             + (uint32_t)(lane >> 4) * 16;
    const uint32_t b_row_off = 2*OPBYTES
                             + (uint32_t)(wn*32 + (lane & 7) + ((lane >> 4) & 1)*8) * 80
                             + (uint32_t)((lane >> 3) & 1) * 16;

    for (int c = 0; c < nc; c++) {
        __syncthreads();
        if (c + 1 < nc) {
            const size_t k0 = (size_t)(c + 1) * 32;
            const size_t a0 = (size_t)(row0 + r0q)*K + k0 + c0q;
            const size_t a1 = (size_t)(row0 + r1q)*K + k0 + c1q;
            const size_t b0 = (size_t)(col0 + r0q)*K + k0 + c0q;
            const size_t b1 = (size_t)(col0 + r1q)*K + k0 + c1q;
            st[0] = *(const uint4*)(Ah + a0); st[1] = *(const uint4*)(Al + a0);
            st[2] = *(const uint4*)(Bh + b0); st[3] = *(const uint4*)(Bl + b0);
            st[4] = *(const uint4*)(Ah + a1); st[5] = *(const uint4*)(Al + a1);
            st[6] = *(const uint4*)(Bh + b1); st[7] = *(const uint4*)(Bl + b1);
        }

        const uint32_t sb = sbase0 + (uint32_t)(c & 1) * BUFBYTES;
        #pragma unroll
        for (int ks = 0; ks < 2; ks++) {
            uint32_t ah[4][4], al[4][4], bh[4][2], bl[4][2];
            const uint32_t abase = sb + a_row_off + ks*32;
            #pragma unroll
            for (int mt = 0; mt < 4; mt++) {
                const uint32_t ad = abase + mt*(16*80);
                ldsm4(ah[mt][0], ah[mt][1], ah[mt][2], ah[mt][3], ad);
                ldsm4(al[mt][0], al[mt][1], al[mt][2], al[mt][3], ad + OPBYTES);
            }
            const uint32_t bbase = sb + b_row_off + ks*32;
            #pragma unroll
            for (int p = 0; p < 2; p++) {
                const uint32_t bd = bbase + p*(16*80);
                ldsm4(bh[2*p][0], bh[2*p][1], bh[2*p+1][0], bh[2*p+1][1], bd);
                ldsm4(bl[2*p][0], bl[2*p][1], bl[2*p+1][0], bl[2*p+1][1], bd + OPBYTES);
            }
            #pragma unroll
            for (int mt = 0; mt < 4; mt++)
                #pragma unroll
                for (int nt = 0; nt < 4; nt++) {
                    mma16816(acc[mt][nt], ah[mt], bh[nt]);
                    mma16816(acc[mt][nt], ah[mt], bl[nt]);
                    mma16816(acc[mt][nt], al[mt], bh[nt]);
                }
        }

        if (c + 1 < nc) {
            bf16* bp = smem + ((c + 1) & 1) * BUFELEMS;
            const int s0 = r0q*SROW + c0q, s1 = r1q*SROW + c1q;
            *(uint4*)(bp + s0)             = st[0];
            *(uint4*)(bp + OPELEMS + s0)   = st[1];
            *(uint4*)(bp + 2*OPELEMS + s0) = st[2];
            *(uint4*)(bp + 3*OPELEMS + s0) = st[3];
            *(uint4*)(bp + s1)             = st[4];
            *(uint4*)(bp + OPELEMS + s1)   = st[5];
            *(uint4*)(bp + 2*OPELEMS + s1) = st[6];
            *(uint4*)(bp + 3*OPELEMS + s1) = st[7];
        }
    }

    const int er = lane >> 2, ec = (lane & 3) * 2;
    #pragma unroll
    for (int mt = 0; mt < 4; mt++) {
        #pragma unroll
        for (int nt = 0; nt < 4; nt++) {
            const int grow = row0 + wm*64 + mt*16 + er;
            const int gcol = col0 + wn*32 + nt*8 + ec;
            if (EPI == 0) {
                *(float2*)&Cf[(size_t)grow*N + gcol] =
                    make_float2(acc[mt][nt][0], acc[mt][nt][1]);
                *(float2*)&Cf[(size_t)(grow+8)*N + gcol] =
                    make_float2(acc[mt][nt][2], acc[mt][nt][3]);
            } else {
                float f0 = acc[mt][nt][0], f1 = acc[mt][nt][1];
                float f2 = acc[mt][nt][2], f3 = acc[mt][nt][3];
                if (EPI == 1) {
                    f0 = fmaxf(f0, 0.f); f1 = fmaxf(f1, 0.f);
                    f2 = fmaxf(f2, 0.f); f3 = fmaxf(f3, 0.f);
                }
                bf16 h0,l0,h1,l1,h2,l2,h3,l3;
                split2(f0,h0,l0); split2(f1,h1,l1);
                split2(f2,h2,l2); split2(f3,h3,l3);
                __nv_bfloat162 hp0, lp0, hp1, lp1;
                hp0.x=h0; hp0.y=h1; lp0.x=l0; lp0.y=l1;
                hp1.x=h2; hp1.y=h3; lp1.x=l2; lp1.y=l3;
                *(__nv_bfloat162*)&Ch[(size_t)grow*N + gcol]     = hp0;
                *(__nv_bfloat162*)&Cl[(size_t)grow*N + gcol]     = lp0;
                *(__nv_bfloat162*)&Ch[(size_t)(grow+8)*N + gcol] = hp1;
                *(__nv_bfloat162*)&Cl[(size_t)(grow+8)*N + gcol] = lp1;
            }
        }
    }
}

// ---------------- MMA flash attention: cp.async pipeline + rolling BDW ------
#define ASTR 144
#define A_QWH 0
#define A_QWL 9216
#define A_QRH 18432
#define A_QRL 27648
#define A_STG 36864
#define S_KH  0
#define S_KL  9216
#define S_VH  18432
#define S_VL  27648
#define S_RH  36864
#define S_RL  46080
#define STG_SZ 55296
#define A_SCR (A_STG + 2*STG_SZ)       // 147456
#define W_BDW 0
#define W_PH  8448
#define W_PL  10752
#define WSCR_SZ 13056
#define A_TOT (A_SCR + 4*WSCR_SZ)      // 199680

// one 64-col BDW half: D = Qr @ Rstage^T, stored at phys cols [pb, pb+64)
__device__ __forceinline__ void bdw_half(
    char* sm, uint32_t sb, uint32_t rbase, int pb,
    uint32_t aoff, uint32_t boff, uint32_t wscr, int er, int ec)
{
    float D[8][4];
    #pragma unroll
    for (int nt = 0; nt < 8; nt++)
        #pragma unroll
        for (int u = 0; u < 4; u++) D[nt][u] = 0.f;
    #pragma unroll
    for (int ks = 0; ks < 4; ks++) {
        uint32_t arh[4], arl[4];
        ldsm4(arh[0], arh[1], arh[2], arh[3], sb + A_QRH + aoff + ks*32);
        ldsm4(arl[0], arl[1], arl[2], arl[3], sb + A_QRL + aoff + ks*32);
        #pragma unroll
        for (int p = 0; p < 4; p++) {
            uint32_t bh4[4], bl4[4];
            const uint32_t ra = rbase + boff + (uint32_t)(p*16)*ASTR + ks*32;
            ldsm4(bh4[0], bh4[1], bh4[2], bh4[3], ra);
            ldsm4(bl4[0], bl4[1], bl4[2], bl4[3], ra + (S_RL - S_RH));
            mma16816(D[2*p],   arh, bh4);   mma16816(D[2*p],   arh, bl4);
            mma16816(D[2*p],   arl, bh4);
            mma16816(D[2*p+1], arh, bh4+2); mma16816(D[2*p+1], arh, bl4+2);
            mma16816(D[2*p+1], arl, bh4+2);
        }
    }
    float* bdw = (float*)(sm + wscr + W_BDW);
    #pragma unroll
    for (int nt = 0; nt < 8; nt++) {
        const int c = pb + nt*8 + ec;
        bdw[er*132 + c]       = D[nt][0];
        bdw[er*132 + c + 1]   = D[nt][1];
        bdw[(er+8)*132 + c]   = D[nt][2];
        bdw[(er+8)*132 + c+1] = D[nt][3];
    }
}

__global__ __launch_bounds__(128) void attn_mma_kernel(
    const bf16* __restrict__ Qh, const bf16* __restrict__ Ql,
    const bf16* __restrict__ Kh, const bf16* __restrict__ Kl,
    const bf16* __restrict__ Vh, const bf16* __restrict__ Vl,
    const bf16* __restrict__ Rh, const bf16* __restrict__ Rl,
    const float* __restrict__ rwb, const float* __restrict__ rrb,
    bf16* __restrict__ OHp, bf16* __restrict__ OLp)
{
    extern __shared__ char sm[];
    const uint32_t sb = smem_u32(sm);
    const int i0 = blockIdx.x * 64;
    const int h  = blockIdx.y, b = blockIdx.z;
    const int tid = threadIdx.x, w = tid >> 5, lane = tid & 31;

    // ---- load Q, add biases, split, store both variants ----
    #pragma unroll
    for (int it = 0; it < 4; it++) {
        int idx = tid + it*128;
        int row = idx >> 3, c8 = (idx & 7) * 8;
        const size_t g = (size_t)(b*QL + i0 + row)*EE + h*DH + c8;
        union { uint4 u; bf16 e[8]; } uh, ul;
        uh.u = *(const uint4*)(Qh + g);
        ul.u = *(const uint4*)(Ql + g);
        bf16* qwh = (bf16*)(sm + A_QWH + row*ASTR) + c8;
        bf16* qwl = (bf16*)(sm + A_QWL + row*ASTR) + c8;
        bf16* qrh = (bf16*)(sm + A_QRH + row*ASTR) + c8;
        bf16* qrl = (bf16*)(sm + A_QRL + row*ASTR) + c8;
        #pragma unroll
        for (int e = 0; e < 8; e++) {
            float q = __bfloat162float(uh.e[e]) + __bfloat162float(ul.e[e]);
            bf16 hh, ll;
            split2(q + rwb[h*DH + c8 + e], hh, ll); qwh[e] = hh; qwl[e] = ll;
            split2(q + rrb[h*DH + c8 + e], hh, ll); qrh[e] = hh; qrl[e] = ll;
        }
    }

    float O[8][4];
    #pragma unroll
    for (int nt = 0; nt < 8; nt++)
        #pragma unroll
        for (int u = 0; u < 4; u++) O[nt][u] = 0.f;
    float m_i[2] = {-INFINITY, -INFINITY}, l_i[2] = {0.f, 0.f};

    const uint32_t aoff = (uint32_t)(w*16 + (lane&15))*ASTR + ((lane>>4)&1)*16;
    const uint32_t boff = (uint32_t)((lane&7) + ((lane>>4)&1)*8)*ASTR + ((lane>>3)&1)*16;
    const uint32_t voff = (uint32_t)((lane&7) + ((lane>>3)&1)*8)*ASTR + ((lane>>4)&1)*16;
    const uint32_t poff = (uint32_t)(lane&15)*ASTR + ((lane>>4)&1)*16;
    const uint32_t wscr = A_SCR + w*WSCR_SZ;
    const int er = lane >> 2, ec = (lane & 3) * 2;
    const int lr0 = w*16 + er, lr1 = lr0 + 8;
    const int ig0 = i0 + lr0, ig1 = i0 + lr1;

    int njt = (i0 + 63 + ML)/64 + 1;
    if (njt > KL/64) njt = KL/64;
    const int rorg = 960 - i0;   // absolute r-index of physical BDW slot 0

    const int ldrow = tid >> 3, ldc8 = (tid & 7) * 8;

    // ---- prologue: R_low -> stage1 R area; tile0 -> stage0 ----
    #pragma unroll
    for (int it = 0; it < 4; it++) {
        int row = ldrow + it*16;
        int dg = rorg + row;                           // >= 0 always (i0<=960)
        const size_t g = (size_t)dg*EE + h*DH + ldc8;
        uint32_t d = sb + A_STG + STG_SZ + S_RH + row*ASTR + ldc8*2;
        cpa16(d,                 Rh + g);
        cpa16(d + (S_RL - S_RH), Rl + g);
    }
    {
        const uint32_t stg = sb + A_STG;               // stage 0
        #pragma unroll
        for (int it = 0; it < 4; it++) {
            int row = ldrow + it*16;
            const size_t g = (size_t)(b*KL + row)*EE + h*DH + ldc8;
            const uint32_t so = row*ASTR + ldc8*2;
            cpa16(stg + S_KH + so, Kh + g);
            cpa16(stg + S_KL + so, Kl + g);
            cpa16(stg + S_VH + so, Vh + g);
            cpa16(stg + S_VL + so, Vl + g);
            int dg = rorg + 64 + row;
            int ok = dg < KL;
            const size_t gr = (size_t)(ok ? dg : 0)*EE + h*DH + ldc8;
            cpa16z(stg + S_RH + so, Rh + gr, ok ? 16 : 0);
            cpa16z(stg + S_RL + so, Rl + gr, ok ? 16 : 0);
        }
    }
    CPA_COMMIT();
    cpa_wait<0>();
    __syncthreads();

    // prologue BDW (phys cols [0,64), from stage1 R)
    bdw_half(sm, sb, sb + A_STG + STG_SZ + S_RH, 0, aoff, boff, wscr, er, ec);

    for (int jt = 0; jt < njt; jt++) {
        const int j0 = jt * 64;
        __syncthreads();                       // all warps done with jt-1 (+ prologue BDW)
        if (jt + 1 < njt) {
            const uint32_t stg = sb + A_STG + ((jt+1)&1)*STG_SZ;
            const int jn = (jt+1)*64;
            #pragma unroll
            for (int it = 0; it < 4; it++) {
                int row = ldrow + it*16;
                const size_t g = (size_t)(b*KL + jn + row)*EE + h*DH + ldc8;
                const uint32_t so = row*ASTR + ldc8*2;
                cpa16(stg + S_KH + so, Kh + g);
                cpa16(stg + S_KL + so, Kl + g);
                cpa16(stg + S_VH + so, Vh + g);
                cpa16(stg + S_VL + so, Vl + g);
                int dg = rorg + 64*(jt+2) + row;
                int ok = dg < KL;
                const size_t gr = (size_t)(ok ? dg : 0)*EE + h*DH + ldc8;
                cpa16z(stg + S_RH + so, Rh + gr, ok ? 16 : 0);
                cpa16z(stg + S_RL + so, Rl + gr, ok ? 16 : 0);
            }
            CPA_COMMIT();
            cpa_wait<1>();
        } else {
            cpa_wait<0>();
        }
        __syncthreads();

        const uint32_t stg = sb + A_STG + (jt&1)*STG_SZ;

        // ---- BDW new half (64 cols) -> phys base alternates 64/0 ----
        bdw_half(sm, sb, stg + S_RH, (jt&1) ? 0 : 64, aoff, boff, wscr, er, ec);

        // ---- AC = Qw @ K^T ----
        float S[8][4];
        #pragma unroll
        for (int nt = 0; nt < 8; nt++)
            #pragma unroll
            for (int u = 0; u < 4; u++) S[nt][u] = 0.f;
        #pragma unroll
        for (int ks = 0; ks < 4; ks++) {
            uint32_t awh[4], awl[4];
            ldsm4(awh[0], awh[1], awh[2], awh[3], sb + A_QWH + aoff + ks*32);
            ldsm4(awl[0], awl[1], awl[2], awl[3], sb + A_QWL + aoff + ks*32);
            #pragma unroll
            for (int p = 0; p < 4; p++) {
                uint32_t bh4[4], bl4[4];
                const uint32_t ka = stg + S_KH + boff + (uint32_t)(p*16)*ASTR + ks*32;
                ldsm4(bh4[0], bh4[1], bh4[2], bh4[3], ka);
                ldsm4(bl4[0], bl4[1], bl4[2], bl4[3], ka + (S_KL - S_KH));
                mma16816(S[2*p],   awh, bh4);   mma16816(S[2*p],   awh, bl4);
                mma16816(S[2*p],   awl, bh4);
                mma16816(S[2*p+1], awh, bh4+2); mma16816(S[2*p+1], awh, bl4+2);
                mma16816(S[2*p+1], awl, bh4+2);
            }
        }
        __syncwarp();

        // ---- gather rolling BDW diagonal, mask+scale, online softmax ----
        const float* bdw = (const float*)(sm + wscr + W_BDW);
        const int phase = (jt & 1) * 64;
        float mx0 = -INFINITY, mx1 = -INFINITY;
        #pragma unroll
        for (int nt = 0; nt < 8; nt++) {
            const int c = nt*8 + ec;
            float s00 = S[nt][0] + bdw[er*132     + ((c   - lr0 + 63 + phase) & 127)];
            float s01 = S[nt][1] + bdw[er*132     + ((c+1 - lr0 + 63 + phase) & 127)];
            float s10 = S[nt][2] + bdw[(er+8)*132 + ((c   - lr1 + 63 + phase) & 127)];
            float s11 = S[nt][3] + bdw[(er+8)*132 + ((c+1 - lr1 + 63 + phase) & 127)];
            const int jg = j0 + c;
            s00 = (jg   > ig0 + ML) ? -1e30f : s00 * 0.03125f;
            s01 = (jg+1 > ig0 + ML) ? -1e30f : s01 * 0.03125f;
            s10 = (jg   > ig1 + ML) ? -1e30f : s10 * 0.03125f;
            s11 = (jg+1 > ig1 + ML) ? -1e30f : s11 * 0.03125f;
            S[nt][0] = s00; S[nt][1] = s01; S[nt][2] = s10; S[nt][3] = s11;
            mx0 = fmaxf(mx0, fmaxf(s00, s01));
            mx1 = fmaxf(mx1, fmaxf(s10, s11));
        }
        mx0 = fmaxf(mx0, __shfl_xor_sync(0xffffffffu, mx0, 1));
        mx0 = fmaxf(mx0, __shfl_xor_sync(0xffffffffu, mx0, 2));
        mx1 = fmaxf(mx1, __shfl_xor_sync(0xffffffffu, mx1, 1));
        mx1 = fmaxf(mx1, __shfl_xor_sync(0xffffffffu, mx1, 2));
        const float mn0 = fmaxf(m_i[0], mx0), mn1 = fmaxf(m_i[1], mx1);
        const float sf0 = __expf(m_i[0] - mn0), sf1 = __expf(m_i[1] - mn1);
        m_i[0] = mn0; m_i[1] = mn1;

        bf16* pph = (bf16*)(sm + wscr + W_PH);
        bf16* ppl = (bf16*)(sm + wscr + W_PL);
        float ps0 = 0.f, ps1 = 0.f;
        #pragma unroll
        for (int nt = 0; nt < 8; nt++) {
            const int c = nt*8 + ec;
            float p00 = __expf(S[nt][0] - mn0);
            float p01 = __expf(S[nt][1] - mn0);
            float p10 = __expf(S[nt][2] - mn1);
            float p11 = __expf(S[nt][3] - mn1);
            ps0 += p00 + p01; ps1 += p10 + p11;
            bf16 h0,l0,h1,l1;
            __nv_bfloat162 hp, lp;
            split2(p00,h0,l0); split2(p01,h1,l1);
            hp.x=h0; hp.y=h1; lp.x=l0; lp.y=l1;
            *(__nv_bfloat162*)(pph + er*72 + c) = hp;
            *(__nv_bfloat162*)(ppl + er*72 + c) = lp;
            split2(p10,h0,l0); split2(p11,h1,l1);
            hp.x=h0; hp.y=h1; lp.x=l0; lp.y=l1;
            *(__nv_bfloat162*)(pph + (er+8)*72 + c) = hp;
            *(__nv_bfloat162*)(ppl + (er+8)*72 + c) = lp;
        }
        ps0 += __shfl_xor_sync(0xffffffffu, ps0, 1);
        ps0 += __shfl_xor_sync(0xffffffffu, ps0, 2);
        ps1 += __shfl_xor_sync(0xffffffffu, ps1, 1);
        ps1 += __shfl_xor_sync(0xffffffffu, ps1, 2);
        l_i[0] = l_i[0]*sf0 + ps0;
        l_i[1] = l_i[1]*sf1 + ps1;
        #pragma unroll
        for (int nt = 0; nt < 8; nt++) {
            O[nt][0] *= sf0; O[nt][1] *= sf0;
            O[nt][2] *= sf1; O[nt][3] *= sf1;
        }
        __syncwarp();

        // ---- O += P @ V ----
        #pragma unroll
        for (int ks = 0; ks < 4; ks++) {
            uint32_t ph4[4], pl4[4];
            ldsm4(ph4[0], ph4[1], ph4[2], ph4[3], sb + wscr + W_PH + poff + ks*32);
            ldsm4(pl4[0], pl4[1], pl4[2], pl4[3], sb + wscr + W_PL + poff + ks*32);
            #pragma unroll
            for (int p = 0; p < 4; p++) {
                uint32_t vh4[4], vl4[4];
                const uint32_t va = stg + S_VH + voff + (uint32_t)(ks*16)*ASTR + p*32;
                ldsm4t(vh4[0], vh4[1], vh4[2], vh4[3], va);
                ldsm4t(vl4[0], vl4[1], vl4[2], vl4[3], va + (S_VL - S_VH));
                mma16816(O[2*p],   ph4, vh4);   mma16816(O[2*p],   ph4, vl4);
                mma16816(O[2*p],   pl4, vh4);
                mma16816(O[2*p+1], ph4, vh4+2); mma16816(O[2*p+1], ph4, vl4+2);
                mma16816(O[2*p+1], pl4, vh4+2);
            }
        }
    }

    // ---- epilogue: normalize + split store ----
    const float inv0 = 1.0f / l_i[0], inv1 = 1.0f / l_i[1];
    #pragma unroll
    for (int nt = 0; nt < 8; nt++) {
        const int c = nt*8 + ec;
        const size_t g0 = (size_t)(b*QL + ig0)*EE + h*DH + c;
        const size_t g1 = (size_t)(b*QL + ig1)*EE + h*DH + c;
        bf16 h0,l0,h1,l1;
        __nv_bfloat162 hp, lp;
        split2(O[nt][0]*inv0, h0, l0); split2(O[nt][1]*inv0, h1, l1);
        hp.x=h0; hp.y=h1; lp.x=l0; lp.y=l1;
        *(__nv_bfloat162*)(OHp + g0) = hp;
        *(__nv_bfloat162*)(OLp + g0) = lp;
        split2(O[nt][2]*inv1, h0, l0); split2(O[nt][3]*inv1, h1, l1);
        hp.x=h0; hp.y=h1; lp.x=l0; lp.y=l1;
        *(__nv_bfloat162*)(OHp + g1) = hp;
        *(__nv_bfloat162*)(OLp + g1) = lp;
    }
}

// ---------------- residual add + LayerNorm ----------------------------------
template<int WB>
__global__ __launch_bounds__(256) void add_ln_kernel(
    const float* __restrict__ a, const float* __restrict__ res,
    const float* __restrict__ g, const float* __restrict__ bt,
    float* __restrict__ out, bf16* __restrict__ oh, bf16* __restrict__ ol)
{
    __shared__ float red[256];
    const int row = blockIdx.x;
    const int tid = threadIdx.x;
    const size_t base = (size_t)row * EE;

    float v[4];
    #pragma unroll
    for (int u = 0; u < 4; u++)
        v[u] = a[base + u*256 + tid] + res[base + u*256 + tid];

    float s = v[0] + v[1] + v[2] + v[3];
    red[tid] = s; __syncthreads();
    for (int off = 128; off > 0; off >>= 1) {
        if (tid < off) red[tid] += red[tid + off];
        __syncthreads();
    }
    const float mu = red[0] * (1.0f / EE);
    __syncthreads();

    float d = 0.f;
    #pragma unroll
    for (int u = 0; u < 4; u++) { float t = v[u] - mu; d += t*t; }
    red[tid] = d; __syncthreads();
    for (int off = 128; off > 0; off >>= 1) {
        if (tid < off) red[tid] += red[tid + off];
        __syncthreads();
    }
    const float rs = rsqrtf(red[0] * (1.0f / EE) + 1e-3f);

    #pragma unroll
    for (int u = 0; u < 4; u++) {
        int c = u*256 + tid;
        float o = (v[u] - mu) * rs * g[c] + bt[c];
        out[base + c] = o;
        if (WB) {
            bf16 hh_, ll_; split2(o, hh_, ll_);
            oh[base + c] = hh_; ol[base + c] = ll_;
        }
    }
}

// ---------------- launch ----------------------------------------------------
extern "C" void kernel_launch(void* const* d_in, const int* in_sizes, int n_in,
                              void* d_out, int out_size)
{
    const float* w      = (const float*)d_in[0];
    const float* r      = (const float*)d_in[1];
    const float* member = (const float*)d_in[2];
    const float* Wq     = (const float*)d_in[4];
    const float* Wk     = (const float*)d_in[5];
    const float* Wv     = (const float*)d_in[6];
    const float* Wr     = (const float*)d_in[7];
    const float* Wo     = (const float*)d_in[8];
    const float* rwb    = (const float*)d_in[9];
    const float* rrb    = (const float*)d_in[10];
    const float* ln1g   = (const float*)d_in[11];
    const float* ln1b   = (const float*)d_in[12];
    const float* W1     = (const float*)d_in[13];
    const float* W2     = (const float*)d_in[14];
    const float* ln2g   = (const float*)d_in[15];
    const float* ln2b   = (const float*)d_in[16];
    float* out = (float*)d_out;

    float *ao,*x,*y;
    cudaGetSymbolAddress((void**)&ao, g_ao);
    cudaGetSymbolAddress((void**)&x,  g_x);
    cudaGetSymbolAddress((void**)&y,  g_y);
    bf16 *cath,*catl,*wh,*wl,*rih,*ril,*atth,*attl,*xh,*xl,*hhh,*hhl;
    bf16 *qph,*qpl,*kph,*kpl,*vph,*vpl,*rph,*rpl;
    bf16 *wqh,*wql,*wkh,*wkl,*wvh,*wvl,*wrh,*wrl,*woh,*wol,*w1h,*w1l,*w2h,*w2l;
    cudaGetSymbolAddress((void**)&cath, g_cat_h); cudaGetSymbolAddress((void**)&catl, g_cat_l);
    cudaGetSymbolAddress((void**)&wh,   g_w_h);   cudaGetSymbolAddress((void**)&wl,   g_w_l);
    cudaGetSymbolAddress((void**)&rih,  g_r_h);   cudaGetSymbolAddress((void**)&ril,  g_r_l);
    cudaGetSymbolAddress((void**)&qph,  g_q_h);   cudaGetSymbolAddress((void**)&qpl,  g_q_l);
    cudaGetSymbolAddress((void**)&kph,  g_k_h);   cudaGetSymbolAddress((void**)&kpl,  g_k_l);
    cudaGetSymbolAddress((void**)&vph,  g_v_h);   cudaGetSymbolAddress((void**)&vpl,  g_v_l);
    cudaGetSymbolAddress((void**)&rph,  g_rpj_h); cudaGetSymbolAddress((void**)&rpl,  g_rpj_l);
    cudaGetSymbolAddress((void**)&atth, g_att_h); cudaGetSymbolAddress((void**)&attl, g_att_l);
    cudaGetSymbolAddress((void**)&xh,   g_x_h);   cudaGetSymbolAddress((void**)&xl,   g_x_l);
    cudaGetSymbolAddress((void**)&hhh,  g_hh_h);  cudaGetSymbolAddress((void**)&hhl,  g_hh_l);
    cudaGetSymbolAddress((void**)&wqh,  g_Wq_h);  cudaGetSymbolAddress((void**)&wql,  g_Wq_l);
    cudaGetSymbolAddress((void**)&wkh,  g_Wk_h);  cudaGetSymbolAddress((void**)&wkl,  g_Wk_l);
    cudaGetSymbolAddress((void**)&wvh,  g_Wv_h);  cudaGetSymbolAddress((void**)&wvl,  g_Wv_l);
    cudaGetSymbolAddress((void**)&wrh,  g_Wr_h);  cudaGetSymbolAddress((void**)&wrl,  g_Wr_l);
    cudaGetSymbolAddress((void**)&woh,  g_Wo_h);  cudaGetSymbolAddress((void**)&wol,  g_Wo_l);
    cudaGetSymbolAddress((void**)&w1h,  g_W1_h);  cudaGetSymbolAddress((void**)&w1l,  g_W1_l);
    cudaGetSymbolAddress((void**)&w2h,  g_W2_h);  cudaGetSymbolAddress((void**)&w2l,  g_W2_l);

    cudaFuncSetAttribute(mma_gemm<0>, cudaFuncAttributeMaxDynamicSharedMemorySize, GSM_TOTAL);
    cudaFuncSetAttribute(mma_gemm<1>, cudaFuncAttributeMaxDynamicSharedMemorySize, GSM_TOTAL);
    cudaFuncSetAttribute(mma_gemm<2>, cudaFuncAttributeMaxDynamicSharedMemorySize, GSM_TOTAL);
    cudaFuncSetAttribute(attn_mma_kernel, cudaFuncAttributeMaxDynamicSharedMemorySize, A_TOT);

    // input conversions
    concat_convert_kernel<<<BB*KL*EE/4/256, 256>>>(member, w, cath, catl);
    convert_split_kernel <<<BB*QL*EE/4/256, 256>>>(w, wh, wl);
    convert_split_kernel <<<KL*EE/4/256,    256>>>(r, rih, ril);
    {
        TC5 p;
        p.s[0]=Wq; p.dh[0]=wqh; p.dl[0]=wql;
        p.s[1]=Wk; p.dh[1]=wkh; p.dl[1]=wkl;
        p.s[2]=Wv; p.dh[2]=wvh; p.dl[2]=wvl;
        p.s[3]=Wr; p.dh[3]=wrh; p.dl[3]=wrl;
        p.s[4]=Wo; p.dh[4]=woh; p.dl[4]=wol;
        transpose_convert5_kernel<<<dim3(EE/32, EE/32, 5), dim3(32,8)>>>(p);
    }
    transpose_convert_kernel<<<dim3(FF/32, EE/32), dim3(32,8)>>>(W1, w1h, w1l, EE, FF);
    transpose_convert_kernel<<<dim3(EE/32, FF/32), dim3(32,8)>>>(W2, w2h, w2l, FF, EE);

    // projections (split bf16 outputs)
    mma_gemm<2><<<dim3(EE/128, (BB*KL)/128), 256, GSM_TOTAL>>>(
        cath, catl, wkh, wkl, nullptr, kph, kpl, BB*KL, EE, EE);
    mma_gemm<2><<<dim3(EE/128, (BB*KL)/128), 256, GSM_TOTAL>>>(
        cath, catl, wvh, wvl, nullptr, vph, vpl, BB*KL, EE, EE);
    mma_gemm<2><<<dim3(EE/128, (BB*QL)/128), 256, GSM_TOTAL>>>(
        wh, wl, wqh, wql, nullptr, qph, qpl, BB*QL, EE, EE);
    mma_gemm<2><<<dim3(EE/128, KL/128), 256, GSM_TOTAL>>>(
        rih, ril, wrh, wrl, nullptr, rph, rpl, KL, EE, EE);

    // fused MMA attention (cp.async pipelined, rolling BDW)
    attn_mma_kernel<<<dim3(QL/64, HH, BB), 128, A_TOT>>>(
        qph, qpl, kph, kpl, vph, vpl, rph, rpl, rwb, rrb, atth, attl);

    // output projection + LN1
    mma_gemm<0><<<dim3(EE/128, (BB*QL)/128), 256, GSM_TOTAL>>>(
        atth, attl, woh, wol, ao, nullptr, nullptr, BB*QL, EE, EE);
    add_ln_kernel<1><<<BB*QL, 256>>>(ao, w, ln1g, ln1b, x, xh, xl);

    // FFN + LN2
    mma_gemm<1><<<dim3(FF/128, (BB*QL)/128), 256, GSM_TOTAL>>>(
        xh, xl, w1h, w1l, nullptr, hhh, hhl, BB*QL, FF, EE);
    mma_gemm<0><<<dim3(EE/128, (BB*QL)/128), 256, GSM_TOTAL>>>(
        hhh, hhl, w2h, w2l, y, nullptr, nullptr, BB*QL, EE, FF);
    add_ln_kernel<0><<<BB*QL, 256>>>(y, x, ln2g, ln2b, out, nullptr, nullptr);
}

// round 7
// speedup vs baseline: 5.3161x; 1.0476x over previous
#include <cuda_runtime.h>
#include <cuda_bf16.h>
#include <math.h>
#include <stdint.h>

#define BB 2
#define QL 1024
#define ML 1024
#define KL 2048
#define EE 1024
#define HH 16
#define DH 64
#define FF 4096

typedef __nv_bfloat16 bf16;

// ---------------- scratch (static device globals) ---------------------------
__device__ float g_ao [BB*QL*EE];
__device__ float g_x  [BB*QL*EE];
__device__ float g_y  [BB*QL*EE];

__device__ bf16 g_cat_h[BB*KL*EE], g_cat_l[BB*KL*EE];
__device__ bf16 g_r_h  [KL*EE],    g_r_l  [KL*EE];
__device__ bf16 g_q_h  [BB*QL*EE], g_q_l  [BB*QL*EE];
__device__ bf16 g_k_h  [BB*KL*EE], g_k_l  [BB*KL*EE];
__device__ bf16 g_v_h  [BB*KL*EE], g_v_l  [BB*KL*EE];
__device__ bf16 g_rpj_h[KL*EE],    g_rpj_l[KL*EE];
__device__ bf16 g_att_h[BB*QL*EE], g_att_l[BB*QL*EE];
__device__ bf16 g_x_h  [BB*QL*EE], g_x_l  [BB*QL*EE];
__device__ bf16 g_hh_h [BB*QL*FF], g_hh_l [BB*QL*FF];
__device__ bf16 g_Wq_h[EE*EE], g_Wq_l[EE*EE];
__device__ bf16 g_Wk_h[EE*EE], g_Wk_l[EE*EE];
__device__ bf16 g_Wv_h[EE*EE], g_Wv_l[EE*EE];
__device__ bf16 g_Wr_h[EE*EE], g_Wr_l[EE*EE];
__device__ bf16 g_Wo_h[EE*EE], g_Wo_l[EE*EE];
__device__ bf16 g_W1_h[FF*EE], g_W1_l[FF*EE];
__device__ bf16 g_W2_h[EE*FF], g_W2_l[EE*FF];

// ---------------- helpers ----------------------------------------------------
__device__ __forceinline__ uint32_t smem_u32(const void* p) {
    uint32_t a;
    asm("{ .reg .u64 t; cvta.to.shared.u64 t, %1; cvt.u32.u64 %0, t; }"
        : "=r"(a) : "l"(p));
    return a;
}
__device__ __forceinline__ void split2(float v, bf16& h, bf16& l) {
    h = __float2bfloat16(v);
    l = __float2bfloat16(v - __bfloat162float(h));
}
__device__ __forceinline__ void ldsm4(uint32_t& r0, uint32_t& r1,
                                      uint32_t& r2, uint32_t& r3, uint32_t addr) {
    asm volatile("ldmatrix.sync.aligned.m8n8.x4.shared.b16 {%0,%1,%2,%3}, [%4];"
        : "=r"(r0), "=r"(r1), "=r"(r2), "=r"(r3) : "r"(addr));
}
__device__ __forceinline__ void ldsm4t(uint32_t& r0, uint32_t& r1,
                                       uint32_t& r2, uint32_t& r3, uint32_t addr) {
    asm volatile("ldmatrix.sync.aligned.m8n8.x4.trans.shared.b16 {%0,%1,%2,%3}, [%4];"
        : "=r"(r0), "=r"(r1), "=r"(r2), "=r"(r3) : "r"(addr));
}
__device__ __forceinline__ void mma16816(float* d, const uint32_t* a, const uint32_t* b) {
    asm volatile(
        "mma.sync.aligned.m16n8k16.row.col.f32.bf16.bf16.f32 "
        "{%0,%1,%2,%3}, {%4,%5,%6,%7}, {%8,%9}, {%0,%1,%2,%3};"
        : "+f"(d[0]), "+f"(d[1]), "+f"(d[2]), "+f"(d[3])
        : "r"(a[0]), "r"(a[1]), "r"(a[2]), "r"(a[3]), "r"(b[0]), "r"(b[1]));
}
__device__ __forceinline__ void cpa16(uint32_t d, const void* s) {
    asm volatile("cp.async.cg.shared.global [%0], [%1], 16;" :: "r"(d), "l"(s));
}
__device__ __forceinline__ void cpa16z(uint32_t d, const void* s, int sz) {
    asm volatile("cp.async.cg.shared.global [%0], [%1], 16, %2;"
                 :: "r"(d), "l"(s), "r"(sz));
}
#define CPA_COMMIT() asm volatile("cp.async.commit_group;")
template<int N> __device__ __forceinline__ void cpa_wait() {
    asm volatile("cp.async.wait_group %0;" :: "n"(N));
}

// ---------------- conversion kernels ----------------------------------------
__global__ __launch_bounds__(256) void concat_convert_kernel(
    const float* __restrict__ member, const float* __restrict__ w,
    bf16* __restrict__ dh, bf16* __restrict__ dl)
{
    int idx = blockIdx.x * 256 + threadIdx.x;
    int fidx = idx * 4;
    int b   = fidx / (KL*EE);
    int rem = fidx % (KL*EE);
    int s   = rem / EE;
    int e   = rem % EE;
    float4 v;
    if (s < ML) v = *(const float4*)&member[(size_t)(b*ML + s)*EE + e];
    else        v = *(const float4*)&w[(size_t)(b*QL + (s-ML))*EE + e];
    bf16 h0,l0,h1,l1,h2,l2,h3,l3;
    split2(v.x,h0,l0); split2(v.y,h1,l1); split2(v.z,h2,l2); split2(v.w,h3,l3);
    __nv_bfloat162 hp0, hp1, lp0, lp1;
    hp0.x=h0; hp0.y=h1; hp1.x=h2; hp1.y=h3;
    lp0.x=l0; lp0.y=l1; lp1.x=l2; lp1.y=l3;
    ((__nv_bfloat162*)dh)[idx*2]   = hp0; ((__nv_bfloat162*)dh)[idx*2+1] = hp1;
    ((__nv_bfloat162*)dl)[idx*2]   = lp0; ((__nv_bfloat162*)dl)[idx*2+1] = lp1;
}

__global__ __launch_bounds__(256) void convert_split_kernel(
    const float* __restrict__ s, bf16* __restrict__ dh, bf16* __restrict__ dl)
{
    int idx = blockIdx.x * 256 + threadIdx.x;
    float4 v = ((const float4*)s)[idx];
    bf16 h0,l0,h1,l1,h2,l2,h3,l3;
    split2(v.x,h0,l0); split2(v.y,h1,l1); split2(v.z,h2,l2); split2(v.w,h3,l3);
    __nv_bfloat162 hp0, hp1, lp0, lp1;
    hp0.x=h0; hp0.y=h1; hp1.x=h2; hp1.y=h3;
    lp0.x=l0; lp0.y=l1; lp1.x=l2; lp1.y=l3;
    ((__nv_bfloat162*)dh)[idx*2]   = hp0; ((__nv_bfloat162*)dh)[idx*2+1] = hp1;
    ((__nv_bfloat162*)dl)[idx*2]   = lp0; ((__nv_bfloat162*)dl)[idx*2+1] = lp1;
}

struct TC5 { const float* s[5]; bf16* dh[5]; bf16* dl[5]; };

__global__ void transpose_convert5_kernel(TC5 p)   // 5x square EExEE
{
    __shared__ float t[32][33];
    const float* s = p.s[blockIdx.z];
    bf16* dh = p.dh[blockIdx.z];
    bf16* dl = p.dl[blockIdx.z];
    int n0 = blockIdx.x * 32, k0 = blockIdx.y * 32;
    int tx = threadIdx.x, ty = threadIdx.y;
    #pragma unroll
    for (int i = 0; i < 4; i++)
        t[ty + i*8][tx] = s[(size_t)(k0 + ty + i*8)*EE + n0 + tx];
    __syncthreads();
    #pragma unroll
    for (int i = 0; i < 4; i++) {
        float v = t[tx][ty + i*8];
        bf16 h, l; split2(v, h, l);
        size_t o = (size_t)(n0 + ty + i*8)*EE + k0 + tx;
        dh[o] = h; dl[o] = l;
    }
}

__global__ void transpose_convert_kernel(
    const float* __restrict__ s, bf16* __restrict__ dh, bf16* __restrict__ dl,
    int K, int N)
{
    __shared__ float t[32][33];
    int n0 = blockIdx.x * 32, k0 = blockIdx.y * 32;
    int tx = threadIdx.x, ty = threadIdx.y;
    #pragma unroll
    for (int i = 0; i < 4; i++)
        t[ty + i*8][tx] = s[(size_t)(k0 + ty + i*8)*N + n0 + tx];
    __syncthreads();
    #pragma unroll
    for (int i = 0; i < 4; i++) {
        float v = t[tx][ty + i*8];
        bf16 h, l; split2(v, h, l);
        size_t o = (size_t)(n0 + ty + i*8)*K + k0 + tx;
        dh[o] = h; dl[o] = l;
    }
}

// ---------------- bf16x3 warp-MMA GEMM (cp.async double-buffered) -----------
#define SROW     40
#define OPELEMS  (128*SROW)
#define OPBYTES  (OPELEMS*2)
#define BUFELEMS (4*OPELEMS)
#define BUFBYTES (BUFELEMS*2)
#define GSM_TOTAL (2*BUFBYTES)

// EPI: 0 = fp32 store, 1 = relu + split bf16, 2 = split bf16
// REMAP: A rows remapped grow -> (grow/QL)*KL + ML + grow%QL  (Q-from-cat)
template<int EPI, int REMAP>
__global__ __launch_bounds__(256, 2) void mma_gemm(
    const bf16* __restrict__ Ah, const bf16* __restrict__ Al,
    const bf16* __restrict__ Bh, const bf16* __restrict__ Bl,
    float* __restrict__ Cf, bf16* __restrict__ Ch, bf16* __restrict__ Cl,
    int M, int N, int K)
{
    extern __shared__ bf16 smem[];
    const int tid = threadIdx.x, wid = tid >> 5, lane = tid & 31;
    const int row0 = blockIdx.y * 128, col0 = blockIdx.x * 128;
    const int wm = wid & 1, wn = wid >> 1;
    const uint32_t sbase0 = smem_u32(smem);

    float acc[4][4][4];
    #pragma unroll
    for (int mt = 0; mt < 4; mt++)
        #pragma unroll
        for (int nt = 0; nt < 4; nt++)
            #pragma unroll
            for (int u = 0; u < 4; u++) acc[mt][nt][u] = 0.f;

    const int nc = K >> 5;
    const int r0q = tid >> 2, c0q = (tid & 3) * 8;
    const int r1q = r0q + 64;

    size_t aR0, aR1;
    if (REMAP) {
        const int g0 = row0 + r0q, g1 = row0 + r1q;
        aR0 = ((size_t)(g0 >> 10)*KL + ML + (g0 & 1023)) * (size_t)K;
        aR1 = ((size_t)(g1 >> 10)*KL + ML + (g1 & 1023)) * (size_t)K;
    } else {
        aR0 = (size_t)(row0 + r0q) * K;
        aR1 = (size_t)(row0 + r1q) * K;
    }
    const size_t bR0 = (size_t)(col0 + r0q) * K;
    const size_t bR1 = (size_t)(col0 + r1q) * K;
    const uint32_t s0b = (uint32_t)(r0q*80 + c0q*2);
    const uint32_t s1b = (uint32_t)(r1q*80 + c0q*2);

    auto issue = [&](int c) {
        const uint32_t d = sbase0 + (uint32_t)(c & 1) * BUFBYTES;
        const size_t k0 = (size_t)(c * 32) + c0q;
        cpa16(d + s0b,             Ah + aR0 + k0);
        cpa16(d + s0b + OPBYTES,   Al + aR0 + k0);
        cpa16(d + s0b + 2*OPBYTES, Bh + bR0 + k0);
        cpa16(d + s0b + 3*OPBYTES, Bl + bR0 + k0);
        cpa16(d + s1b,             Ah + aR1 + k0);
        cpa16(d + s1b + OPBYTES,   Al + aR1 + k0);
        cpa16(d + s1b + 2*OPBYTES, Bh + bR1 + k0);
        cpa16(d + s1b + 3*OPBYTES, Bl + bR1 + k0);
        CPA_COMMIT();
    };

    issue(0);

    const uint32_t a_row_off = (uint32_t)(wm*64 + (lane & 15)) * 80
                             + (uint32_t)(lane >> 4) * 16;
    const uint32_t b_row_off = 2*OPBYTES
                             + (uint32_t)(wn*32 + (lane & 7) + ((lane >> 4) & 1)*8) * 80
                             + (uint32_t)((lane >> 3) & 1) * 16;

    for (int c = 0; c < nc; c++) {
        cpa_wait<0>();
        __syncthreads();
        if (c + 1 < nc) issue(c + 1);

        const uint32_t sb = sbase0 + (uint32_t)(c & 1) * BUFBYTES;
        #pragma unroll
        for (int ks = 0; ks < 2; ks++) {
            uint32_t ah[4][4], al[4][4], bh[4][2], bl[4][2];
            const uint32_t abase = sb + a_row_off + ks*32;
            #pragma unroll
            for (int mt = 0; mt < 4; mt++) {
                const uint32_t ad = abase + mt*(16*80);
                ldsm4(ah[mt][0], ah[mt][1], ah[mt][2], ah[mt][3], ad);
                ldsm4(al[mt][0], al[mt][1], al[mt][2], al[mt][3], ad + OPBYTES);
            }
            const uint32_t bbase = sb + b_row_off + ks*32;
            #pragma unroll
            for (int p = 0; p < 2; p++) {
                const uint32_t bd = bbase + p*(16*80);
                ldsm4(bh[2*p][0], bh[2*p][1], bh[2*p+1][0], bh[2*p+1][1], bd);
                ldsm4(bl[2*p][0], bl[2*p][1], bl[2*p+1][0], bl[2*p+1][1], bd + OPBYTES);
            }
            #pragma unroll
            for (int mt = 0; mt < 4; mt++)
                #pragma unroll
                for (int nt = 0; nt < 4; nt++) {
                    mma16816(acc[mt][nt], ah[mt], bh[nt]);
                    mma16816(acc[mt][nt], ah[mt], bl[nt]);
                    mma16816(acc[mt][nt], al[mt], bh[nt]);
                }
        }
    }

    const int er = lane >> 2, ec = (lane & 3) * 2;
    #pragma unroll
    for (int mt = 0; mt < 4; mt++) {
        #pragma unroll
        for (int nt = 0; nt < 4; nt++) {
            const int grow = row0 + wm*64 + mt*16 + er;
            const int gcol = col0 + wn*32 + nt*8 + ec;
            if (EPI == 0) {
                *(float2*)&Cf[(size_t)grow*N + gcol] =
                    make_float2(acc[mt][nt][0], acc[mt][nt][1]);
                *(float2*)&Cf[(size_t)(grow+8)*N + gcol] =
                    make_float2(acc[mt][nt][2], acc[mt][nt][3]);
            } else {
                float f0 = acc[mt][nt][0], f1 = acc[mt][nt][1];
                float f2 = acc[mt][nt][2], f3 = acc[mt][nt][3];
                if (EPI == 1) {
                    f0 = fmaxf(f0, 0.f); f1 = fmaxf(f1, 0.f);
                    f2 = fmaxf(f2, 0.f); f3 = fmaxf(f3, 0.f);
                }
                bf16 h0,l0,h1,l1,h2,l2,h3,l3;
                split2(f0,h0,l0); split2(f1,h1,l1);
                split2(f2,h2,l2); split2(f3,h3,l3);
                __nv_bfloat162 hp0, lp0, hp1, lp1;
                hp0.x=h0; hp0.y=h1; lp0.x=l0; lp0.y=l1;
                hp1.x=h2; hp1.y=h3; lp1.x=l2; lp1.y=l3;
                *(__nv_bfloat162*)&Ch[(size_t)grow*N + gcol]     = hp0;
                *(__nv_bfloat162*)&Cl[(size_t)grow*N + gcol]     = lp0;
                *(__nv_bfloat162*)&Ch[(size_t)(grow+8)*N + gcol] = hp1;
                *(__nv_bfloat162*)&Cl[(size_t)(grow+8)*N + gcol] = lp1;
            }
        }
    }
}

// ---------------- MMA flash attention: cp.async pipeline + rolling BDW ------
#define ASTR 144
#define A_QWH 0
#define A_QWL 9216
#define A_QRH 18432
#define A_QRL 27648
#define A_STG 36864
#define S_KH  0
#define S_KL  9216
#define S_VH  18432
#define S_VL  27648
#define S_RH  36864
#define S_RL  46080
#define STG_SZ 55296
#define A_SCR (A_STG + 2*STG_SZ)       // 147456
#define W_BDW 0
#define W_PH  8448
#define W_PL  10752
#define WSCR_SZ 13056
#define A_TOT (A_SCR + 4*WSCR_SZ)      // 199680

// one 64-col BDW half: D = Qr @ Rstage^T, stored at phys cols [pb, pb+64)
__device__ __forceinline__ void bdw_half(
    char* sm, uint32_t sb, uint32_t rbase, int pb,
    uint32_t aoff, uint32_t boff, uint32_t wscr, int er, int ec)
{
    float D[8][4];
    #pragma unroll
    for (int nt = 0; nt < 8; nt++)
        #pragma unroll
        for (int u = 0; u < 4; u++) D[nt][u] = 0.f;
    #pragma unroll
    for (int ks = 0; ks < 4; ks++) {
        uint32_t arh[4], arl[4];
        ldsm4(arh[0], arh[1], arh[2], arh[3], sb + A_QRH + aoff + ks*32);
        ldsm4(arl[0], arl[1], arl[2], arl[3], sb + A_QRL + aoff + ks*32);
        #pragma unroll
        for (int p = 0; p < 4; p++) {
            uint32_t bh4[4], bl4[4];
            const uint32_t ra = rbase + boff + (uint32_t)(p*16)*ASTR + ks*32;
            ldsm4(bh4[0], bh4[1], bh4[2], bh4[3], ra);
            ldsm4(bl4[0], bl4[1], bl4[2], bl4[3], ra + (S_RL - S_RH));
            mma16816(D[2*p],   arh, bh4);   mma16816(D[2*p],   arh, bl4);
            mma16816(D[2*p],   arl, bh4);
            mma16816(D[2*p+1], arh, bh4+2); mma16816(D[2*p+1], arh, bl4+2);
            mma16816(D[2*p+1], arl, bh4+2);
        }
    }
    float* bdw = (float*)(sm + wscr + W_BDW);
    #pragma unroll
    for (int nt = 0; nt < 8; nt++) {
        const int c = pb + nt*8 + ec;
        bdw[er*132 + c]       = D[nt][0];
        bdw[er*132 + c + 1]   = D[nt][1];
        bdw[(er+8)*132 + c]   = D[nt][2];
        bdw[(er+8)*132 + c+1] = D[nt][3];
    }
}

__global__ __launch_bounds__(128) void attn_mma_kernel(
    const bf16* __restrict__ Qh, const bf16* __restrict__ Ql,
    const bf16* __restrict__ Kh, const bf16* __restrict__ Kl,
    const bf16* __restrict__ Vh, const bf16* __restrict__ Vl,
    const bf16* __restrict__ Rh, const bf16* __restrict__ Rl,
    const float* __restrict__ rwb, const float* __restrict__ rrb,
    bf16* __restrict__ OHp, bf16* __restrict__ OLp)
{
    extern __shared__ char sm[];
    const uint32_t sb = smem_u32(sm);
    const int i0 = blockIdx.x * 64;
    const int h  = blockIdx.y, b = blockIdx.z;
    const int tid = threadIdx.x, w = tid >> 5, lane = tid & 31;

    // ---- load Q, add biases, split, store both variants ----
    #pragma unroll
    for (int it = 0; it < 4; it++) {
        int idx = tid + it*128;
        int row = idx >> 3, c8 = (idx & 7) * 8;
        const size_t g = (size_t)(b*QL + i0 + row)*EE + h*DH + c8;
        union { uint4 u; bf16 e[8]; } uh, ul;
        uh.u = *(const uint4*)(Qh + g);
        ul.u = *(const uint4*)(Ql + g);
        bf16* qwh = (bf16*)(sm + A_QWH + row*ASTR) + c8;
        bf16* qwl = (bf16*)(sm + A_QWL + row*ASTR) + c8;
        bf16* qrh = (bf16*)(sm + A_QRH + row*ASTR) + c8;
        bf16* qrl = (bf16*)(sm + A_QRL + row*ASTR) + c8;
        #pragma unroll
        for (int e = 0; e < 8; e++) {
            float q = __bfloat162float(uh.e[e]) + __bfloat162float(ul.e[e]);
            bf16 hh, ll;
            split2(q + rwb[h*DH + c8 + e], hh, ll); qwh[e] = hh; qwl[e] = ll;
            split2(q + rrb[h*DH + c8 + e], hh, ll); qrh[e] = hh; qrl[e] = ll;
        }
    }

    float O[8][4];
    #pragma unroll
    for (int nt = 0; nt < 8; nt++)
        #pragma unroll
        for (int u = 0; u < 4; u++) O[nt][u] = 0.f;
    float m_i[2] = {-INFINITY, -INFINITY}, l_i[2] = {0.f, 0.f};

    const uint32_t aoff = (uint32_t)(w*16 + (lane&15))*ASTR + ((lane>>4)&1)*16;
    const uint32_t boff = (uint32_t)((lane&7) + ((lane>>4)&1)*8)*ASTR + ((lane>>3)&1)*16;
    const uint32_t voff = (uint32_t)((lane&7) + ((lane>>3)&1)*8)*ASTR + ((lane>>4)&1)*16;
    const uint32_t poff = (uint32_t)(lane&15)*ASTR + ((lane>>4)&1)*16;
    const uint32_t wscr = A_SCR + w*WSCR_SZ;
    const int er = lane >> 2, ec = (lane & 3) * 2;
    const int lr0 = w*16 + er, lr1 = lr0 + 8;
    const int ig0 = i0 + lr0, ig1 = i0 + lr1;

    int njt = (i0 + 63 + ML)/64 + 1;
    if (njt > KL/64) njt = KL/64;
    const int rorg = 960 - i0;   // absolute r-index of physical BDW slot 0

    const int ldrow = tid >> 3, ldc8 = (tid & 7) * 8;

    // ---- prologue: R_low -> stage1 R area; tile0 -> stage0 ----
    #pragma unroll
    for (int it = 0; it < 4; it++) {
        int row = ldrow + it*16;
        int dg = rorg + row;                           // >= 0 always (i0<=960)
        const size_t g = (size_t)dg*EE + h*DH + ldc8;
        uint32_t d = sb + A_STG + STG_SZ + S_RH + row*ASTR + ldc8*2;
        cpa16(d,                 Rh + g);
        cpa16(d + (S_RL - S_RH), Rl + g);
    }
    {
        const uint32_t stg = sb + A_STG;               // stage 0
        #pragma unroll
        for (int it = 0; it < 4; it++) {
            int row = ldrow + it*16;
            const size_t g = (size_t)(b*KL + row)*EE + h*DH + ldc8;
            const uint32_t so = row*ASTR + ldc8*2;
            cpa16(stg + S_KH + so, Kh + g);
            cpa16(stg + S_KL + so, Kl + g);
            cpa16(stg + S_VH + so, Vh + g);
            cpa16(stg + S_VL + so, Vl + g);
            int dg = rorg + 64 + row;
            int ok = dg < KL;
            const size_t gr = (size_t)(ok ? dg : 0)*EE + h*DH + ldc8;
            cpa16z(stg + S_RH + so, Rh + gr, ok ? 16 : 0);
            cpa16z(stg + S_RL + so, Rl + gr, ok ? 16 : 0);
        }
    }
    CPA_COMMIT();
    cpa_wait<0>();
    __syncthreads();

    // prologue BDW (phys cols [0,64), from stage1 R)
    bdw_half(sm, sb, sb + A_STG + STG_SZ + S_RH, 0, aoff, boff, wscr, er, ec);

    for (int jt = 0; jt < njt; jt++) {
        const int j0 = jt * 64;
        __syncthreads();                       // all warps done with jt-1 (+ prologue BDW)
        if (jt + 1 < njt) {
            const uint32_t stg = sb + A_STG + ((jt+1)&1)*STG_SZ;
            const int jn = (jt+1)*64;
            #pragma unroll
            for (int it = 0; it < 4; it++) {
                int row = ldrow + it*16;
                const size_t g = (size_t)(b*KL + jn + row)*EE + h*DH + ldc8;
                const uint32_t so = row*ASTR + ldc8*2;
                cpa16(stg + S_KH + so, Kh + g);
                cpa16(stg + S_KL + so, Kl + g);
                cpa16(stg + S_VH + so, Vh + g);
                cpa16(stg + S_VL + so, Vl + g);
                int dg = rorg + 64*(jt+2) + row;
                int ok = dg < KL;
                const size_t gr = (size_t)(ok ? dg : 0)*EE + h*DH + ldc8;
                cpa16z(stg + S_RH + so, Rh + gr, ok ? 16 : 0);
                cpa16z(stg + S_RL + so, Rl + gr, ok ? 16 : 0);
            }
            CPA_COMMIT();
            cpa_wait<1>();
        } else {
            cpa_wait<0>();
        }
        __syncthreads();

        const uint32_t stg = sb + A_STG + (jt&1)*STG_SZ;

        // ---- BDW new half (64 cols) -> phys base alternates 64/0 ----
        bdw_half(sm, sb, stg + S_RH, (jt&1) ? 0 : 64, aoff, boff, wscr, er, ec);

        // ---- AC = Qw @ K^T ----
        float S[8][4];
        #pragma unroll
        for (int nt = 0; nt < 8; nt++)
            #pragma unroll
            for (int u = 0; u < 4; u++) S[nt][u] = 0.f;
        #pragma unroll
        for (int ks = 0; ks < 4; ks++) {
            uint32_t awh[4], awl[4];
            ldsm4(awh[0], awh[1], awh[2], awh[3], sb + A_QWH + aoff + ks*32);
            ldsm4(awl[0], awl[1], awl[2], awl[3], sb + A_QWL + aoff + ks*32);
            #pragma unroll
            for (int p = 0; p < 4; p++) {
                uint32_t bh4[4], bl4[4];
                const uint32_t ka = stg + S_KH + boff + (uint32_t)(p*16)*ASTR + ks*32;
                ldsm4(bh4[0], bh4[1], bh4[2], bh4[3], ka);
                ldsm4(bl4[0], bl4[1], bl4[2], bl4[3], ka + (S_KL - S_KH));
                mma16816(S[2*p],   awh, bh4);   mma16816(S[2*p],   awh, bl4);
                mma16816(S[2*p],   awl, bh4);
                mma16816(S[2*p+1], awh, bh4+2); mma16816(S[2*p+1], awh, bl4+2);
                mma16816(S[2*p+1], awl, bh4+2);
            }
        }
        __syncwarp();

        // ---- gather rolling BDW diagonal, mask+scale, online softmax ----
        const float* bdw = (const float*)(sm + wscr + W_BDW);
        const int phase = (jt & 1) * 64;
        float mx0 = -INFINITY, mx1 = -INFINITY;
        #pragma unroll
        for (int nt = 0; nt < 8; nt++) {
            const int c = nt*8 + ec;
            float s00 = S[nt][0] + bdw[er*132     + ((c   - lr0 + 63 + phase) & 127)];
            float s01 = S[nt][1] + bdw[er*132     + ((c+1 - lr0 + 63 + phase) & 127)];
            float s10 = S[nt][2] + bdw[(er+8)*132 + ((c   - lr1 + 63 + phase) & 127)];
            float s11 = S[nt][3] + bdw[(er+8)*132 + ((c+1 - lr1 + 63 + phase) & 127)];
            const int jg = j0 + c;
            s00 = (jg   > ig0 + ML) ? -1e30f : s00 * 0.03125f;
            s01 = (jg+1 > ig0 + ML) ? -1e30f : s01 * 0.03125f;
            s10 = (jg   > ig1 + ML) ? -1e30f : s10 * 0.03125f;
            s11 = (jg+1 > ig1 + ML) ? -1e30f : s11 * 0.03125f;
            S[nt][0] = s00; S[nt][1] = s01; S[nt][2] = s10; S[nt][3] = s11;
            mx0 = fmaxf(mx0, fmaxf(s00, s01));
            mx1 = fmaxf(mx1, fmaxf(s10, s11));
        }
        mx0 = fmaxf(mx0, __shfl_xor_sync(0xffffffffu, mx0, 1));
        mx0 = fmaxf(mx0, __shfl_xor_sync(0xffffffffu, mx0, 2));
        mx1 = fmaxf(mx1, __shfl_xor_sync(0xffffffffu, mx1, 1));
        mx1 = fmaxf(mx1, __shfl_xor_sync(0xffffffffu, mx1, 2));
        const float mn0 = fmaxf(m_i[0], mx0), mn1 = fmaxf(m_i[1], mx1);
        const float sf0 = __expf(m_i[0] - mn0), sf1 = __expf(m_i[1] - mn1);
        m_i[0] = mn0; m_i[1] = mn1;

        bf16* pph = (bf16*)(sm + wscr + W_PH);
        bf16* ppl = (bf16*)(sm + wscr + W_PL);
        float ps0 = 0.f, ps1 = 0.f;
        #pragma unroll
        for (int nt = 0; nt < 8; nt++) {
            const int c = nt*8 + ec;
            float p00 = __expf(S[nt][0] - mn0);
            float p01 = __expf(S[nt][1] - mn0);
            float p10 = __expf(S[nt][2] - mn1);
            float p11 = __expf(S[nt][3] - mn1);
            ps0 += p00 + p01; ps1 += p10 + p11;
            bf16 h0,l0,h1,l1;
            __nv_bfloat162 hp, lp;
            split2(p00,h0,l0); split2(p01,h1,l1);
            hp.x=h0; hp.y=h1; lp.x=l0; lp.y=l1;
            *(__nv_bfloat162*)(pph + er*72 + c) = hp;
            *(__nv_bfloat162*)(ppl + er*72 + c) = lp;
            split2(p10,h0,l0); split2(p11,h1,l1);
            hp.x=h0; hp.y=h1; lp.x=l0; lp.y=l1;
            *(__nv_bfloat162*)(pph + (er+8)*72 + c) = hp;
            *(__nv_bfloat162*)(ppl + (er+8)*72 + c) = lp;
        }
        ps0 += __shfl_xor_sync(0xffffffffu, ps0, 1);
        ps0 += __shfl_xor_sync(0xffffffffu, ps0, 2);
        ps1 += __shfl_xor_sync(0xffffffffu, ps1, 1);
        ps1 += __shfl_xor_sync(0xffffffffu, ps1, 2);
        l_i[0] = l_i[0]*sf0 + ps0;
        l_i[1] = l_i[1]*sf1 + ps1;
        #pragma unroll
        for (int nt = 0; nt < 8; nt++) {
            O[nt][0] *= sf0; O[nt][1] *= sf0;
            O[nt][2] *= sf1; O[nt][3] *= sf1;
        }
        __syncwarp();

        // ---- O += P @ V ----
        #pragma unroll
        for (int ks = 0; ks < 4; ks++) {
            uint32_t ph4[4], pl4[4];
            ldsm4(ph4[0], ph4[1], ph4[2], ph4[3], sb + wscr + W_PH + poff + ks*32);
            ldsm4(pl4[0], pl4[1], pl4[2], pl4[3], sb + wscr + W_PL + poff + ks*32);
            #pragma unroll
            for (int p = 0; p < 4; p++) {
                uint32_t vh4[4], vl4[4];
                const uint32_t va = stg + S_VH + voff + (uint32_t)(ks*16)*ASTR + p*32;
                ldsm4t(vh4[0], vh4[1], vh4[2], vh4[3], va);
                ldsm4t(vl4[0], vl4[1], vl4[2], vl4[3], va + (S_VL - S_VH));
                mma16816(O[2*p],   ph4, vh4);   mma16816(O[2*p],   ph4, vl4);
                mma16816(O[2*p],   pl4, vh4);
                mma16816(O[2*p+1], ph4, vh4+2); mma16816(O[2*p+1], ph4, vl4+2);
                mma16816(O[2*p+1], pl4, vh4+2);
            }
        }
    }

    // ---- epilogue: normalize + split store ----
    const float inv0 = 1.0f / l_i[0], inv1 = 1.0f / l_i[1];
    #pragma unroll
    for (int nt = 0; nt < 8; nt++) {
        const int c = nt*8 + ec;
        const size_t g0 = (size_t)(b*QL + ig0)*EE + h*DH + c;
        const size_t g1 = (size_t)(b*QL + ig1)*EE + h*DH + c;
        bf16 h0,l0,h1,l1;
        __nv_bfloat162 hp, lp;
        split2(O[nt][0]*inv0, h0, l0); split2(O[nt][1]*inv0, h1, l1);
        hp.x=h0; hp.y=h1; lp.x=l0; lp.y=l1;
        *(__nv_bfloat162*)(OHp + g0) = hp;
        *(__nv_bfloat162*)(OLp + g0) = lp;
        split2(O[nt][2]*inv1, h0, l0); split2(O[nt][3]*inv1, h1, l1);
        hp.x=h0; hp.y=h1; lp.x=l0; lp.y=l1;
        *(__nv_bfloat162*)(OHp + g1) = hp;
        *(__nv_bfloat162*)(OLp + g1) = lp;
    }
}

// ---------------- residual add + LayerNorm ----------------------------------
template<int WB>
__global__ __launch_bounds__(256) void add_ln_kernel(
    const float* __restrict__ a, const float* __restrict__ res,
    const float* __restrict__ g, const float* __restrict__ bt,
    float* __restrict__ out, bf16* __restrict__ oh, bf16* __restrict__ ol)
{
    __shared__ float red[256];
    const int row = blockIdx.x;
    const int tid = threadIdx.x;
    const size_t base = (size_t)row * EE;

    float v[4];
    #pragma unroll
    for (int u = 0; u < 4; u++)
        v[u] = a[base + u*256 + tid] + res[base + u*256 + tid];

    float s = v[0] + v[1] + v[2] + v[3];
    red[tid] = s; __syncthreads();
    for (int off = 128; off > 0; off >>= 1) {
        if (tid < off) red[tid] += red[tid + off];
        __syncthreads();
    }
    const float mu = red[0] * (1.0f / EE);
    __syncthreads();

    float d = 0.f;
    #pragma unroll
    for (int u = 0; u < 4; u++) { float t = v[u] - mu; d += t*t; }
    red[tid] = d; __syncthreads();
    for (int off = 128; off > 0; off >>= 1) {
        if (tid < off) red[tid] += red[tid + off];
        __syncthreads();
    }
    const float rs = rsqrtf(red[0] * (1.0f / EE) + 1e-3f);

    #pragma unroll
    for (int u = 0; u < 4; u++) {
        int c = u*256 + tid;
        float o = (v[u] - mu) * rs * g[c] + bt[c];
        out[base + c] = o;
        if (WB) {
            bf16 hh_, ll_; split2(o, hh_, ll_);
            oh[base + c] = hh_; ol[base + c] = ll_;
        }
    }
}

// ---------------- launch ----------------------------------------------------
extern "C" void kernel_launch(void* const* d_in, const int* in_sizes, int n_in,
                              void* d_out, int out_size)
{
    const float* w      = (const float*)d_in[0];
    const float* r      = (const float*)d_in[1];
    const float* member = (const float*)d_in[2];
    const float* Wq     = (const float*)d_in[4];
    const float* Wk     = (const float*)d_in[5];
    const float* Wv     = (const float*)d_in[6];
    const float* Wr     = (const float*)d_in[7];
    const float* Wo     = (const float*)d_in[8];
    const float* rwb    = (const float*)d_in[9];
    const float* rrb    = (const float*)d_in[10];
    const float* ln1g   = (const float*)d_in[11];
    const float* ln1b   = (const float*)d_in[12];
    const float* W1     = (const float*)d_in[13];
    const float* W2     = (const float*)d_in[14];
    const float* ln2g   = (const float*)d_in[15];
    const float* ln2b   = (const float*)d_in[16];
    float* out = (float*)d_out;

    float *ao,*x,*y;
    cudaGetSymbolAddress((void**)&ao, g_ao);
    cudaGetSymbolAddress((void**)&x,  g_x);
    cudaGetSymbolAddress((void**)&y,  g_y);
    bf16 *cath,*catl,*rih,*ril,*atth,*attl,*xh,*xl,*hhh,*hhl;
    bf16 *qph,*qpl,*kph,*kpl,*vph,*vpl,*rph,*rpl;
    bf16 *wqh,*wql,*wkh,*wkl,*wvh,*wvl,*wrh,*wrl,*woh,*wol,*w1h,*w1l,*w2h,*w2l;
    cudaGetSymbolAddress((void**)&cath, g_cat_h); cudaGetSymbolAddress((void**)&catl, g_cat_l);
    cudaGetSymbolAddress((void**)&rih,  g_r_h);   cudaGetSymbolAddress((void**)&ril,  g_r_l);
    cudaGetSymbolAddress((void**)&qph,  g_q_h);   cudaGetSymbolAddress((void**)&qpl,  g_q_l);
    cudaGetSymbolAddress((void**)&kph,  g_k_h);   cudaGetSymbolAddress((void**)&kpl,  g_k_l);
    cudaGetSymbolAddress((void**)&vph,  g_v_h);   cudaGetSymbolAddress((void**)&vpl,  g_v_l);
    cudaGetSymbolAddress((void**)&rph,  g_rpj_h); cudaGetSymbolAddress((void**)&rpl,  g_rpj_l);
    cudaGetSymbolAddress((void**)&atth, g_att_h); cudaGetSymbolAddress((void**)&attl, g_att_l);
    cudaGetSymbolAddress((void**)&xh,   g_x_h);   cudaGetSymbolAddress((void**)&xl,   g_x_l);
    cudaGetSymbolAddress((void**)&hhh,  g_hh_h);  cudaGetSymbolAddress((void**)&hhl,  g_hh_l);
    cudaGetSymbolAddress((void**)&wqh,  g_Wq_h);  cudaGetSymbolAddress((void**)&wql,  g_Wq_l);
    cudaGetSymbolAddress((void**)&wkh,  g_Wk_h);  cudaGetSymbolAddress((void**)&wkl,  g_Wk_l);
    cudaGetSymbolAddress((void**)&wvh,  g_Wv_h);  cudaGetSymbolAddress((void**)&wvl,  g_Wv_l);
    cudaGetSymbolAddress((void**)&wrh,  g_Wr_h);  cudaGetSymbolAddress((void**)&wrl,  g_Wr_l);
    cudaGetSymbolAddress((void**)&woh,  g_Wo_h);  cudaGetSymbolAddress((void**)&wol,  g_Wo_l);
    cudaGetSymbolAddress((void**)&w1h,  g_W1_h);  cudaGetSymbolAddress((void**)&w1l,  g_W1_l);
    cudaGetSymbolAddress((void**)&w2h,  g_W2_h);  cudaGetSymbolAddress((void**)&w2l,  g_W2_l);

    cudaFuncSetAttribute((const void*)mma_gemm<0,0>, cudaFuncAttributeMaxDynamicSharedMemorySize, GSM_TOTAL);
    cudaFuncSetAttribute((const void*)mma_gemm<1,0>, cudaFuncAttributeMaxDynamicSharedMemorySize, GSM_TOTAL);
    cudaFuncSetAttribute((const void*)mma_gemm<2,0>, cudaFuncAttributeMaxDynamicSharedMemorySize, GSM_TOTAL);
    cudaFuncSetAttribute((const void*)mma_gemm<2,1>, cudaFuncAttributeMaxDynamicSharedMemorySize, GSM_TOTAL);
    cudaFuncSetAttribute((const void*)attn_mma_kernel, cudaFuncAttributeMaxDynamicSharedMemorySize, A_TOT);

    // input conversions
    concat_convert_kernel<<<BB*KL*EE/4/256, 256>>>(member, w, cath, catl);
    convert_split_kernel <<<KL*EE/4/256,    256>>>(r, rih, ril);
    {
        TC5 p;
        p.s[0]=Wq; p.dh[0]=wqh; p.dl[0]=wql;
        p.s[1]=Wk; p.dh[1]=wkh; p.dl[1]=wkl;
        p.s[2]=Wv; p.dh[2]=wvh; p.dl[2]=wvl;
        p.s[3]=Wr; p.dh[3]=wrh; p.dl[3]=wrl;
        p.s[4]=Wo; p.dh[4]=woh; p.dl[4]=wol;
        transpose_convert5_kernel<<<dim3(EE/32, EE/32, 5), dim3(32,8)>>>(p);
    }
    transpose_convert_kernel<<<dim3(FF/32, EE/32), dim3(32,8)>>>(W1, w1h, w1l, EE, FF);
    transpose_convert_kernel<<<dim3(EE/32, FF/32), dim3(32,8)>>>(W2, w2h, w2l, FF, EE);

    // projections (split bf16 outputs); Q reads cat with row remap
    mma_gemm<2,0><<<dim3(EE/128, (BB*KL)/128), 256, GSM_TOTAL>>>(
        cath, catl, wkh, wkl, nullptr, kph, kpl, BB*KL, EE, EE);
    mma_gemm<2,0><<<dim3(EE/128, (BB*KL)/128), 256, GSM_TOTAL>>>(
        cath, catl, wvh, wvl, nullptr, vph, vpl, BB*KL, EE, EE);
    mma_gemm<2,1><<<dim3(EE/128, (BB*QL)/128), 256, GSM_TOTAL>>>(
        cath, catl, wqh, wql, nullptr, qph, qpl, BB*QL, EE, EE);
    mma_gemm<2,0><<<dim3(EE/128, KL/128), 256, GSM_TOTAL>>>(
        rih, ril, wrh, wrl, nullptr, rph, rpl, KL, EE, EE);

    // fused MMA attention (cp.async pipelined, rolling BDW)
    attn_mma_kernel<<<dim3(QL/64, HH, BB), 128, A_TOT>>>(
        qph, qpl, kph, kpl, vph, vpl, rph, rpl, rwb, rrb, atth, attl);

    // output projection + LN1
    mma_gemm<0,0><<<dim3(EE/128, (BB*QL)/128), 256, GSM_TOTAL>>>(
        atth, attl, woh, wol, ao, nullptr, nullptr, BB*QL, EE, EE);
    add_ln_kernel<1><<<BB*QL, 256>>>(ao, w, ln1g, ln1b, x, xh, xl);

    // FFN + LN2
    mma_gemm<1,0><<<dim3(FF/128, (BB*QL)/128), 256, GSM_TOTAL>>>(
        xh, xl, w1h, w1l, nullptr, hhh, hhl, BB*QL, FF, EE);
    mma_gemm<0,0><<<dim3(EE/128, (BB*QL)/128), 256, GSM_TOTAL>>>(
        hhh, hhl, w2h, w2l, y, nullptr, nullptr, BB*QL, EE, FF);
    add_ln_kernel<0><<<BB*QL, 256>>>(y, x, ln2g, ln2b, out, nullptr, nullptr);
}

// round 11
// speedup vs baseline: 5.4778x; 1.0304x over previous
#include <cuda_runtime.h>
#include <cuda_bf16.h>
#include <math.h>
#include <stdint.h>

#define BB 2
#define QL 1024
#define ML 1024
#define KL 2048
#define EE 1024
#define HH 16
#define DH 64
#define FF 4096

typedef __nv_bfloat16 bf16;

// ---------------- scratch (static device globals) ---------------------------
__device__ float g_ao [BB*QL*EE];
__device__ float g_x  [BB*QL*EE];
__device__ float g_y  [BB*QL*EE];

__device__ bf16 g_cat_h[BB*KL*EE], g_cat_l[BB*KL*EE];
__device__ bf16 g_r_h  [KL*EE],    g_r_l  [KL*EE];
__device__ bf16 g_q_h  [BB*QL*EE], g_q_l  [BB*QL*EE];
__device__ bf16 g_k_h  [BB*KL*EE], g_k_l  [BB*KL*EE];
__device__ bf16 g_v_h  [BB*KL*EE], g_v_l  [BB*KL*EE];
__device__ bf16 g_rpj_h[KL*EE],    g_rpj_l[KL*EE];
__device__ bf16 g_att_h[BB*QL*EE], g_att_l[BB*QL*EE];
__device__ bf16 g_x_h  [BB*QL*EE], g_x_l  [BB*QL*EE];
__device__ bf16 g_hh_h [BB*QL*FF], g_hh_l [BB*QL*FF];
__device__ bf16 g_Wq_h[EE*EE], g_Wq_l[EE*EE];
__device__ bf16 g_Wk_h[EE*EE], g_Wk_l[EE*EE];
__device__ bf16 g_Wv_h[EE*EE], g_Wv_l[EE*EE];
__device__ bf16 g_Wr_h[EE*EE], g_Wr_l[EE*EE];
__device__ bf16 g_Wo_h[EE*EE], g_Wo_l[EE*EE];
__device__ bf16 g_W1_h[FF*EE], g_W1_l[FF*EE];
__device__ bf16 g_W2_h[EE*FF], g_W2_l[EE*FF];

// ---------------- persistent streams/events (host-side, created pre-run) ----
struct StreamSet {
    cudaStream_t s1, s2, s3;
    cudaEvent_t e0, eCat, eW, eV, eQ, eRg, eW12;
    StreamSet() {
        cudaStreamCreateWithFlags(&s1, cudaStreamNonBlocking);
        cudaStreamCreateWithFlags(&s2, cudaStreamNonBlocking);
        cudaStreamCreateWithFlags(&s3, cudaStreamNonBlocking);
        cudaEventCreateWithFlags(&e0,   cudaEventDisableTiming);
        cudaEventCreateWithFlags(&eCat, cudaEventDisableTiming);
        cudaEventCreateWithFlags(&eW,   cudaEventDisableTiming);
        cudaEventCreateWithFlags(&eV,   cudaEventDisableTiming);
        cudaEventCreateWithFlags(&eQ,   cudaEventDisableTiming);
        cudaEventCreateWithFlags(&eRg,  cudaEventDisableTiming);
        cudaEventCreateWithFlags(&eW12, cudaEventDisableTiming);
    }
};
static StreamSet g_ss;

// ---------------- helpers ----------------------------------------------------
__device__ __forceinline__ uint32_t smem_u32(const void* p) {
    uint32_t a;
    asm("{ .reg .u64 t; cvta.to.shared.u64 t, %1; cvt.u32.u64 %0, t; }"
        : "=r"(a) : "l"(p));
    return a;
}
__device__ __forceinline__ void split2(float v, bf16& h, bf16& l) {
    h = __float2bfloat16(v);
    l = __float2bfloat16(v - __bfloat162float(h));
}
__device__ __forceinline__ void ldsm4(uint32_t& r0, uint32_t& r1,
                                      uint32_t& r2, uint32_t& r3, uint32_t addr) {
    asm volatile("ldmatrix.sync.aligned.m8n8.x4.shared.b16 {%0,%1,%2,%3}, [%4];"
        : "=r"(r0), "=r"(r1), "=r"(r2), "=r"(r3) : "r"(addr));
}
__device__ __forceinline__ void ldsm4t(uint32_t& r0, uint32_t& r1,
                                       uint32_t& r2, uint32_t& r3, uint32_t addr) {
    asm volatile("ldmatrix.sync.aligned.m8n8.x4.trans.shared.b16 {%0,%1,%2,%3}, [%4];"
        : "=r"(r0), "=r"(r1), "=r"(r2), "=r"(r3) : "r"(addr));
}
__device__ __forceinline__ void mma16816(float* d, const uint32_t* a, const uint32_t* b) {
    asm volatile(
        "mma.sync.aligned.m16n8k16.row.col.f32.bf16.bf16.f32 "
        "{%0,%1,%2,%3}, {%4,%5,%6,%7}, {%8,%9}, {%0,%1,%2,%3};"
        : "+f"(d[0]), "+f"(d[1]), "+f"(d[2]), "+f"(d[3])
        : "r"(a[0]), "r"(a[1]), "r"(a[2]), "r"(a[3]), "r"(b[0]), "r"(b[1]));
}
__device__ __forceinline__ void cpa16(uint32_t d, const void* s) {
    asm volatile("cp.async.cg.shared.global [%0], [%1], 16;" :: "r"(d), "l"(s));
}
__device__ __forceinline__ void cpa16z(uint32_t d, const void* s, int sz) {
    asm volatile("cp.async.cg.shared.global [%0], [%1], 16, %2;"
                 :: "r"(d), "l"(s), "r"(sz));
}
#define CPA_COMMIT() asm volatile("cp.async.commit_group;")
template<int N> __device__ __forceinline__ void cpa_wait() {
    asm volatile("cp.async.wait_group %0;" :: "n"(N));
}

// ---------------- conversion kernels ----------------------------------------
__global__ __launch_bounds__(256) void concat_convert_kernel(
    const float* __restrict__ member, const float* __restrict__ w,
    bf16* __restrict__ dh, bf16* __restrict__ dl)
{
    int idx = blockIdx.x * 256 + threadIdx.x;
    int fidx = idx * 4;
    int b   = fidx / (KL*EE);
    int rem = fidx % (KL*EE);
    int s   = rem / EE;
    int e   = rem % EE;
    float4 v;
    if (s < ML) v = *(const float4*)&member[(size_t)(b*ML + s)*EE + e];
    else        v = *(const float4*)&w[(size_t)(b*QL + (s-ML))*EE + e];
    bf16 h0,l0,h1,l1,h2,l2,h3,l3;
    split2(v.x,h0,l0); split2(v.y,h1,l1); split2(v.z,h2,l2); split2(v.w,h3,l3);
    __nv_bfloat162 hp0, hp1, lp0, lp1;
    hp0.x=h0; hp0.y=h1; hp1.x=h2; hp1.y=h3;
    lp0.x=l0; lp0.y=l1; lp1.x=l2; lp1.y=l3;
    ((__nv_bfloat162*)dh)[idx*2]   = hp0; ((__nv_bfloat162*)dh)[idx*2+1] = hp1;
    ((__nv_bfloat162*)dl)[idx*2]   = lp0; ((__nv_bfloat162*)dl)[idx*2+1] = lp1;
}

__global__ __launch_bounds__(256) void convert_split_kernel(
    const float* __restrict__ s, bf16* __restrict__ dh, bf16* __restrict__ dl)
{
    int idx = blockIdx.x * 256 + threadIdx.x;
    float4 v = ((const float4*)s)[idx];
    bf16 h0,l0,h1,l1,h2,l2,h3,l3;
    split2(v.x,h0,l0); split2(v.y,h1,l1); split2(v.z,h2,l2); split2(v.w,h3,l3);
    __nv_bfloat162 hp0, hp1, lp0, lp1;
    hp0.x=h0; hp0.y=h1; hp1.x=h2; hp1.y=h3;
    lp0.x=l0; lp0.y=l1; lp1.x=l2; lp1.y=l3;
    ((__nv_bfloat162*)dh)[idx*2]   = hp0; ((__nv_bfloat162*)dh)[idx*2+1] = hp1;
    ((__nv_bfloat162*)dl)[idx*2]   = lp0; ((__nv_bfloat162*)dl)[idx*2+1] = lp1;
}

struct TC5 { const float* s[5]; bf16* dh[5]; bf16* dl[5]; };

__global__ void transpose_convert5_kernel(TC5 p)   // 5x square EExEE
{
    __shared__ float t[32][33];
    const float* s = p.s[blockIdx.z];
    bf16* dh = p.dh[blockIdx.z];
    bf16* dl = p.dl[blockIdx.z];
    int n0 = blockIdx.x * 32, k0 = blockIdx.y * 32;
    int tx = threadIdx.x, ty = threadIdx.y;
    #pragma unroll
    for (int i = 0; i < 4; i++)
        t[ty + i*8][tx] = s[(size_t)(k0 + ty + i*8)*EE + n0 + tx];
    __syncthreads();
    #pragma unroll
    for (int i = 0; i < 4; i++) {
        float v = t[tx][ty + i*8];
        bf16 h, l; split2(v, h, l);
        size_t o = (size_t)(n0 + ty + i*8)*EE + k0 + tx;
        dh[o] = h; dl[o] = l;
    }
}

__global__ void transpose_convert_kernel(
    const float* __restrict__ s, bf16* __restrict__ dh, bf16* __restrict__ dl,
    int K, int N)
{
    __shared__ float t[32][33];
    int n0 = blockIdx.x * 32, k0 = blockIdx.y * 32;
    int tx = threadIdx.x, ty = threadIdx.y;
    #pragma unroll
    for (int i = 0; i < 4; i++)
        t[ty + i*8][tx] = s[(size_t)(k0 + ty + i*8)*N + n0 + tx];
    __syncthreads();
    #pragma unroll
    for (int i = 0; i < 4; i++) {
        float v = t[tx][ty + i*8];
        bf16 h, l; split2(v, h, l);
        size_t o = (size_t)(n0 + ty + i*8)*K + k0 + tx;
        dh[o] = h; dl[o] = l;
    }
}

// ---------------- bf16x3 warp-MMA GEMM (cp.async double-buffered) -----------
#define SROW     40
#define OPELEMS  (128*SROW)
#define OPBYTES  (OPELEMS*2)
#define BUFELEMS (4*OPELEMS)
#define BUFBYTES (BUFELEMS*2)
#define GSM_TOTAL (2*BUFBYTES)

// EPI: 0 = fp32 store, 1 = relu + split bf16, 2 = split bf16
// REMAP: A rows remapped grow -> (grow/QL)*KL + ML + grow%QL  (Q-from-cat)
template<int EPI, int REMAP>
__global__ __launch_bounds__(256, 2) void mma_gemm(
    const bf16* __restrict__ Ah, const bf16* __restrict__ Al,
    const bf16* __restrict__ Bh, const bf16* __restrict__ Bl,
    float* __restrict__ Cf, bf16* __restrict__ Ch, bf16* __restrict__ Cl,
    int M, int N, int K)
{
    extern __shared__ bf16 smem[];
    const int tid = threadIdx.x, wid = tid >> 5, lane = tid & 31;
    const int row0 = blockIdx.y * 128, col0 = blockIdx.x * 128;
    const int wm = wid & 1, wn = wid >> 1;
    const uint32_t sbase0 = smem_u32(smem);

    float acc[4][4][4];
    #pragma unroll
    for (int mt = 0; mt < 4; mt++)
        #pragma unroll
        for (int nt = 0; nt < 4; nt++)
            #pragma unroll
            for (int u = 0; u < 4; u++) acc[mt][nt][u] = 0.f;

    const int nc = K >> 5;
    const int r0q = tid >> 2, c0q = (tid & 3) * 8;
    const int r1q = r0q + 64;

    size_t aR0, aR1;
    if (REMAP) {
        const int g0 = row0 + r0q, g1 = row0 + r1q;
        aR0 = ((size_t)(g0 >> 10)*KL + ML + (g0 & 1023)) * (size_t)K;
        aR1 = ((size_t)(g1 >> 10)*KL + ML + (g1 & 1023)) * (size_t)K;
    } else {
        aR0 = (size_t)(row0 + r0q) * K;
        aR1 = (size_t)(row0 + r1q) * K;
    }
    const size_t bR0 = (size_t)(col0 + r0q) * K;
    const size_t bR1 = (size_t)(col0 + r1q) * K;
    const uint32_t s0b = (uint32_t)(r0q*80 + c0q*2);
    const uint32_t s1b = (uint32_t)(r1q*80 + c0q*2);

    auto issue = [&](int c) {
        const uint32_t d = sbase0 + (uint32_t)(c & 1) * BUFBYTES;
        const size_t k0 = (size_t)(c * 32) + c0q;
        cpa16(d + s0b,             Ah + aR0 + k0);
        cpa16(d + s0b + OPBYTES,   Al + aR0 + k0);
        cpa16(d + s0b + 2*OPBYTES, Bh + bR0 + k0);
        cpa16(d + s0b + 3*OPBYTES, Bl + bR0 + k0);
        cpa16(d + s1b,             Ah + aR1 + k0);
        cpa16(d + s1b + OPBYTES,   Al + aR1 + k0);
        cpa16(d + s1b + 2*OPBYTES, Bh + bR1 + k0);
        cpa16(d + s1b + 3*OPBYTES, Bl + bR1 + k0);
        CPA_COMMIT();
    };

    issue(0);

    const uint32_t a_row_off = (uint32_t)(wm*64 + (lane & 15)) * 80
                             + (uint32_t)(lane >> 4) * 16;
    const uint32_t b_row_off = 2*OPBYTES
                             + (uint32_t)(wn*32 + (lane & 7) + ((lane >> 4) & 1)*8) * 80
                             + (uint32_t)((lane >> 3) & 1) * 16;

    for (int c = 0; c < nc; c++) {
        cpa_wait<0>();
        __syncthreads();
        if (c + 1 < nc) issue(c + 1);

        const uint32_t sb = sbase0 + (uint32_t)(c & 1) * BUFBYTES;
        #pragma unroll
        for (int ks = 0; ks < 2; ks++) {
            uint32_t ah[4][4], al[4][4], bh[4][2], bl[4][2];
            const uint32_t abase = sb + a_row_off + ks*32;
            #pragma unroll
            for (int mt = 0; mt < 4; mt++) {
                const uint32_t ad = abase + mt*(16*80);
                ldsm4(ah[mt][0], ah[mt][1], ah[mt][2], ah[mt][3], ad);
                ldsm4(al[mt][0], al[mt][1], al[mt][2], al[mt][3], ad + OPBYTES);
            }
            const uint32_t bbase = sb + b_row_off + ks*32;
            #pragma unroll
            for (int p = 0; p < 2; p++) {
                const uint32_t bd = bbase + p*(16*80);
                ldsm4(bh[2*p][0], bh[2*p][1], bh[2*p+1][0], bh[2*p+1][1], bd);
                ldsm4(bl[2*p][0], bl[2*p][1], bl[2*p+1][0], bl[2*p+1][1], bd + OPBYTES);
            }
            #pragma unroll
            for (int mt = 0; mt < 4; mt++)
                #pragma unroll
                for (int nt = 0; nt < 4; nt++) {
                    mma16816(acc[mt][nt], ah[mt], bh[nt]);
                    mma16816(acc[mt][nt], ah[mt], bl[nt]);
                    mma16816(acc[mt][nt], al[mt], bh[nt]);
                }
        }
    }

    const int er = lane >> 2, ec = (lane & 3) * 2;
    #pragma unroll
    for (int mt = 0; mt < 4; mt++) {
        #pragma unroll
        for (int nt = 0; nt < 4; nt++) {
            const int grow = row0 + wm*64 + mt*16 + er;
            const int gcol = col0 + wn*32 + nt*8 + ec;
            if (EPI == 0) {
                *(float2*)&Cf[(size_t)grow*N + gcol] =
                    make_float2(acc[mt][nt][0], acc[mt][nt][1]);
                *(float2*)&Cf[(size_t)(grow+8)*N + gcol] =
                    make_float2(acc[mt][nt][2], acc[mt][nt][3]);
            } else {
                float f0 = acc[mt][nt][0], f1 = acc[mt][nt][1];
                float f2 = acc[mt][nt][2], f3 = acc[mt][nt][3];
                if (EPI == 1) {
                    f0 = fmaxf(f0, 0.f); f1 = fmaxf(f1, 0.f);
                    f2 = fmaxf(f2, 0.f); f3 = fmaxf(f3, 0.f);
                }
                bf16 h0,l0,h1,l1,h2,l2,h3,l3;
                split2(f0,h0,l0); split2(f1,h1,l1);
                split2(f2,h2,l2); split2(f3,h3,l3);
                __nv_bfloat162 hp0, lp0, hp1, lp1;
                hp0.x=h0; hp0.y=h1; lp0.x=l0; lp0.y=l1;
                hp1.x=h2; hp1.y=h3; lp1.x=l2; lp1.y=l3;
                *(__nv_bfloat162*)&Ch[(size_t)grow*N + gcol]     = hp0;
                *(__nv_bfloat162*)&Cl[(size_t)grow*N + gcol]     = lp0;
                *(__nv_bfloat162*)&Ch[(size_t)(grow+8)*N + gcol] = hp1;
                *(__nv_bfloat162*)&Cl[(size_t)(grow+8)*N + gcol] = lp1;
            }
        }
    }
}

// ---------------- MMA flash attention: cp.async pipeline + rolling BDW ------
#define ASTR 144
#define A_QWH 0
#define A_QWL 9216
#define A_QRH 18432
#define A_QRL 27648
#define A_STG 36864
#define S_KH  0
#define S_KL  9216
#define S_VH  18432
#define S_VL  27648
#define S_RH  36864
#define S_RL  46080
#define STG_SZ 55296
#define A_SCR (A_STG + 2*STG_SZ)       // 147456
#define W_BDW 0
#define W_PH  8448
#define W_PL  10752
#define WSCR_SZ 13056
#define A_TOT (A_SCR + 4*WSCR_SZ)      // 199680

// one 64-col BDW half: D = Qr @ Rstage^T, stored at phys cols [pb, pb+64)
__device__ __forceinline__ void bdw_half(
    char* sm, uint32_t sb, uint32_t rbase, int pb,
    uint32_t aoff, uint32_t boff, uint32_t wscr, int er, int ec)
{
    float D[8][4];
    #pragma unroll
    for (int nt = 0; nt < 8; nt++)
        #pragma unroll
        for (int u = 0; u < 4; u++) D[nt][u] = 0.f;
    #pragma unroll
    for (int ks = 0; ks < 4; ks++) {
        uint32_t arh[4], arl[4];
        ldsm4(arh[0], arh[1], arh[2], arh[3], sb + A_QRH + aoff + ks*32);
        ldsm4(arl[0], arl[1], arl[2], arl[3], sb + A_QRL + aoff + ks*32);
        #pragma unroll
        for (int p = 0; p < 4; p++) {
            uint32_t bh4[4], bl4[4];
            const uint32_t ra = rbase + boff + (uint32_t)(p*16)*ASTR + ks*32;
            ldsm4(bh4[0], bh4[1], bh4[2], bh4[3], ra);
            ldsm4(bl4[0], bl4[1], bl4[2], bl4[3], ra + (S_RL - S_RH));
            mma16816(D[2*p],   arh, bh4);   mma16816(D[2*p],   arh, bl4);
            mma16816(D[2*p],   arl, bh4);
            mma16816(D[2*p+1], arh, bh4+2); mma16816(D[2*p+1], arh, bl4+2);
            mma16816(D[2*p+1], arl, bh4+2);
        }
    }
    float* bdw = (float*)(sm + wscr + W_BDW);
    #pragma unroll
    for (int nt = 0; nt < 8; nt++) {
        const int c = pb + nt*8 + ec;
        bdw[er*132 + c]       = D[nt][0];
        bdw[er*132 + c + 1]   = D[nt][1];
        bdw[(er+8)*132 + c]   = D[nt][2];
        bdw[(er+8)*132 + c+1] = D[nt][3];
    }
}

__global__ __launch_bounds__(128) void attn_mma_kernel(
    const bf16* __restrict__ Qh, const bf16* __restrict__ Ql,
    const bf16* __restrict__ Kh, const bf16* __restrict__ Kl,
    const bf16* __restrict__ Vh, const bf16* __restrict__ Vl,
    const bf16* __restrict__ Rh, const bf16* __restrict__ Rl,
    const float* __restrict__ rwb, const float* __restrict__ rrb,
    bf16* __restrict__ OHp, bf16* __restrict__ OLp)
{
    extern __shared__ char sm[];
    const uint32_t sb = smem_u32(sm);
    const int i0 = blockIdx.x * 64;
    const int h  = blockIdx.y, b = blockIdx.z;
    const int tid = threadIdx.x, w = tid >> 5, lane = tid & 31;

    // ---- load Q, add biases, split, store both variants ----
    #pragma unroll
    for (int it = 0; it < 4; it++) {
        int idx = tid + it*128;
        int row = idx >> 3, c8 = (idx & 7) * 8;
        const size_t g = (size_t)(b*QL + i0 + row)*EE + h*DH + c8;
        union { uint4 u; bf16 e[8]; } uh, ul;
        uh.u = *(const uint4*)(Qh + g);
        ul.u = *(const uint4*)(Ql + g);
        bf16* qwh = (bf16*)(sm + A_QWH + row*ASTR) + c8;
        bf16* qwl = (bf16*)(sm + A_QWL + row*ASTR) + c8;
        bf16* qrh = (bf16*)(sm + A_QRH + row*ASTR) + c8;
        bf16* qrl = (bf16*)(sm + A_QRL + row*ASTR) + c8;
        #pragma unroll
        for (int e = 0; e < 8; e++) {
            float q = __bfloat162float(uh.e[e]) + __bfloat162float(ul.e[e]);
            bf16 hh, ll;
            split2(q + rwb[h*DH + c8 + e], hh, ll); qwh[e] = hh; qwl[e] = ll;
            split2(q + rrb[h*DH + c8 + e], hh, ll); qrh[e] = hh; qrl[e] = ll;
        }
    }

    float O[8][4];
    #pragma unroll
    for (int nt = 0; nt < 8; nt++)
        #pragma unroll
        for (int u = 0; u < 4; u++) O[nt][u] = 0.f;
    float m_i[2] = {-INFINITY, -INFINITY}, l_i[2] = {0.f, 0.f};

    const uint32_t aoff = (uint32_t)(w*16 + (lane&15))*ASTR + ((lane>>4)&1)*16;
    const uint32_t boff = (uint32_t)((lane&7) + ((lane>>4)&1)*8)*ASTR + ((lane>>3)&1)*16;
    const uint32_t voff = (uint32_t)((lane&7) + ((lane>>3)&1)*8)*ASTR + ((lane>>4)&1)*16;
    const uint32_t poff = (uint32_t)(lane&15)*ASTR + ((lane>>4)&1)*16;
    const uint32_t wscr = A_SCR + w*WSCR_SZ;
    const int er = lane >> 2, ec = (lane & 3) * 2;
    const int lr0 = w*16 + er, lr1 = lr0 + 8;
    const int ig0 = i0 + lr0, ig1 = i0 + lr1;

    int njt = (i0 + 63 + ML)/64 + 1;
    if (njt > KL/64) njt = KL/64;
    const int rorg = 960 - i0;   // absolute r-index of physical BDW slot 0

    const int ldrow = tid >> 3, ldc8 = (tid & 7) * 8;

    // ---- prologue: R_low -> stage1 R area; tile0 -> stage0 ----
    #pragma unroll
    for (int it = 0; it < 4; it++) {
        int row = ldrow + it*16;
        int dg = rorg + row;                           // >= 0 always (i0<=960)
        const size_t g = (size_t)dg*EE + h*DH + ldc8;
        uint32_t d = sb + A_STG + STG_SZ + S_RH + row*ASTR + ldc8*2;
        cpa16(d,                 Rh + g);
        cpa16(d + (S_RL - S_RH), Rl + g);
    }
    {
        const uint32_t stg = sb + A_STG;               // stage 0
        #pragma unroll
        for (int it = 0; it < 4; it++) {
            int row = ldrow + it*16;
            const size_t g = (size_t)(b*KL + row)*EE + h*DH + ldc8;
            const uint32_t so = row*ASTR + ldc8*2;
            cpa16(stg + S_KH + so, Kh + g);
            cpa16(stg + S_KL + so, Kl + g);
            cpa16(stg + S_VH + so, Vh + g);
            cpa16(stg + S_VL + so, Vl + g);
            int dg = rorg + 64 + row;
            int ok = dg < KL;
            const size_t gr = (size_t)(ok ? dg : 0)*EE + h*DH + ldc8;
            cpa16z(stg + S_RH + so, Rh + gr, ok ? 16 : 0);
            cpa16z(stg + S_RL + so, Rl + gr, ok ? 16 : 0);
        }
    }
    CPA_COMMIT();
    cpa_wait<0>();
    __syncthreads();

    // prologue BDW (phys cols [0,64), from stage1 R)
    bdw_half(sm, sb, sb + A_STG + STG_SZ + S_RH, 0, aoff, boff, wscr, er, ec);

    for (int jt = 0; jt < njt; jt++) {
        const int j0 = jt * 64;
        __syncthreads();                       // all warps done with jt-1 (+ prologue BDW)
        if (jt + 1 < njt) {
            const uint32_t stg = sb + A_STG + ((jt+1)&1)*STG_SZ;
            const int jn = (jt+1)*64;
            #pragma unroll
            for (int it = 0; it < 4; it++) {
                int row = ldrow + it*16;
                const size_t g = (size_t)(b*KL + jn + row)*EE + h*DH + ldc8;
                const uint32_t so = row*ASTR + ldc8*2;
                cpa16(stg + S_KH + so, Kh + g);
                cpa16(stg + S_KL + so, Kl + g);
                cpa16(stg + S_VH + so, Vh + g);
                cpa16(stg + S_VL + so, Vl + g);
                int dg = rorg + 64*(jt+2) + row;
                int ok = dg < KL;
                const size_t gr = (size_t)(ok ? dg : 0)*EE + h*DH + ldc8;
                cpa16z(stg + S_RH + so, Rh + gr, ok ? 16 : 0);
                cpa16z(stg + S_RL + so, Rl + gr, ok ? 16 : 0);
            }
            CPA_COMMIT();
            cpa_wait<1>();
        } else {
            cpa_wait<0>();
        }
        __syncthreads();

        const uint32_t stg = sb + A_STG + (jt&1)*STG_SZ;

        // ---- BDW new half (64 cols) -> phys base alternates 64/0 ----
        bdw_half(sm, sb, stg + S_RH, (jt&1) ? 0 : 64, aoff, boff, wscr, er, ec);

        // ---- AC = Qw @ K^T ----
        float S[8][4];
        #pragma unroll
        for (int nt = 0; nt < 8; nt++)
            #pragma unroll
            for (int u = 0; u < 4; u++) S[nt][u] = 0.f;
        #pragma unroll
        for (int ks = 0; ks < 4; ks++) {
            uint32_t awh[4], awl[4];
            ldsm4(awh[0], awh[1], awh[2], awh[3], sb + A_QWH + aoff + ks*32);
            ldsm4(awl[0], awl[1], awl[2], awl[3], sb + A_QWL + aoff + ks*32);
            #pragma unroll
            for (int p = 0; p < 4; p++) {
                uint32_t bh4[4], bl4[4];
                const uint32_t ka = stg + S_KH + boff + (uint32_t)(p*16)*ASTR + ks*32;
                ldsm4(bh4[0], bh4[1], bh4[2], bh4[3], ka);
                ldsm4(bl4[0], bl4[1], bl4[2], bl4[3], ka + (S_KL - S_KH));
                mma16816(S[2*p],   awh, bh4);   mma16816(S[2*p],   awh, bl4);
                mma16816(S[2*p],   awl, bh4);
                mma16816(S[2*p+1], awh, bh4+2); mma16816(S[2*p+1], awh, bl4+2);
                mma16816(S[2*p+1], awl, bh4+2);
            }
        }
        __syncwarp();

        // ---- gather rolling BDW diagonal, mask+scale, online softmax ----
        const float* bdw = (const float*)(sm + wscr + W_BDW);
        const int phase = (jt & 1) * 64;
        float mx0 = -INFINITY, mx1 = -INFINITY;
        #pragma unroll
        for (int nt = 0; nt < 8; nt++) {
            const int c = nt*8 + ec;
            float s00 = S[nt][0] + bdw[er*132     + ((c   - lr0 + 63 + phase) & 127)];
            float s01 = S[nt][1] + bdw[er*132     + ((c+1 - lr0 + 63 + phase) & 127)];
            float s10 = S[nt][2] + bdw[(er+8)*132 + ((c   - lr1 + 63 + phase) & 127)];
            float s11 = S[nt][3] + bdw[(er+8)*132 + ((c+1 - lr1 + 63 + phase) & 127)];
            const int jg = j0 + c;
            s00 = (jg   > ig0 + ML) ? -1e30f : s00 * 0.03125f;
            s01 = (jg+1 > ig0 + ML) ? -1e30f : s01 * 0.03125f;
            s10 = (jg   > ig1 + ML) ? -1e30f : s10 * 0.03125f;
            s11 = (jg+1 > ig1 + ML) ? -1e30f : s11 * 0.03125f;
            S[nt][0] = s00; S[nt][1] = s01; S[nt][2] = s10; S[nt][3] = s11;
            mx0 = fmaxf(mx0, fmaxf(s00, s01));
            mx1 = fmaxf(mx1, fmaxf(s10, s11));
        }
        mx0 = fmaxf(mx0, __shfl_xor_sync(0xffffffffu, mx0, 1));
        mx0 = fmaxf(mx0, __shfl_xor_sync(0xffffffffu, mx0, 2));
        mx1 = fmaxf(mx1, __shfl_xor_sync(0xffffffffu, mx1, 1));
        mx1 = fmaxf(mx1, __shfl_xor_sync(0xffffffffu, mx1, 2));
        const float mn0 = fmaxf(m_i[0], mx0), mn1 = fmaxf(m_i[1], mx1);
        const float sf0 = __expf(m_i[0] - mn0), sf1 = __expf(m_i[1] - mn1);
        m_i[0] = mn0; m_i[1] = mn1;

        bf16* pph = (bf16*)(sm + wscr + W_PH);
        bf16* ppl = (bf16*)(sm + wscr + W_PL);
        float ps0 = 0.f, ps1 = 0.f;
        #pragma unroll
        for (int nt = 0; nt < 8; nt++) {
            const int c = nt*8 + ec;
            float p00 = __expf(S[nt][0] - mn0);
            float p01 = __expf(S[nt][1] - mn0);
            float p10 = __expf(S[nt][2] - mn1);
            float p11 = __expf(S[nt][3] - mn1);
            ps0 += p00 + p01; ps1 += p10 + p11;
            bf16 h0,l0,h1,l1;
            __nv_bfloat162 hp, lp;
            split2(p00,h0,l0); split2(p01,h1,l1);
            hp.x=h0; hp.y=h1; lp.x=l0; lp.y=l1;
            *(__nv_bfloat162*)(pph + er*72 + c) = hp;
            *(__nv_bfloat162*)(ppl + er*72 + c) = lp;
            split2(p10,h0,l0); split2(p11,h1,l1);
            hp.x=h0; hp.y=h1; lp.x=l0; lp.y=l1;
            *(__nv_bfloat162*)(pph + (er+8)*72 + c) = hp;
            *(__nv_bfloat162*)(ppl + (er+8)*72 + c) = lp;
        }
        ps0 += __shfl_xor_sync(0xffffffffu, ps0, 1);
        ps0 += __shfl_xor_sync(0xffffffffu, ps0, 2);
        ps1 += __shfl_xor_sync(0xffffffffu, ps1, 1);
        ps1 += __shfl_xor_sync(0xffffffffu, ps1, 2);
        l_i[0] = l_i[0]*sf0 + ps0;
        l_i[1] = l_i[1]*sf1 + ps1;
        #pragma unroll
        for (int nt = 0; nt < 8; nt++) {
            O[nt][0] *= sf0; O[nt][1] *= sf0;
            O[nt][2] *= sf1; O[nt][3] *= sf1;
        }
        __syncwarp();

        // ---- O += P @ V ----
        #pragma unroll
        for (int ks = 0; ks < 4; ks++) {
            uint32_t ph4[4], pl4[4];
            ldsm4(ph4[0], ph4[1], ph4[2], ph4[3], sb + wscr + W_PH + poff + ks*32);
            ldsm4(pl4[0], pl4[1], pl4[2], pl4[3], sb + wscr + W_PL + poff + ks*32);
            #pragma unroll
            for (int p = 0; p < 4; p++) {
                uint32_t vh4[4], vl4[4];
                const uint32_t va = stg + S_VH + voff + (uint32_t)(ks*16)*ASTR + p*32;
                ldsm4t(vh4[0], vh4[1], vh4[2], vh4[3], va);
                ldsm4t(vl4[0], vl4[1], vl4[2], vl4[3], va + (S_VL - S_VH));
                mma16816(O[2*p],   ph4, vh4);   mma16816(O[2*p],   ph4, vl4);
                mma16816(O[2*p],   pl4, vh4);
                mma16816(O[2*p+1], ph4, vh4+2); mma16816(O[2*p+1], ph4, vl4+2);
                mma16816(O[2*p+1], pl4, vh4+2);
            }
        }
    }

    // ---- epilogue: normalize + split store ----
    const float inv0 = 1.0f / l_i[0], inv1 = 1.0f / l_i[1];
    #pragma unroll
    for (int nt = 0; nt < 8; nt++) {
        const int c = nt*8 + ec;
        const size_t g0 = (size_t)(b*QL + ig0)*EE + h*DH + c;
        const size_t g1 = (size_t)(b*QL + ig1)*EE + h*DH + c;
        bf16 h0,l0,h1,l1;
        __nv_bfloat162 hp, lp;
        split2(O[nt][0]*inv0, h0, l0); split2(O[nt][1]*inv0, h1, l1);
        hp.x=h0; hp.y=h1; lp.x=l0; lp.y=l1;
        *(__nv_bfloat162*)(OHp + g0) = hp;
        *(__nv_bfloat162*)(OLp + g0) = lp;
        split2(O[nt][2]*inv1, h0, l0); split2(O[nt][3]*inv1, h1, l1);
        hp.x=h0; hp.y=h1; lp.x=l0; lp.y=l1;
        *(__nv_bfloat162*)(OHp + g1) = hp;
        *(__nv_bfloat162*)(OLp + g1) = lp;
    }
}

// ---------------- residual add + LayerNorm ----------------------------------
template<int WB>
__global__ __launch_bounds__(256) void add_ln_kernel(
    const float* __restrict__ a, const float* __restrict__ res,
    const float* __restrict__ g, const float* __restrict__ bt,
    float* __restrict__ out, bf16* __restrict__ oh, bf16* __restrict__ ol)
{
    __shared__ float red[256];
    const int row = blockIdx.x;
    const int tid = threadIdx.x;
    const size_t base = (size_t)row * EE;

    float v[4];
    #pragma unroll
    for (int u = 0; u < 4; u++)
        v[u] = a[base + u*256 + tid] + res[base + u*256 + tid];

    float s = v[0] + v[1] + v[2] + v[3];
    red[tid] = s; __syncthreads();
    for (int off = 128; off > 0; off >>= 1) {
        if (tid < off) red[tid] += red[tid + off];
        __syncthreads();
    }
    const float mu = red[0] * (1.0f / EE);
    __syncthreads();

    float d = 0.f;
    #pragma unroll
    for (int u = 0; u < 4; u++) { float t = v[u] - mu; d += t*t; }
    red[tid] = d; __syncthreads();
    for (int off = 128; off > 0; off >>= 1) {
        if (tid < off) red[tid] += red[tid + off];
        __syncthreads();
    }
    const float rs = rsqrtf(red[0] * (1.0f / EE) + 1e-3f);

    #pragma unroll
    for (int u = 0; u < 4; u++) {
        int c = u*256 + tid;
        float o = (v[u] - mu) * rs * g[c] + bt[c];
        out[base + c] = o;
        if (WB) {
            bf16 hh_, ll_; split2(o, hh_, ll_);
            oh[base + c] = hh_; ol[base + c] = ll_;
        }
    }
}

// ---------------- launch ----------------------------------------------------
extern "C" void kernel_launch(void* const* d_in, const int* in_sizes, int n_in,
                              void* d_out, int out_size)
{
    const float* w      = (const float*)d_in[0];
    const float* r      = (const float*)d_in[1];
    const float* member = (const float*)d_in[2];
    const float* Wq     = (const float*)d_in[4];
    const float* Wk     = (const float*)d_in[5];
    const float* Wv     = (const float*)d_in[6];
    const float* Wr     = (const float*)d_in[7];
    const float* Wo     = (const float*)d_in[8];
    const float* rwb    = (const float*)d_in[9];
    const float* rrb    = (const float*)d_in[10];
    const float* ln1g   = (const float*)d_in[11];
    const float* ln1b   = (const float*)d_in[12];
    const float* W1     = (const float*)d_in[13];
    const float* W2     = (const float*)d_in[14];
    const float* ln2g   = (const float*)d_in[15];
    const float* ln2b   = (const float*)d_in[16];
    float* out = (float*)d_out;

    float *ao,*x,*y;
    cudaGetSymbolAddress((void**)&ao, g_ao);
    cudaGetSymbolAddress((void**)&x,  g_x);
    cudaGetSymbolAddress((void**)&y,  g_y);
    bf16 *cath,*catl,*rih,*ril,*atth,*attl,*xh,*xl,*hhh,*hhl;
    bf16 *qph,*qpl,*kph,*kpl,*vph,*vpl,*rph,*rpl;
    bf16 *wqh,*wql,*wkh,*wkl,*wvh,*wvl,*wrh,*wrl,*woh,*wol,*w1h,*w1l,*w2h,*w2l;
    cudaGetSymbolAddress((void**)&cath, g_cat_h); cudaGetSymbolAddress((void**)&catl, g_cat_l);
    cudaGetSymbolAddress((void**)&rih,  g_r_h);   cudaGetSymbolAddress((void**)&ril,  g_r_l);
    cudaGetSymbolAddress((void**)&qph,  g_q_h);   cudaGetSymbolAddress((void**)&qpl,  g_q_l);
    cudaGetSymbolAddress((void**)&kph,  g_k_h);   cudaGetSymbolAddress((void**)&kpl,  g_k_l);
    cudaGetSymbolAddress((void**)&vph,  g_v_h);   cudaGetSymbolAddress((void**)&vpl,  g_v_l);
    cudaGetSymbolAddress((void**)&rph,  g_rpj_h); cudaGetSymbolAddress((void**)&rpl,  g_rpj_l);
    cudaGetSymbolAddress((void**)&atth, g_att_h); cudaGetSymbolAddress((void**)&attl, g_att_l);
    cudaGetSymbolAddress((void**)&xh,   g_x_h);   cudaGetSymbolAddress((void**)&xl,   g_x_l);
    cudaGetSymbolAddress((void**)&hhh,  g_hh_h);  cudaGetSymbolAddress((void**)&hhl,  g_hh_l);
    cudaGetSymbolAddress((void**)&wqh,  g_Wq_h);  cudaGetSymbolAddress((void**)&wql,  g_Wq_l);
    cudaGetSymbolAddress((void**)&wkh,  g_Wk_h);  cudaGetSymbolAddress((void**)&wkl,  g_Wk_l);
    cudaGetSymbolAddress((void**)&wvh,  g_Wv_h);  cudaGetSymbolAddress((void**)&wvl,  g_Wv_l);
    cudaGetSymbolAddress((void**)&wrh,  g_Wr_h);  cudaGetSymbolAddress((void**)&wrl,  g_Wr_l);
    cudaGetSymbolAddress((void**)&woh,  g_Wo_h);  cudaGetSymbolAddress((void**)&wol,  g_Wo_l);
    cudaGetSymbolAddress((void**)&w1h,  g_W1_h);  cudaGetSymbolAddress((void**)&w1l,  g_W1_l);
    cudaGetSymbolAddress((void**)&w2h,  g_W2_h);  cudaGetSymbolAddress((void**)&w2l,  g_W2_l);

    cudaFuncSetAttribute((const void*)mma_gemm<0,0>, cudaFuncAttributeMaxDynamicSharedMemorySize, GSM_TOTAL);
    cudaFuncSetAttribute((const void*)mma_gemm<1,0>, cudaFuncAttributeMaxDynamicSharedMemorySize, GSM_TOTAL);
    cudaFuncSetAttribute((const void*)mma_gemm<2,0>, cudaFuncAttributeMaxDynamicSharedMemorySize, GSM_TOTAL);
    cudaFuncSetAttribute((const void*)mma_gemm<2,1>, cudaFuncAttributeMaxDynamicSharedMemorySize, GSM_TOTAL);
    cudaFuncSetAttribute((const void*)attn_mma_kernel, cudaFuncAttributeMaxDynamicSharedMemorySize, A_TOT);

    cudaStream_t s1 = g_ss.s1, s2 = g_ss.s2, s3 = g_ss.s3;

    // fork side streams into the capture
    cudaEventRecord(g_ss.e0, 0);
    cudaStreamWaitEvent(s1, g_ss.e0, 0);
    cudaStreamWaitEvent(s2, g_ss.e0, 0);
    cudaStreamWaitEvent(s3, g_ss.e0, 0);

    // stream 0: concat conversion
    concat_convert_kernel<<<BB*KL*EE/4/256, 256>>>(member, w, cath, catl);
    cudaEventRecord(g_ss.eCat, 0);

    // s1: square weight transposes
    {
        TC5 p;
        p.s[0]=Wq; p.dh[0]=wqh; p.dl[0]=wql;
        p.s[1]=Wk; p.dh[1]=wkh; p.dl[1]=wkl;
        p.s[2]=Wv; p.dh[2]=wvh; p.dl[2]=wvl;
        p.s[3]=Wr; p.dh[3]=wrh; p.dl[3]=wrl;
        p.s[4]=Wo; p.dh[4]=woh; p.dl[4]=wol;
        transpose_convert5_kernel<<<dim3(EE/32, EE/32, 5), dim3(32,8), 0, s1>>>(p);
    }
    cudaEventRecord(g_ss.eW, s1);

    // s2: r conversion, then FFN weight transposes
    convert_split_kernel<<<KL*EE/4/256, 256, 0, s2>>>(r, rih, ril);
    transpose_convert_kernel<<<dim3(FF/32, EE/32), dim3(32,8), 0, s2>>>(W1, w1h, w1l, EE, FF);
    transpose_convert_kernel<<<dim3(EE/32, FF/32), dim3(32,8), 0, s2>>>(W2, w2h, w2l, FF, EE);
    cudaEventRecord(g_ss.eW12, s2);

    // projections spread over 4 streams
    cudaStreamWaitEvent(0, g_ss.eW, 0);
    mma_gemm<2,0><<<dim3(EE/128, (BB*KL)/128), 256, GSM_TOTAL>>>(
        cath, catl, wkh, wkl, nullptr, kph, kpl, BB*KL, EE, EE);

    cudaStreamWaitEvent(s1, g_ss.eCat, 0);
    mma_gemm<2,0><<<dim3(EE/128, (BB*KL)/128), 256, GSM_TOTAL, s1>>>(
        cath, catl, wvh, wvl, nullptr, vph, vpl, BB*KL, EE, EE);
    cudaEventRecord(g_ss.eV, s1);

    cudaStreamWaitEvent(s3, g_ss.eCat, 0);
    cudaStreamWaitEvent(s3, g_ss.eW, 0);
    mma_gemm<2,1><<<dim3(EE/128, (BB*QL)/128), 256, GSM_TOTAL, s3>>>(
        cath, catl, wqh, wql, nullptr, qph, qpl, BB*QL, EE, EE);
    cudaEventRecord(g_ss.eQ, s3);

    cudaStreamWaitEvent(s2, g_ss.eW, 0);
    mma_gemm<2,0><<<dim3(EE/128, KL/128), 256, GSM_TOTAL, s2>>>(
        rih, ril, wrh, wrl, nullptr, rph, rpl, KL, EE, EE);
    cudaEventRecord(g_ss.eRg, s2);

    // join, then attention on stream 0
    cudaStreamWaitEvent(0, g_ss.eV, 0);
    cudaStreamWaitEvent(0, g_ss.eQ, 0);
    cudaStreamWaitEvent(0, g_ss.eRg, 0);
    attn_mma_kernel<<<dim3(QL/64, HH, BB), 128, A_TOT>>>(
        qph, qpl, kph, kpl, vph, vpl, rph, rpl, rwb, rrb, atth, attl);

    // output projection + LN1
    mma_gemm<0,0><<<dim3(EE/128, (BB*QL)/128), 256, GSM_TOTAL>>>(
        atth, attl, woh, wol, ao, nullptr, nullptr, BB*QL, EE, EE);
    add_ln_kernel<1><<<BB*QL, 256>>>(ao, w, ln1g, ln1b, x, xh, xl);

    // FFN + LN2
    cudaStreamWaitEvent(0, g_ss.eW12, 0);
    mma_gemm<1,0><<<dim3(FF/128, (BB*QL)/128), 256, GSM_TOTAL>>>(
        xh, xl, w1h, w1l, nullptr, hhh, hhl, BB*QL, FF, EE);
    mma_gemm<0,0><<<dim3(EE/128, (BB*QL)/128), 256, GSM_TOTAL>>>(
        hhh, hhl, w2h, w2l, y, nullptr, nullptr, BB*QL, EE, FF);
    add_ln_kernel<0><<<BB*QL, 256>>>(y, x, ln2g, ln2b, out, nullptr, nullptr);
}